// round 9
// baseline (speedup 1.0000x reference)
#include <cuda_runtime.h>
#include <math.h>
#include <stdint.h>

#define Bb 4
#define T 1024
#define C 1024
#define NH 16
#define HD 64
#define E 8
#define TOPK 2
#define FF 4096
#define BT (Bb*T)
#define BH (Bb*NH)
#define NASSIGN (BT*TOPK)

// MMA smem tile: 128 rows x 32 floats, padded stride 36 floats (144B)
#define TILEB (128*144)        // 18432 bytes
#define DYNSMEM  (4*TILEB)     // MoE: A0,A1,B0,B1
#define DYNSMEM3 (8*TILEB)     // split: Ah0,Ah1,Al0,Al1,Bh0,Bh1,Bl0,Bl1 = 147456

// ---------------- scratch ----------------
__device__ float g_hhi[BT*C];
__device__ float g_hlo[BT*C];
__device__ float g_qhi[BT*C];
__device__ float g_qlo[BT*C];
__device__ float g_khi[BT*C];
__device__ float g_klo[BT*C];
__device__ float g_v  [BT*C];
__device__ float g_S  [(size_t)BH*T*T];   // logits, then probs-hi
__device__ float g_Slo[(size_t)BH*T*T];   // probs-lo
__device__ float g_vthi[(size_t)BH*128*T]; // v^T, zero-padded rows 64..127
__device__ float g_vtlo[(size_t)BH*128*T];
__device__ float g_yhi[BT*C];
__device__ float g_ylo[BT*C];
__device__ float g_x1 [BT*C];
__device__ float g_h2 [BT*C];    // exact (gate)
__device__ float g_h2r[BT*C];    // tf32-rounded (fc A)
__device__ float g_h1 [(size_t)NASSIGN*FF];
__device__ float g_wqh[C*C]; __device__ float g_wql[C*C];
__device__ float g_wkh[C*C]; __device__ float g_wkl[C*C];
__device__ float g_wvh[C*C]; __device__ float g_wvl[C*C];
__device__ float g_woh[C*C]; __device__ float g_wol[C*C];
__device__ int   g_cnt[E];
__device__ int   g_off[E];
__device__ int   g_expidx[NASSIGN];
__device__ int   g_pos  [NASSIGN];
__device__ float g_gscore[NASSIGN];
__device__ int   g_list [NASSIGN];
__device__ float g_slotscore[NASSIGN];

__device__ __forceinline__ float tf32r(float x){
    float o; asm("cvt.rna.tf32.f32 %0, %1;" : "=f"(o) : "f"(x)); return o;
}

// ---------------- PTX helpers ----------------
__device__ __forceinline__ uint32_t smem_u32(const void* p){
    uint32_t a; asm("{ .reg .u64 t; cvta.to.shared.u64 t, %1; cvt.u32.u64 %0, t; }" : "=r"(a) : "l"(p)); return a;
}
__device__ __forceinline__ void cpa16(uint32_t saddr, const void* g, uint32_t srcsize){
    asm volatile("cp.async.cg.shared.global [%0], [%1], 16, %2;" :: "r"(saddr), "l"(g), "r"(srcsize) : "memory");
}
#define CPA_COMMIT() asm volatile("cp.async.commit_group;" ::: "memory")
#define CPA_WAIT1()  asm volatile("cp.async.wait_group 1;" ::: "memory")
#define CPA_WAIT0()  asm volatile("cp.async.wait_group 0;" ::: "memory")

__device__ __forceinline__ void ldsm_x4(uint32_t &r0, uint32_t &r1, uint32_t &r2, uint32_t &r3, uint32_t addr){
    asm volatile("ldmatrix.sync.aligned.m8n8.x4.shared.b16 {%0,%1,%2,%3},[%4];"
                 : "=r"(r0),"=r"(r1),"=r"(r2),"=r"(r3) : "r"(addr));
}
__device__ __forceinline__ void mma_tf32(float* c, const uint32_t* a, const uint32_t* b){
    asm volatile("mma.sync.aligned.m16n8k8.row.col.f32.tf32.tf32.f32 "
                 "{%0,%1,%2,%3},{%4,%5,%6,%7},{%8,%9},{%0,%1,%2,%3};"
                 : "+f"(c[0]),"+f"(c[1]),"+f"(c[2]),"+f"(c[3])
                 : "r"(a[0]),"r"(a[1]),"r"(a[2]),"r"(a[3]), "r"(b[0]),"r"(b[1]));
}
__device__ __forceinline__ uint32_t tf32r_bits(uint32_t x){
    return __float_as_uint(tf32r(__uint_as_float(x)));
}

// =============== fragment offset helpers (validated) ===============
__device__ __forceinline__ void frag_offsets(int tid, uint32_t a_off[4], uint32_t b_off[2]){
    int lane = tid & 31, wid = tid >> 5;
    int warpM = wid >> 2, warpN = wid & 3;
#pragma unroll
    for (int mi = 0; mi < 4; mi++) {
        int row = warpM*64 + mi*16 + (lane & 7) + ((lane >> 3) & 1)*8;
        int col4 = (lane >> 4) * 4;
        a_off[mi] = (uint32_t)row*144 + (uint32_t)col4*4;
    }
#pragma unroll
    for (int p = 0; p < 2; p++) {
        int n = warpN*32 + p*16 + (lane & 7) + ((lane >> 4) * 8);
        int col4 = ((lane >> 3) & 1) * 4;
        b_off[p] = (uint32_t)n*144 + (uint32_t)col4*4;
    }
}

// ---------------- tf32 1x MMA mainloop (MoE); RB: rna-round B fragments ----------------
template<bool RB>
__device__ __forceinline__ void gemm_mainloop(
    const float* const* rowA, const float* const* rowB,
    const float* dummy, int nchunk, char* sm,
    float acc[4][4][4], int tid)
{
    uint32_t base = smem_u32(sm);
    uint32_t a_off[4], b_off[2];
    frag_offsets(tid, a_off, b_off);

#define ISSUE(kc) do { \
        int b_ = (kc) & 1; \
        uint32_t sa_ = base + b_*TILEB; \
        uint32_t sb_ = base + 2*TILEB + b_*TILEB; \
        _Pragma("unroll") \
        for (int q = 0; q < 4; q++) { \
            int idx = tid + 256*q; \
            int row = idx >> 3, c16 = idx & 7; \
            uint32_t off = (uint32_t)row*144 + c16*16; \
            const float* pa = rowA[row]; \
            const void* ga = pa ? (const void*)(pa + (kc)*32 + c16*4) : (const void*)dummy; \
            cpa16(sa_ + off, ga, pa ? 16u : 0u); \
            cpa16(sb_ + off, rowB[row] + (kc)*32 + c16*4, 16u); \
        } \
        CPA_COMMIT(); \
    } while (0)

    ISSUE(0);
    for (int kc = 0; kc < nchunk; kc++) {
        if (kc + 1 < nchunk) { ISSUE(kc+1); CPA_WAIT1(); } else { CPA_WAIT0(); }
        __syncthreads();
        int b = kc & 1;
        uint32_t sa = base + b*TILEB;
        uint32_t sb = base + 2*TILEB + b*TILEB;
#pragma unroll
        for (int ks = 0; ks < 4; ks++) {
            uint32_t afr[4][4];
#pragma unroll
            for (int mi = 0; mi < 4; mi++)
                ldsm_x4(afr[mi][0], afr[mi][1], afr[mi][2], afr[mi][3], sa + a_off[mi] + ks*32);
            uint32_t bfr[4][2];
#pragma unroll
            for (int p = 0; p < 2; p++)
                ldsm_x4(bfr[2*p][0], bfr[2*p][1], bfr[2*p+1][0], bfr[2*p+1][1], sb + b_off[p] + ks*32);
            if (RB) {
#pragma unroll
                for (int ni = 0; ni < 4; ni++) {
                    bfr[ni][0] = tf32r_bits(bfr[ni][0]);
                    bfr[ni][1] = tf32r_bits(bfr[ni][1]);
                }
            }
#pragma unroll
            for (int mi = 0; mi < 4; mi++)
#pragma unroll
                for (int ni = 0; ni < 4; ni++)
                    mma_tf32(acc[mi][ni], afr[mi], bfr[ni]);
        }
        __syncthreads();
    }
#undef ISSUE
}

// ---------------- 3xTF32 split mainloop: C += (Ah+Al)*(Bh+Bl)^T (drop Al*Bl) ----------------
__device__ __forceinline__ void gemm3_mainloop(
    const float* Ah, const float* Al, const float* Bh, const float* Bl,
    int lda, int ldb, int nchunk, char* sm, float acc[4][4][4], int tid)
{
    uint32_t base = smem_u32(sm);
    uint32_t a_off[4], b_off[2];
    frag_offsets(tid, a_off, b_off);

#define ISSUE3(kc) do { \
        int b_ = (kc) & 1; \
        uint32_t sah_ = base + b_*TILEB; \
        uint32_t sal_ = base + 2*TILEB + b_*TILEB; \
        uint32_t sbh_ = base + 4*TILEB + b_*TILEB; \
        uint32_t sbl_ = base + 6*TILEB + b_*TILEB; \
        _Pragma("unroll") \
        for (int q = 0; q < 4; q++) { \
            int idx = tid + 256*q; \
            int row = idx >> 3, c16 = idx & 7; \
            uint32_t off = (uint32_t)row*144 + c16*16; \
            size_t goa = (size_t)row*lda + (kc)*32 + c16*4; \
            size_t gob = (size_t)row*ldb + (kc)*32 + c16*4; \
            cpa16(sah_ + off, Ah + goa, 16u); \
            cpa16(sal_ + off, Al + goa, 16u); \
            cpa16(sbh_ + off, Bh + gob, 16u); \
            cpa16(sbl_ + off, Bl + gob, 16u); \
        } \
        CPA_COMMIT(); \
    } while (0)

    ISSUE3(0);
    for (int kc = 0; kc < nchunk; kc++) {
        if (kc + 1 < nchunk) { ISSUE3(kc+1); CPA_WAIT1(); } else { CPA_WAIT0(); }
        __syncthreads();
        int b = kc & 1;
        uint32_t sah = base + b*TILEB;
        uint32_t sal = base + 2*TILEB + b*TILEB;
        uint32_t sbh = base + 4*TILEB + b*TILEB;
        uint32_t sbl = base + 6*TILEB + b*TILEB;
#pragma unroll
        for (int ks = 0; ks < 4; ks++) {
            uint32_t bh[4][2], bl[4][2];
#pragma unroll
            for (int p = 0; p < 2; p++) {
                ldsm_x4(bh[2*p][0], bh[2*p][1], bh[2*p+1][0], bh[2*p+1][1], sbh + b_off[p] + ks*32);
                ldsm_x4(bl[2*p][0], bl[2*p][1], bl[2*p+1][0], bl[2*p+1][1], sbl + b_off[p] + ks*32);
            }
#pragma unroll
            for (int mi = 0; mi < 4; mi++) {
                uint32_t ah[4], al[4];
                ldsm_x4(ah[0], ah[1], ah[2], ah[3], sah + a_off[mi] + ks*32);
                ldsm_x4(al[0], al[1], al[2], al[3], sal + a_off[mi] + ks*32);
#pragma unroll
                for (int ni = 0; ni < 4; ni++) {
                    mma_tf32(acc[mi][ni], ah, bh[ni]);
                    mma_tf32(acc[mi][ni], ah, bl[ni]);
                    mma_tf32(acc[mi][ni], al, bh[ni]);
                }
            }
        }
        __syncthreads();
    }
#undef ISSUE3
}

// ---------------- QKV via 3xTF32; q,k written split, v plain ----------------
__global__ __launch_bounds__(256) void gemm3_qkv()
{
    extern __shared__ char sm[];
    int tid = threadIdx.x;
    int z = blockIdx.z;
    const float* Bh = (z == 0) ? g_wqh : (z == 1) ? g_wkh : g_wvh;
    const float* Bl = (z == 0) ? g_wql : (z == 1) ? g_wkl : g_wvl;
    int rowBase = blockIdx.y * 128, colBase = blockIdx.x * 128;
    float acc[4][4][4] = {};
    gemm3_mainloop(g_hhi + (size_t)rowBase*C, g_hlo + (size_t)rowBase*C,
                   Bh + (size_t)colBase*C,   Bl + (size_t)colBase*C,
                   C, C, C/32, sm, acc, tid);
    int lane = tid & 31, wid = tid >> 5, warpM = wid >> 2, warpN = wid & 3;
    int g = lane >> 2, tg = lane & 3;
    float* Hi = (z == 0) ? g_qhi : g_khi;
    float* Lo = (z == 0) ? g_qlo : g_klo;
#pragma unroll
    for (int mi = 0; mi < 4; mi++)
#pragma unroll
        for (int ni = 0; ni < 4; ni++) {
            int r0 = rowBase + warpM*64 + mi*16 + g;
            int cc = colBase + warpN*32 + ni*8 + tg*2;
#pragma unroll
            for (int h = 0; h < 2; h++) {
                int r = r0 + h*8;
                float v0 = acc[mi][ni][2*h+0];
                float v1 = acc[mi][ni][2*h+1];
                size_t p = (size_t)r*C + cc;
                if (z < 2) {
                    float h0 = tf32r(v0), h1 = tf32r(v1);
                    *(float2*)(Hi + p) = make_float2(h0, h1);
                    *(float2*)(Lo + p) = make_float2(tf32r(v0 - h0), tf32r(v1 - h1));
                } else {
                    *(float2*)(g_v + p) = make_float2(v0, v1);
                }
            }
        }
}

// ---------------- scores via 3xTF32 (K=64, causal tile skip) ----------------
__global__ __launch_bounds__(256) void gemm3_scores()
{
    int z = blockIdx.z; int bb = z >> 4; int hh = z & 15;
    int rowBase = blockIdx.y * 128;
    int colBase = blockIdx.x * 128;
    if (colBase >= rowBase + 128) return;
    extern __shared__ char sm[];
    int tid = threadIdx.x;
    size_t aoff = ((size_t)bb*T + rowBase)*C + hh*HD;
    size_t boff = ((size_t)bb*T + colBase)*C + hh*HD;
    float acc[4][4][4] = {};
    gemm3_mainloop(g_qhi + aoff, g_qlo + aoff, g_khi + boff, g_klo + boff,
                   C, C, HD/32, sm, acc, tid);
    float* Cc = g_S + (size_t)z*T*T;
    int lane = tid & 31, wid = tid >> 5, warpM = wid >> 2, warpN = wid & 3;
    int g = lane >> 2, tg = lane & 3;
#pragma unroll
    for (int mi = 0; mi < 4; mi++)
#pragma unroll
        for (int ni = 0; ni < 4; ni++) {
            int r0 = rowBase + warpM*64 + mi*16 + g;
            int cc = colBase + warpN*32 + ni*8 + tg*2;
#pragma unroll
            for (int h = 0; h < 2; h++) {
                int r = r0 + h*8;
                float* crow = Cc + (size_t)r*T;
                crow[cc]   = (cc   <= r) ? acc[mi][ni][2*h+0]*0.125f : -1e30f;
                crow[cc+1] = (cc+1 <= r) ? acc[mi][ni][2*h+1]*0.125f : -1e30f;
            }
        }
}

// ---------------- row softmax (valid 128-blocks only), split output ----------------
__global__ void softmax_kernel()
{
    size_t row = blockIdx.x;
    int r = (int)(row & (T-1));
    int nv = ((r >> 7) + 1) << 7;
    float* rp  = g_S   + row * T;
    float* rlo = g_Slo + row * T;
    int t = threadIdx.x;
    float v[4]; float m = -1e30f;
#pragma unroll
    for (int i = 0; i < 4; i++) {
        int idx = t + 256*i;
        v[i] = (idx < nv) ? rp[idx] : -1e30f;
        m = fmaxf(m, v[i]);
    }
#pragma unroll
    for (int o = 16; o; o >>= 1) m = fmaxf(m, __shfl_xor_sync(0xffffffffu, m, o));
    __shared__ float sh[8];
    int w = t >> 5, lane = t & 31;
    if (!lane) sh[w] = m;
    __syncthreads();
    __shared__ float m_s, inv_s;
    if (t == 0) {
        float mm = sh[0];
#pragma unroll
        for (int i = 1; i < 8; i++) mm = fmaxf(mm, sh[i]);
        m_s = mm;
    }
    __syncthreads();
    m = m_s;
    float s = 0.f;
#pragma unroll
    for (int i = 0; i < 4; i++) { v[i] = expf(v[i] - m); s += v[i]; }
#pragma unroll
    for (int o = 16; o; o >>= 1) s += __shfl_xor_sync(0xffffffffu, s, o);
    if (!lane) sh[w] = s;
    __syncthreads();
    if (t == 0) {
        float ss = 0.f;
#pragma unroll
        for (int i = 0; i < 8; i++) ss += sh[i];
        inv_s = 1.f / ss;
    }
    __syncthreads();
    float inv = inv_s;
#pragma unroll
    for (int i = 0; i < 4; i++) {
        int idx = t + 256*i;
        if (idx < nv) {
            float p = v[i] * inv;
            float hi = tf32r(p);
            rp[idx]  = hi;
            rlo[idx] = tf32r(p - hi);
        }
    }
}

// ---------------- v transpose + split: vT[bh][c(0..127, pad>=64)][k] ----------------
__global__ void transp_split()
{
    __shared__ float tile[32][33];
    int z  = blockIdx.z;
    int bb = z >> 4, hh = z & 15;
    int c0 = blockIdx.y * 32;
    int k0 = blockIdx.x * 32;
    int tx = threadIdx.x, ty = threadIdx.y;
#pragma unroll
    for (int i = 0; i < 4; i++) {
        int kk = k0 + ty + i*8;
        int cc = c0 + tx;
        float val = (cc < HD) ? g_v[((size_t)bb*T + kk)*C + hh*HD + cc] : 0.f;
        tile[ty + i*8][tx] = val;
    }
    __syncthreads();
#pragma unroll
    for (int i = 0; i < 4; i++) {
        int cc = c0 + ty + i*8;
        int kk = k0 + tx;
        float val = tile[tx][ty + i*8];
        float hi = tf32r(val);
        size_t p = ((size_t)z*128 + cc)*T + kk;
        g_vthi[p] = hi;
        g_vtlo[p] = tf32r(val - hi);
    }
}

// ---------------- AV via 3xTF32 (causal k-bound; N padded to 128, write c<64) ----------------
__global__ __launch_bounds__(256) void gemm3_av()
{
    int z = blockIdx.z; int bb = z >> 4; int hh = z & 15;
    int rowBase = blockIdx.y * 128;
    int nchunk = (rowBase + 128) / 32;
    extern __shared__ char sm[];
    int tid = threadIdx.x;
    size_t aoff = (size_t)z*T*T + (size_t)rowBase*T;
    size_t boff = (size_t)z*128*T;
    float acc[4][4][4] = {};
    gemm3_mainloop(g_S + aoff, g_Slo + aoff, g_vthi + boff, g_vtlo + boff,
                   T, T, nchunk, sm, acc, tid);
    size_t ybase = (size_t)bb*T*C + hh*HD;
    int lane = tid & 31, wid = tid >> 5, warpM = wid >> 2, warpN = wid & 3;
    int g = lane >> 2, tg = lane & 3;
    if (warpN >= 2) return;
#pragma unroll
    for (int mi = 0; mi < 4; mi++)
#pragma unroll
        for (int ni = 0; ni < 4; ni++) {
            int r0 = rowBase + warpM*64 + mi*16 + g;
            int cc = warpN*32 + ni*8 + tg*2;
#pragma unroll
            for (int h = 0; h < 2; h++) {
                int r = r0 + h*8;
                float v0 = acc[mi][ni][2*h+0];
                float v1 = acc[mi][ni][2*h+1];
                float h0 = tf32r(v0), h1 = tf32r(v1);
                size_t p = ybase + (size_t)r*C + cc;
                *(float2*)(g_yhi + p) = make_float2(h0, h1);
                *(float2*)(g_ylo + p) = make_float2(tf32r(v0 - h0), tf32r(v1 - h1));
            }
        }
}

// ---------------- Wo via 3xTF32: out = res + y*Wo^T + bias, dual write ----------------
__global__ __launch_bounds__(256) void gemm3_wo(
    const float* __restrict__ bias, const float* __restrict__ res,
    float* __restrict__ out1, float* __restrict__ out2)
{
    extern __shared__ char sm[];
    int tid = threadIdx.x;
    int rowBase = blockIdx.y * 128, colBase = blockIdx.x * 128;
    float acc[4][4][4] = {};
    gemm3_mainloop(g_yhi + (size_t)rowBase*C, g_ylo + (size_t)rowBase*C,
                   g_woh + (size_t)colBase*C, g_wol + (size_t)colBase*C,
                   C, C, C/32, sm, acc, tid);
    int lane = tid & 31, wid = tid >> 5, warpM = wid >> 2, warpN = wid & 3;
    int g = lane >> 2, tg = lane & 3;
#pragma unroll
    for (int mi = 0; mi < 4; mi++)
#pragma unroll
        for (int ni = 0; ni < 4; ni++) {
            int r0 = rowBase + warpM*64 + mi*16 + g;
            int cc = colBase + warpN*32 + ni*8 + tg*2;
#pragma unroll
            for (int h = 0; h < 2; h++) {
                int r = r0 + h*8;
                float v0 = acc[mi][ni][2*h+0] + bias[cc]   + res[(size_t)r*C + cc];
                float v1 = acc[mi][ni][2*h+1] + bias[cc+1] + res[(size_t)r*C + cc + 1];
                *(float2*)(out1 + (size_t)r*C + cc) = make_float2(v0, v1);
                *(float2*)(out2 + (size_t)r*C + cc) = make_float2(v0, v1);
            }
        }
}

// ---------------- fc: gathered A, raw weights (rna-rounded in-loop), GELU ----------------
__global__ __launch_bounds__(256) void gemm_fc_tc(const float* __restrict__ fcw,
                                                  const float* __restrict__ fcb)
{
    int e = blockIdx.z;
    int cnt = g_cnt[e], off = g_off[e];
    int rowBase = blockIdx.y * 128;
    if (rowBase >= cnt) return;
    int colBase = blockIdx.x * 128;
    extern __shared__ char sm[];
    __shared__ const float* rowA[128];
    __shared__ const float* rowB[128];
    int tid = threadIdx.x;
    const float* wbase = fcw + (size_t)e * FF * C;
    if (tid < 128) {
        int r = rowBase + tid;
        rowA[tid] = (r < cnt) ? g_h2r + (size_t)g_list[off + r] * C : nullptr;
        rowB[tid] = wbase + (size_t)(colBase + tid) * C;
    }
    __syncthreads();
    float acc[4][4][4] = {};
    gemm_mainloop<true>(rowA, rowB, wbase, C/32, sm, acc, tid);
    int lane = tid & 31, wid = tid >> 5, warpM = wid >> 2, warpN = wid & 3;
    int g = lane >> 2, tg = lane & 3;
    const float* fb = fcb + (size_t)e * FF;
#pragma unroll
    for (int mi = 0; mi < 4; mi++)
#pragma unroll
        for (int ni = 0; ni < 4; ni++) {
            int r0 = rowBase + warpM*64 + mi*16 + g;
            int cc = colBase + warpN*32 + ni*8 + tg*2;
#pragma unroll
            for (int h = 0; h < 2; h++) {
                int r = r0 + h*8;
                if (r >= cnt) continue;
                float v0 = acc[mi][ni][2*h+0] + fb[cc];
                float v1 = acc[mi][ni][2*h+1] + fb[cc+1];
                v0 = v0 * 0.5f * (1.f + erff(v0 * 0.70710678118654752f));
                v1 = v1 * 0.5f * (1.f + erff(v1 * 0.70710678118654752f));
                *(float2*)(g_h1 + (size_t)(off + r)*FF + cc) = make_float2(tf32r(v0), tf32r(v1));
            }
        }
}

// ---------------- pj: raw weights (rna-rounded in-loop), +bias, gate-scale, atomicAdd ----------------
__global__ __launch_bounds__(256) void gemm_pj_tc(const float* __restrict__ pjw,
                                                  const float* __restrict__ pjb,
                                                  float* __restrict__ outp)
{
    int e = blockIdx.z;
    int cnt = g_cnt[e], off = g_off[e];
    int rowBase = blockIdx.y * 128;
    if (rowBase >= cnt) return;
    int colBase = blockIdx.x * 128;
    extern __shared__ char sm[];
    __shared__ const float* rowA[128];
    __shared__ const float* rowB[128];
    int tid = threadIdx.x;
    const float* wbase = pjw + (size_t)e * C * FF;
    if (tid < 128) {
        int r = rowBase + tid;
        rowA[tid] = (r < cnt) ? g_h1 + (size_t)(off + r) * FF : nullptr;
        rowB[tid] = wbase + (size_t)(colBase + tid) * FF;
    }
    __syncthreads();
    float acc[4][4][4] = {};
    gemm_mainloop<true>(rowA, rowB, wbase, FF/32, sm, acc, tid);
    int lane = tid & 31, wid = tid >> 5, warpM = wid >> 2, warpN = wid & 3;
    int g = lane >> 2, tg = lane & 3;
    const float* pb = pjb + (size_t)e * C;
#pragma unroll
    for (int mi = 0; mi < 4; mi++)
#pragma unroll
        for (int ni = 0; ni < 4; ni++) {
            int r0 = rowBase + warpM*64 + mi*16 + g;
            int cc = colBase + warpN*32 + ni*8 + tg*2;
#pragma unroll
            for (int h = 0; h < 2; h++) {
                int r = r0 + h*8;
                if (r >= cnt) continue;
                int tok = g_list[off + r];
                float sc = g_slotscore[off + r];
                float* orow = outp + (size_t)tok * C;
                atomicAdd(&orow[cc],   sc * (acc[mi][ni][2*h+0] + pb[cc]));
                atomicAdd(&orow[cc+1], sc * (acc[mi][ni][2*h+1] + pb[cc+1]));
            }
        }
}

// ---------------- fp32 -> (hi, lo) split ----------------
__global__ void conv_split(const float* __restrict__ in, float* __restrict__ hi,
                           float* __restrict__ lo, int n4)
{
    int stride = gridDim.x * blockDim.x;
    for (int idx = blockIdx.x * blockDim.x + threadIdx.x; idx < n4; idx += stride) {
        float4 v = ((const float4*)in)[idx];
        float4 h, l;
        h.x = tf32r(v.x); l.x = tf32r(v.x - h.x);
        h.y = tf32r(v.y); l.y = tf32r(v.y - h.y);
        h.z = tf32r(v.z); l.z = tf32r(v.z - h.z);
        h.w = tf32r(v.w); l.w = tf32r(v.w - h.w);
        ((float4*)hi)[idx] = h;
        ((float4*)lo)[idx] = l;
    }
}

// ---------------- layernorm: optional exact / tf32-rounded / split outputs ----------------
__global__ void ln_kernel(const float* __restrict__ x, const float* __restrict__ g,
                          const float* __restrict__ b, float* __restrict__ outf,
                          float* __restrict__ outr,
                          float* __restrict__ outhi, float* __restrict__ outlo)
{
    int row = blockIdx.x;
    const float* xr = x + (size_t)row * C;
    int t = threadIdx.x;
    float v[4]; float s = 0.f, s2 = 0.f;
#pragma unroll
    for (int i = 0; i < 4; i++) { float val = xr[t + 256*i]; v[i] = val; s += val; s2 += val*val; }
#pragma unroll
    for (int o = 16; o; o >>= 1) { s += __shfl_xor_sync(0xffffffffu, s, o); s2 += __shfl_xor_sync(0xffffffffu, s2, o); }
    __shared__ float sh[8], sh2[8];
    int w = t >> 5, lane = t & 31;
    if (!lane) { sh[w] = s; sh2[w] = s2; }
    __syncthreads();
    __shared__ float mean_s, rstd_s;
    if (t == 0) {
        float S = 0.f, S2 = 0.f;
#pragma unroll
        for (int i = 0; i < 8; i++) { S += sh[i]; S2 += sh2[i]; }
        float mean = S * (1.f/C);
        float var  = S2 * (1.f/C) - mean*mean;
        mean_s = mean; rstd_s = rsqrtf(var + 1e-5f);
    }
    __syncthreads();
    float mean = mean_s, rstd = rstd_s;
#pragma unroll
    for (int i = 0; i < 4; i++) {
        int c = t + 256*i;
        float o = (v[i] - mean) * rstd * g[c] + b[c];
        size_t p = (size_t)row*C + c;
        if (outf) outf[p] = o;
        if (outr) outr[p] = tf32r(o);
        if (outhi) { float hh = tf32r(o); outhi[p] = hh; outlo[p] = tf32r(o - hh); }
    }
}

// ---------------- gate / routing (reads EXACT h2 once; 8 dots per pass) ----------------
__global__ void gate_kernel(const float* __restrict__ gW, const float* __restrict__ gb)
{
    int token = blockIdx.x * 4 + (threadIdx.x >> 5);
    int lane = threadIdx.x & 31;
    const float* hr = g_h2 + (size_t)token * C;
    float acc[E] = {};
    for (int j = lane; j < C; j += 32) {
        float hv = hr[j];
#pragma unroll
        for (int e = 0; e < E; e++) acc[e] += hv * gW[(size_t)e*C + j];
    }
#pragma unroll
    for (int e = 0; e < E; e++)
#pragma unroll
        for (int o = 16; o; o >>= 1) acc[e] += __shfl_xor_sync(0xffffffffu, acc[e], o);
    if (lane == 0) {
        float logits[E];
#pragma unroll
        for (int e = 0; e < E; e++) logits[e] = acc[e] + gb[e];
        int i0 = 0; float m0 = logits[0];
#pragma unroll
        for (int e = 1; e < E; e++) if (logits[e] > m0) { m0 = logits[e]; i0 = e; }
        int i1 = -1; float m1 = -1e30f;
#pragma unroll
        for (int e = 0; e < E; e++) if (e != i0 && logits[e] > m1) { m1 = logits[e]; i1 = e; }
        float den = 0.f;
#pragma unroll
        for (int e = 0; e < E; e++) den += expf(logits[e] - m0);
        float s0 = 1.f / den;
        float s1 = expf(m1 - m0) / den;
        g_expidx[token*2+0] = i0; g_gscore[token*2+0] = s0;
        g_expidx[token*2+1] = i1; g_gscore[token*2+1] = s1;
        g_pos[token*2+0] = atomicAdd(&g_cnt[i0], 1);
        g_pos[token*2+1] = atomicAdd(&g_cnt[i1], 1);
    }
}

__global__ void zero_cnt_kernel() { if (threadIdx.x < E) g_cnt[threadIdx.x] = 0; }

__global__ void scan_kernel()
{
    if (threadIdx.x == 0) {
        int acc = 0;
        for (int e = 0; e < E; e++) { g_off[e] = acc; acc += g_cnt[e]; }
    }
}

__global__ void scatter_kernel()
{
    int i = blockIdx.x * 256 + threadIdx.x;
    if (i < NASSIGN) {
        int e = g_expidx[i];
        int slot = g_off[e] + g_pos[i];
        g_list[slot] = i >> 1;
        g_slotscore[slot] = g_gscore[i];
    }
}

// ---------------- host launcher ----------------
extern "C" void kernel_launch(void* const* d_in, const int* in_sizes, int n_in,
                              void* d_out, int out_size)
{
    const float* x     = (const float*)d_in[0];
    const float* ln1g  = (const float*)d_in[1];
    const float* ln1b  = (const float*)d_in[2];
    const float* Wq    = (const float*)d_in[3];
    const float* Wk    = (const float*)d_in[4];
    const float* Wv    = (const float*)d_in[5];
    const float* Wo    = (const float*)d_in[6];
    const float* bo    = (const float*)d_in[7];
    const float* ln2g  = (const float*)d_in[8];
    const float* ln2b  = (const float*)d_in[9];
    const float* gateW = (const float*)d_in[10];
    const float* gateb = (const float*)d_in[11];
    const float* fcW   = (const float*)d_in[12];
    const float* fcb   = (const float*)d_in[13];
    const float* pjW   = (const float*)d_in[14];
    const float* pjb   = (const float*)d_in[15];
    float* outp = (float*)d_out;

    float *p_hhi, *p_hlo, *p_x1, *p_h2, *p_h2r;
    float *p_wqh, *p_wql, *p_wkh, *p_wkl, *p_wvh, *p_wvl, *p_woh, *p_wol;
    cudaGetSymbolAddress((void**)&p_hhi, g_hhi);
    cudaGetSymbolAddress((void**)&p_hlo, g_hlo);
    cudaGetSymbolAddress((void**)&p_x1,  g_x1);
    cudaGetSymbolAddress((void**)&p_h2,  g_h2);
    cudaGetSymbolAddress((void**)&p_h2r, g_h2r);
    cudaGetSymbolAddress((void**)&p_wqh, g_wqh); cudaGetSymbolAddress((void**)&p_wql, g_wql);
    cudaGetSymbolAddress((void**)&p_wkh, g_wkh); cudaGetSymbolAddress((void**)&p_wkl, g_wkl);
    cudaGetSymbolAddress((void**)&p_wvh, g_wvh); cudaGetSymbolAddress((void**)&p_wvl, g_wvl);
    cudaGetSymbolAddress((void**)&p_woh, g_woh); cudaGetSymbolAddress((void**)&p_wol, g_wol);

    cudaFuncSetAttribute(gemm_fc_tc,   cudaFuncAttributeMaxDynamicSharedMemorySize, DYNSMEM);
    cudaFuncSetAttribute(gemm_pj_tc,   cudaFuncAttributeMaxDynamicSharedMemorySize, DYNSMEM);
    cudaFuncSetAttribute(gemm3_qkv,    cudaFuncAttributeMaxDynamicSharedMemorySize, DYNSMEM3);
    cudaFuncSetAttribute(gemm3_wo,     cudaFuncAttributeMaxDynamicSharedMemorySize, DYNSMEM3);
    cudaFuncSetAttribute(gemm3_scores, cudaFuncAttributeMaxDynamicSharedMemorySize, DYNSMEM3);
    cudaFuncSetAttribute(gemm3_av,     cudaFuncAttributeMaxDynamicSharedMemorySize, DYNSMEM3);

    zero_cnt_kernel<<<1, 32>>>();

    // Attention weights: hi/lo split (MoE weights consumed raw; rounded in-loop)
    conv_split<<<2048, 256>>>(Wq, p_wqh, p_wql, C*C/4);
    conv_split<<<2048, 256>>>(Wk, p_wkh, p_wkl, C*C/4);
    conv_split<<<2048, 256>>>(Wv, p_wvh, p_wvl, C*C/4);
    conv_split<<<2048, 256>>>(Wo, p_woh, p_wol, C*C/4);

    // LN1 -> split h
    ln_kernel<<<BT, 256>>>(x, ln1g, ln1b, nullptr, nullptr, p_hhi, p_hlo);

    // QKV (3xTF32 MMA): q,k split; v plain
    gemm3_qkv<<<dim3(C/128, BT/128, 3), 256, DYNSMEM3>>>();

    // v transpose + split (padded to 128 rows)
    transp_split<<<dim3(T/32, 4, BH), dim3(32, 8)>>>();

    // attention (3xTF32 MMA, causal-pruned)
    gemm3_scores<<<dim3(T/128, T/128, BH), 256, DYNSMEM3>>>();
    softmax_kernel<<<BH*T, 256>>>();
    gemm3_av<<<dim3(1, T/128, BH), 256, DYNSMEM3>>>();

    // Wo + bias + residual (3xTF32 MMA), dual write
    gemm3_wo<<<dim3(C/128, BT/128), 256, DYNSMEM3>>>(bo, x, p_x1, outp);

    // LN2: exact h2 (gate) + tf32-rounded h2r (fc)
    ln_kernel<<<BT, 256>>>(p_x1, ln2g, ln2b, p_h2, p_h2r, nullptr, nullptr);

    // gating + routing (exact h2)
    gate_kernel<<<BT/4, 128>>>(gateW, gateb);
    scan_kernel<<<1, 32>>>();
    scatter_kernel<<<NASSIGN/256, 256>>>();

    // expert FFN (tf32 MMA, routed top-2, raw weights rounded in-loop)
    gemm_fc_tc<<<dim3(FF/128, BT/128, E), 256, DYNSMEM>>>(fcW, fcb);
    gemm_pj_tc<<<dim3(C/128, BT/128, E), 256, DYNSMEM>>>(pjW, pjb, outp);
}

// round 10
// speedup vs baseline: 1.0692x; 1.0692x over previous
#include <cuda_runtime.h>
#include <math.h>
#include <stdint.h>

#define Bb 4
#define T 1024
#define C 1024
#define NH 16
#define HD 64
#define E 8
#define TOPK 2
#define FF 4096
#define BT (Bb*T)
#define BH (Bb*NH)
#define NASSIGN (BT*TOPK)

// MMA smem tile: 128 rows x 32 floats, padded stride 36 floats (144B)
#define TILEB (128*144)        // 18432 bytes
#define DYNSMEM  (4*TILEB)     // MoE: A0,A1,B0,B1
#define DYNSMEM3 (8*TILEB)     // split: Ah0,Ah1,Al0,Al1,Bh0,Bh1,Bl0,Bl1 = 147456

// ---------------- scratch ----------------
__device__ float g_hhi[BT*C];
__device__ float g_hlo[BT*C];
__device__ float g_qhi[BT*C];
__device__ float g_qlo[BT*C];
__device__ float g_khi[BT*C];
__device__ float g_klo[BT*C];
__device__ float g_v  [BT*C];
__device__ float g_S  [(size_t)BH*T*T];   // logits, then probs-hi
__device__ float g_Slo[(size_t)BH*T*T];   // probs-lo
__device__ float g_vthi[(size_t)BH*128*T]; // v^T, zero-padded rows 64..127
__device__ float g_vtlo[(size_t)BH*128*T];
__device__ float g_yhi[BT*C];
__device__ float g_ylo[BT*C];
__device__ float g_x1 [BT*C];
__device__ float g_h2 [BT*C];    // exact (gate)
__device__ float g_h2r[BT*C];    // tf32-rounded (fc A)
__device__ float g_h1 [(size_t)NASSIGN*FF];
__device__ float g_wqh[C*C]; __device__ float g_wql[C*C];
__device__ float g_wkh[C*C]; __device__ float g_wkl[C*C];
__device__ float g_wvh[C*C]; __device__ float g_wvl[C*C];
__device__ float g_woh[C*C]; __device__ float g_wol[C*C];
__device__ float g_fcw[(size_t)E*FF*C];
__device__ float g_pjw[(size_t)E*C*FF];
__device__ int   g_cnt[E];
__device__ int   g_off[E];
__device__ int   g_expidx[NASSIGN];
__device__ int   g_pos  [NASSIGN];
__device__ float g_gscore[NASSIGN];
__device__ int   g_list [NASSIGN];
__device__ float g_slotscore[NASSIGN];

__device__ __forceinline__ float tf32r(float x){
    float o; asm("cvt.rna.tf32.f32 %0, %1;" : "=f"(o) : "f"(x)); return o;
}

// ---------------- PTX helpers ----------------
__device__ __forceinline__ uint32_t smem_u32(const void* p){
    uint32_t a; asm("{ .reg .u64 t; cvta.to.shared.u64 t, %1; cvt.u32.u64 %0, t; }" : "=r"(a) : "l"(p)); return a;
}
__device__ __forceinline__ void cpa16(uint32_t saddr, const void* g, uint32_t srcsize){
    asm volatile("cp.async.cg.shared.global [%0], [%1], 16, %2;" :: "r"(saddr), "l"(g), "r"(srcsize) : "memory");
}
#define CPA_COMMIT() asm volatile("cp.async.commit_group;" ::: "memory")
#define CPA_WAIT1()  asm volatile("cp.async.wait_group 1;" ::: "memory")
#define CPA_WAIT0()  asm volatile("cp.async.wait_group 0;" ::: "memory")

__device__ __forceinline__ void ldsm_x4(uint32_t &r0, uint32_t &r1, uint32_t &r2, uint32_t &r3, uint32_t addr){
    asm volatile("ldmatrix.sync.aligned.m8n8.x4.shared.b16 {%0,%1,%2,%3},[%4];"
                 : "=r"(r0),"=r"(r1),"=r"(r2),"=r"(r3) : "r"(addr));
}
__device__ __forceinline__ void mma_tf32(float* c, const uint32_t* a, const uint32_t* b){
    asm volatile("mma.sync.aligned.m16n8k8.row.col.f32.tf32.tf32.f32 "
                 "{%0,%1,%2,%3},{%4,%5,%6,%7},{%8,%9},{%0,%1,%2,%3};"
                 : "+f"(c[0]),"+f"(c[1]),"+f"(c[2]),"+f"(c[3])
                 : "r"(a[0]),"r"(a[1]),"r"(a[2]),"r"(a[3]), "r"(b[0]),"r"(b[1]));
}

// =============== fragment offset helpers (validated) ===============
__device__ __forceinline__ void frag_offsets(int tid, uint32_t a_off[4], uint32_t b_off[2]){
    int lane = tid & 31, wid = tid >> 5;
    int warpM = wid >> 2, warpN = wid & 3;
#pragma unroll
    for (int mi = 0; mi < 4; mi++) {
        int row = warpM*64 + mi*16 + (lane & 7) + ((lane >> 3) & 1)*8;
        int col4 = (lane >> 4) * 4;
        a_off[mi] = (uint32_t)row*144 + (uint32_t)col4*4;
    }
#pragma unroll
    for (int p = 0; p < 2; p++) {
        int n = warpN*32 + p*16 + (lane & 7) + ((lane >> 4) * 8);
        int col4 = ((lane >> 3) & 1) * 4;
        b_off[p] = (uint32_t)n*144 + (uint32_t)col4*4;
    }
}

// ---------------- tf32 1x MMA mainloop (MoE) ----------------
__device__ __forceinline__ void gemm_mainloop(
    const float* const* rowA, const float* const* rowB,
    const float* dummy, int nchunk, char* sm,
    float acc[4][4][4], int tid)
{
    uint32_t base = smem_u32(sm);
    uint32_t a_off[4], b_off[2];
    frag_offsets(tid, a_off, b_off);

#define ISSUE(kc) do { \
        int b_ = (kc) & 1; \
        uint32_t sa_ = base + b_*TILEB; \
        uint32_t sb_ = base + 2*TILEB + b_*TILEB; \
        _Pragma("unroll") \
        for (int q = 0; q < 4; q++) { \
            int idx = tid + 256*q; \
            int row = idx >> 3, c16 = idx & 7; \
            uint32_t off = (uint32_t)row*144 + c16*16; \
            const float* pa = rowA[row]; \
            const void* ga = pa ? (const void*)(pa + (kc)*32 + c16*4) : (const void*)dummy; \
            cpa16(sa_ + off, ga, pa ? 16u : 0u); \
            cpa16(sb_ + off, rowB[row] + (kc)*32 + c16*4, 16u); \
        } \
        CPA_COMMIT(); \
    } while (0)

    ISSUE(0);
    for (int kc = 0; kc < nchunk; kc++) {
        if (kc + 1 < nchunk) { ISSUE(kc+1); CPA_WAIT1(); } else { CPA_WAIT0(); }
        __syncthreads();
        int b = kc & 1;
        uint32_t sa = base + b*TILEB;
        uint32_t sb = base + 2*TILEB + b*TILEB;
#pragma unroll
        for (int ks = 0; ks < 4; ks++) {
            uint32_t afr[4][4];
#pragma unroll
            for (int mi = 0; mi < 4; mi++)
                ldsm_x4(afr[mi][0], afr[mi][1], afr[mi][2], afr[mi][3], sa + a_off[mi] + ks*32);
            uint32_t bfr[4][2];
#pragma unroll
            for (int p = 0; p < 2; p++)
                ldsm_x4(bfr[2*p][0], bfr[2*p][1], bfr[2*p+1][0], bfr[2*p+1][1], sb + b_off[p] + ks*32);
#pragma unroll
            for (int mi = 0; mi < 4; mi++)
#pragma unroll
                for (int ni = 0; ni < 4; ni++)
                    mma_tf32(acc[mi][ni], afr[mi], bfr[ni]);
        }
        __syncthreads();
    }
#undef ISSUE
}

// ---------------- 3xTF32 split mainloop: C += (Ah+Al)*(Bh+Bl)^T (drop Al*Bl) ----------------
__device__ __forceinline__ void gemm3_mainloop(
    const float* Ah, const float* Al, const float* Bh, const float* Bl,
    int lda, int ldb, int nchunk, char* sm, float acc[4][4][4], int tid)
{
    uint32_t base = smem_u32(sm);
    uint32_t a_off[4], b_off[2];
    frag_offsets(tid, a_off, b_off);

#define ISSUE3(kc) do { \
        int b_ = (kc) & 1; \
        uint32_t sah_ = base + b_*TILEB; \
        uint32_t sal_ = base + 2*TILEB + b_*TILEB; \
        uint32_t sbh_ = base + 4*TILEB + b_*TILEB; \
        uint32_t sbl_ = base + 6*TILEB + b_*TILEB; \
        _Pragma("unroll") \
        for (int q = 0; q < 4; q++) { \
            int idx = tid + 256*q; \
            int row = idx >> 3, c16 = idx & 7; \
            uint32_t off = (uint32_t)row*144 + c16*16; \
            size_t goa = (size_t)row*lda + (kc)*32 + c16*4; \
            size_t gob = (size_t)row*ldb + (kc)*32 + c16*4; \
            cpa16(sah_ + off, Ah + goa, 16u); \
            cpa16(sal_ + off, Al + goa, 16u); \
            cpa16(sbh_ + off, Bh + gob, 16u); \
            cpa16(sbl_ + off, Bl + gob, 16u); \
        } \
        CPA_COMMIT(); \
    } while (0)

    ISSUE3(0);
    for (int kc = 0; kc < nchunk; kc++) {
        if (kc + 1 < nchunk) { ISSUE3(kc+1); CPA_WAIT1(); } else { CPA_WAIT0(); }
        __syncthreads();
        int b = kc & 1;
        uint32_t sah = base + b*TILEB;
        uint32_t sal = base + 2*TILEB + b*TILEB;
        uint32_t sbh = base + 4*TILEB + b*TILEB;
        uint32_t sbl = base + 6*TILEB + b*TILEB;
#pragma unroll
        for (int ks = 0; ks < 4; ks++) {
            uint32_t bh[4][2], bl[4][2];
#pragma unroll
            for (int p = 0; p < 2; p++) {
                ldsm_x4(bh[2*p][0], bh[2*p][1], bh[2*p+1][0], bh[2*p+1][1], sbh + b_off[p] + ks*32);
                ldsm_x4(bl[2*p][0], bl[2*p][1], bl[2*p+1][0], bl[2*p+1][1], sbl + b_off[p] + ks*32);
            }
#pragma unroll
            for (int mi = 0; mi < 4; mi++) {
                uint32_t ah[4], al[4];
                ldsm_x4(ah[0], ah[1], ah[2], ah[3], sah + a_off[mi] + ks*32);
                ldsm_x4(al[0], al[1], al[2], al[3], sal + a_off[mi] + ks*32);
#pragma unroll
                for (int ni = 0; ni < 4; ni++) {
                    mma_tf32(acc[mi][ni], ah, bh[ni]);
                    mma_tf32(acc[mi][ni], ah, bl[ni]);
                    mma_tf32(acc[mi][ni], al, bh[ni]);
                }
            }
        }
        __syncthreads();
    }
#undef ISSUE3
}

// ---------------- QKV via 3xTF32; q,k written split, v plain ----------------
__global__ __launch_bounds__(256) void gemm3_qkv()
{
    extern __shared__ char sm[];
    int tid = threadIdx.x;
    int z = blockIdx.z;
    const float* Bh = (z == 0) ? g_wqh : (z == 1) ? g_wkh : g_wvh;
    const float* Bl = (z == 0) ? g_wql : (z == 1) ? g_wkl : g_wvl;
    int rowBase = blockIdx.y * 128, colBase = blockIdx.x * 128;
    float acc[4][4][4] = {};
    gemm3_mainloop(g_hhi + (size_t)rowBase*C, g_hlo + (size_t)rowBase*C,
                   Bh + (size_t)colBase*C,   Bl + (size_t)colBase*C,
                   C, C, C/32, sm, acc, tid);
    int lane = tid & 31, wid = tid >> 5, warpM = wid >> 2, warpN = wid & 3;
    int g = lane >> 2, tg = lane & 3;
    float* Hi = (z == 0) ? g_qhi : g_khi;
    float* Lo = (z == 0) ? g_qlo : g_klo;
#pragma unroll
    for (int mi = 0; mi < 4; mi++)
#pragma unroll
        for (int ni = 0; ni < 4; ni++) {
            int r0 = rowBase + warpM*64 + mi*16 + g;
            int cc = colBase + warpN*32 + ni*8 + tg*2;
#pragma unroll
            for (int h = 0; h < 2; h++) {
                int r = r0 + h*8;
                float v0 = acc[mi][ni][2*h+0];
                float v1 = acc[mi][ni][2*h+1];
                size_t p = (size_t)r*C + cc;
                if (z < 2) {
                    float h0 = tf32r(v0), h1 = tf32r(v1);
                    *(float2*)(Hi + p) = make_float2(h0, h1);
                    *(float2*)(Lo + p) = make_float2(tf32r(v0 - h0), tf32r(v1 - h1));
                } else {
                    *(float2*)(g_v + p) = make_float2(v0, v1);
                }
            }
        }
}

// ---------------- scores via 3xTF32 (K=64, causal tile skip) ----------------
__global__ __launch_bounds__(256) void gemm3_scores()
{
    int z = blockIdx.z; int bb = z >> 4; int hh = z & 15;
    int rowBase = blockIdx.y * 128;
    int colBase = blockIdx.x * 128;
    if (colBase >= rowBase + 128) return;
    extern __shared__ char sm[];
    int tid = threadIdx.x;
    size_t aoff = ((size_t)bb*T + rowBase)*C + hh*HD;
    size_t boff = ((size_t)bb*T + colBase)*C + hh*HD;
    float acc[4][4][4] = {};
    gemm3_mainloop(g_qhi + aoff, g_qlo + aoff, g_khi + boff, g_klo + boff,
                   C, C, HD/32, sm, acc, tid);
    float* Cc = g_S + (size_t)z*T*T;
    int lane = tid & 31, wid = tid >> 5, warpM = wid >> 2, warpN = wid & 3;
    int g = lane >> 2, tg = lane & 3;
#pragma unroll
    for (int mi = 0; mi < 4; mi++)
#pragma unroll
        for (int ni = 0; ni < 4; ni++) {
            int r0 = rowBase + warpM*64 + mi*16 + g;
            int cc = colBase + warpN*32 + ni*8 + tg*2;
#pragma unroll
            for (int h = 0; h < 2; h++) {
                int r = r0 + h*8;
                float* crow = Cc + (size_t)r*T;
                crow[cc]   = (cc   <= r) ? acc[mi][ni][2*h+0]*0.125f : -1e30f;
                crow[cc+1] = (cc+1 <= r) ? acc[mi][ni][2*h+1]*0.125f : -1e30f;
            }
        }
}

// ---------------- row softmax (valid 128-blocks only), split output ----------------
__global__ void softmax_kernel()
{
    size_t row = blockIdx.x;
    int r = (int)(row & (T-1));
    int nv = ((r >> 7) + 1) << 7;
    float* rp  = g_S   + row * T;
    float* rlo = g_Slo + row * T;
    int t = threadIdx.x;
    float v[4]; float m = -1e30f;
#pragma unroll
    for (int i = 0; i < 4; i++) {
        int idx = t + 256*i;
        v[i] = (idx < nv) ? rp[idx] : -1e30f;
        m = fmaxf(m, v[i]);
    }
#pragma unroll
    for (int o = 16; o; o >>= 1) m = fmaxf(m, __shfl_xor_sync(0xffffffffu, m, o));
    __shared__ float sh[8];
    int w = t >> 5, lane = t & 31;
    if (!lane) sh[w] = m;
    __syncthreads();
    __shared__ float m_s, inv_s;
    if (t == 0) {
        float mm = sh[0];
#pragma unroll
        for (int i = 1; i < 8; i++) mm = fmaxf(mm, sh[i]);
        m_s = mm;
    }
    __syncthreads();
    m = m_s;
    float s = 0.f;
#pragma unroll
    for (int i = 0; i < 4; i++) { v[i] = expf(v[i] - m); s += v[i]; }
#pragma unroll
    for (int o = 16; o; o >>= 1) s += __shfl_xor_sync(0xffffffffu, s, o);
    if (!lane) sh[w] = s;
    __syncthreads();
    if (t == 0) {
        float ss = 0.f;
#pragma unroll
        for (int i = 0; i < 8; i++) ss += sh[i];
        inv_s = 1.f / ss;
    }
    __syncthreads();
    float inv = inv_s;
#pragma unroll
    for (int i = 0; i < 4; i++) {
        int idx = t + 256*i;
        if (idx < nv) {
            float p = v[i] * inv;
            float hi = tf32r(p);
            rp[idx]  = hi;
            rlo[idx] = tf32r(p - hi);
        }
    }
}

// ---------------- v transpose + split: vT[bh][c(0..127, pad>=64)][k] ----------------
__global__ void transp_split()
{
    __shared__ float tile[32][33];
    int z  = blockIdx.z;
    int bb = z >> 4, hh = z & 15;
    int c0 = blockIdx.y * 32;
    int k0 = blockIdx.x * 32;
    int tx = threadIdx.x, ty = threadIdx.y;
#pragma unroll
    for (int i = 0; i < 4; i++) {
        int kk = k0 + ty + i*8;
        int cc = c0 + tx;
        float val = (cc < HD) ? g_v[((size_t)bb*T + kk)*C + hh*HD + cc] : 0.f;
        tile[ty + i*8][tx] = val;
    }
    __syncthreads();
#pragma unroll
    for (int i = 0; i < 4; i++) {
        int cc = c0 + ty + i*8;
        int kk = k0 + tx;
        float val = tile[tx][ty + i*8];
        float hi = tf32r(val);
        size_t p = ((size_t)z*128 + cc)*T + kk;
        g_vthi[p] = hi;
        g_vtlo[p] = tf32r(val - hi);
    }
}

// ---------------- AV via 3xTF32 (causal k-bound; N padded to 128, write c<64) ----------------
__global__ __launch_bounds__(256) void gemm3_av()
{
    int z = blockIdx.z; int bb = z >> 4; int hh = z & 15;
    int rowBase = blockIdx.y * 128;
    int nchunk = (rowBase + 128) / 32;
    extern __shared__ char sm[];
    int tid = threadIdx.x;
    size_t aoff = (size_t)z*T*T + (size_t)rowBase*T;
    size_t boff = (size_t)z*128*T;
    float acc[4][4][4] = {};
    gemm3_mainloop(g_S + aoff, g_Slo + aoff, g_vthi + boff, g_vtlo + boff,
                   T, T, nchunk, sm, acc, tid);
    size_t ybase = (size_t)bb*T*C + hh*HD;
    int lane = tid & 31, wid = tid >> 5, warpM = wid >> 2, warpN = wid & 3;
    int g = lane >> 2, tg = lane & 3;
    if (warpN >= 2) return;
#pragma unroll
    for (int mi = 0; mi < 4; mi++)
#pragma unroll
        for (int ni = 0; ni < 4; ni++) {
            int r0 = rowBase + warpM*64 + mi*16 + g;
            int cc = warpN*32 + ni*8 + tg*2;
#pragma unroll
            for (int h = 0; h < 2; h++) {
                int r = r0 + h*8;
                float v0 = acc[mi][ni][2*h+0];
                float v1 = acc[mi][ni][2*h+1];
                float h0 = tf32r(v0), h1 = tf32r(v1);
                size_t p = ybase + (size_t)r*C + cc;
                *(float2*)(g_yhi + p) = make_float2(h0, h1);
                *(float2*)(g_ylo + p) = make_float2(tf32r(v0 - h0), tf32r(v1 - h1));
            }
        }
}

// ---------------- Wo via 3xTF32: out = res + y*Wo^T + bias, dual write ----------------
__global__ __launch_bounds__(256) void gemm3_wo(
    const float* __restrict__ bias, const float* __restrict__ res,
    float* __restrict__ out1, float* __restrict__ out2)
{
    extern __shared__ char sm[];
    int tid = threadIdx.x;
    int rowBase = blockIdx.y * 128, colBase = blockIdx.x * 128;
    float acc[4][4][4] = {};
    gemm3_mainloop(g_yhi + (size_t)rowBase*C, g_ylo + (size_t)rowBase*C,
                   g_woh + (size_t)colBase*C, g_wol + (size_t)colBase*C,
                   C, C, C/32, sm, acc, tid);
    int lane = tid & 31, wid = tid >> 5, warpM = wid >> 2, warpN = wid & 3;
    int g = lane >> 2, tg = lane & 3;
#pragma unroll
    for (int mi = 0; mi < 4; mi++)
#pragma unroll
        for (int ni = 0; ni < 4; ni++) {
            int r0 = rowBase + warpM*64 + mi*16 + g;
            int cc = colBase + warpN*32 + ni*8 + tg*2;
#pragma unroll
            for (int h = 0; h < 2; h++) {
                int r = r0 + h*8;
                float v0 = acc[mi][ni][2*h+0] + bias[cc]   + res[(size_t)r*C + cc];
                float v1 = acc[mi][ni][2*h+1] + bias[cc+1] + res[(size_t)r*C + cc + 1];
                *(float2*)(out1 + (size_t)r*C + cc) = make_float2(v0, v1);
                *(float2*)(out2 + (size_t)r*C + cc) = make_float2(v0, v1);
            }
        }
}

// ---------------- fc: gathered A, +bias, GELU (rowTile = blockIdx.x for L2 weight reuse) ----------------
__global__ __launch_bounds__(256) void gemm_fc_tc(const float* __restrict__ fcb)
{
    int e = blockIdx.z;
    int cnt = g_cnt[e], off = g_off[e];
    int rowBase = blockIdx.x * 128;
    if (rowBase >= cnt) return;
    int colBase = blockIdx.y * 128;
    extern __shared__ char sm[];
    __shared__ const float* rowA[128];
    __shared__ const float* rowB[128];
    int tid = threadIdx.x;
    const float* wbase = g_fcw + (size_t)e * FF * C;
    if (tid < 128) {
        int r = rowBase + tid;
        rowA[tid] = (r < cnt) ? g_h2r + (size_t)g_list[off + r] * C : nullptr;
        rowB[tid] = wbase + (size_t)(colBase + tid) * C;
    }
    __syncthreads();
    float acc[4][4][4] = {};
    gemm_mainloop(rowA, rowB, wbase, C/32, sm, acc, tid);
    int lane = tid & 31, wid = tid >> 5, warpM = wid >> 2, warpN = wid & 3;
    int g = lane >> 2, tg = lane & 3;
    const float* fb = fcb + (size_t)e * FF;
#pragma unroll
    for (int mi = 0; mi < 4; mi++)
#pragma unroll
        for (int ni = 0; ni < 4; ni++) {
            int r0 = rowBase + warpM*64 + mi*16 + g;
            int cc = colBase + warpN*32 + ni*8 + tg*2;
#pragma unroll
            for (int h = 0; h < 2; h++) {
                int r = r0 + h*8;
                if (r >= cnt) continue;
                float v0 = acc[mi][ni][2*h+0] + fb[cc];
                float v1 = acc[mi][ni][2*h+1] + fb[cc+1];
                v0 = v0 * 0.5f * (1.f + erff(v0 * 0.70710678118654752f));
                v1 = v1 * 0.5f * (1.f + erff(v1 * 0.70710678118654752f));
                *(float2*)(g_h1 + (size_t)(off + r)*FF + cc) = make_float2(tf32r(v0), tf32r(v1));
            }
        }
}

// ---------------- pj: +bias, gate-scale, atomicAdd (rowTile = blockIdx.x) ----------------
__global__ __launch_bounds__(256) void gemm_pj_tc(const float* __restrict__ pjb,
                                                  float* __restrict__ outp)
{
    int e = blockIdx.z;
    int cnt = g_cnt[e], off = g_off[e];
    int rowBase = blockIdx.x * 128;
    if (rowBase >= cnt) return;
    int colBase = blockIdx.y * 128;
    extern __shared__ char sm[];
    __shared__ const float* rowA[128];
    __shared__ const float* rowB[128];
    int tid = threadIdx.x;
    const float* wbase = g_pjw + (size_t)e * C * FF;
    if (tid < 128) {
        int r = rowBase + tid;
        rowA[tid] = (r < cnt) ? g_h1 + (size_t)(off + r) * FF : nullptr;
        rowB[tid] = wbase + (size_t)(colBase + tid) * FF;
    }
    __syncthreads();
    float acc[4][4][4] = {};
    gemm_mainloop(rowA, rowB, wbase, FF/32, sm, acc, tid);
    int lane = tid & 31, wid = tid >> 5, warpM = wid >> 2, warpN = wid & 3;
    int g = lane >> 2, tg = lane & 3;
    const float* pb = pjb + (size_t)e * C;
#pragma unroll
    for (int mi = 0; mi < 4; mi++)
#pragma unroll
        for (int ni = 0; ni < 4; ni++) {
            int r0 = rowBase + warpM*64 + mi*16 + g;
            int cc = colBase + warpN*32 + ni*8 + tg*2;
#pragma unroll
            for (int h = 0; h < 2; h++) {
                int r = r0 + h*8;
                if (r >= cnt) continue;
                int tok = g_list[off + r];
                float sc = g_slotscore[off + r];
                float* orow = outp + (size_t)tok * C;
                atomicAdd(&orow[cc],   sc * (acc[mi][ni][2*h+0] + pb[cc]));
                atomicAdd(&orow[cc+1], sc * (acc[mi][ni][2*h+1] + pb[cc+1]));
            }
        }
}

// ---------------- fp32 -> tf32-rounded fp32 ----------------
__global__ void conv_tf32(const float* __restrict__ in, float* __restrict__ out, int n4)
{
    int stride = gridDim.x * blockDim.x;
    for (int idx = blockIdx.x * blockDim.x + threadIdx.x; idx < n4; idx += stride) {
        float4 v = ((const float4*)in)[idx];
        v.x = tf32r(v.x); v.y = tf32r(v.y); v.z = tf32r(v.z); v.w = tf32r(v.w);
        ((float4*)out)[idx] = v;
    }
}

// ---------------- fp32 -> (hi, lo) split ----------------
__global__ void conv_split(const float* __restrict__ in, float* __restrict__ hi,
                           float* __restrict__ lo, int n4)
{
    int stride = gridDim.x * blockDim.x;
    for (int idx = blockIdx.x * blockDim.x + threadIdx.x; idx < n4; idx += stride) {
        float4 v = ((const float4*)in)[idx];
        float4 h, l;
        h.x = tf32r(v.x); l.x = tf32r(v.x - h.x);
        h.y = tf32r(v.y); l.y = tf32r(v.y - h.y);
        h.z = tf32r(v.z); l.z = tf32r(v.z - h.z);
        h.w = tf32r(v.w); l.w = tf32r(v.w - h.w);
        ((float4*)hi)[idx] = h;
        ((float4*)lo)[idx] = l;
    }
}

// ---------------- layernorm: optional exact / tf32-rounded / split outputs ----------------
__global__ void ln_kernel(const float* __restrict__ x, const float* __restrict__ g,
                          const float* __restrict__ b, float* __restrict__ outf,
                          float* __restrict__ outr,
                          float* __restrict__ outhi, float* __restrict__ outlo)
{
    int row = blockIdx.x;
    const float* xr = x + (size_t)row * C;
    int t = threadIdx.x;
    float v[4]; float s = 0.f, s2 = 0.f;
#pragma unroll
    for (int i = 0; i < 4; i++) { float val = xr[t + 256*i]; v[i] = val; s += val; s2 += val*val; }
#pragma unroll
    for (int o = 16; o; o >>= 1) { s += __shfl_xor_sync(0xffffffffu, s, o); s2 += __shfl_xor_sync(0xffffffffu, s2, o); }
    __shared__ float sh[8], sh2[8];
    int w = t >> 5, lane = t & 31;
    if (!lane) { sh[w] = s; sh2[w] = s2; }
    __syncthreads();
    __shared__ float mean_s, rstd_s;
    if (t == 0) {
        float S = 0.f, S2 = 0.f;
#pragma unroll
        for (int i = 0; i < 8; i++) { S += sh[i]; S2 += sh2[i]; }
        float mean = S * (1.f/C);
        float var  = S2 * (1.f/C) - mean*mean;
        mean_s = mean; rstd_s = rsqrtf(var + 1e-5f);
    }
    __syncthreads();
    float mean = mean_s, rstd = rstd_s;
#pragma unroll
    for (int i = 0; i < 4; i++) {
        int c = t + 256*i;
        float o = (v[i] - mean) * rstd * g[c] + b[c];
        size_t p = (size_t)row*C + c;
        if (outf) outf[p] = o;
        if (outr) outr[p] = tf32r(o);
        if (outhi) { float hh = tf32r(o); outhi[p] = hh; outlo[p] = tf32r(o - hh); }
    }
}

// ---------------- gate / routing (reads EXACT h2 once; 8 dots per pass) ----------------
__global__ void gate_kernel(const float* __restrict__ gW, const float* __restrict__ gb)
{
    int token = blockIdx.x * 4 + (threadIdx.x >> 5);
    int lane = threadIdx.x & 31;
    const float* hr = g_h2 + (size_t)token * C;
    float acc[E] = {};
    for (int j = lane; j < C; j += 32) {
        float hv = hr[j];
#pragma unroll
        for (int e = 0; e < E; e++) acc[e] += hv * gW[(size_t)e*C + j];
    }
#pragma unroll
    for (int e = 0; e < E; e++)
#pragma unroll
        for (int o = 16; o; o >>= 1) acc[e] += __shfl_xor_sync(0xffffffffu, acc[e], o);
    if (lane == 0) {
        float logits[E];
#pragma unroll
        for (int e = 0; e < E; e++) logits[e] = acc[e] + gb[e];
        int i0 = 0; float m0 = logits[0];
#pragma unroll
        for (int e = 1; e < E; e++) if (logits[e] > m0) { m0 = logits[e]; i0 = e; }
        int i1 = -1; float m1 = -1e30f;
#pragma unroll
        for (int e = 0; e < E; e++) if (e != i0 && logits[e] > m1) { m1 = logits[e]; i1 = e; }
        float den = 0.f;
#pragma unroll
        for (int e = 0; e < E; e++) den += expf(logits[e] - m0);
        float s0 = 1.f / den;
        float s1 = expf(m1 - m0) / den;
        g_expidx[token*2+0] = i0; g_gscore[token*2+0] = s0;
        g_expidx[token*2+1] = i1; g_gscore[token*2+1] = s1;
        g_pos[token*2+0] = atomicAdd(&g_cnt[i0], 1);
        g_pos[token*2+1] = atomicAdd(&g_cnt[i1], 1);
    }
}

__global__ void zero_cnt_kernel() { if (threadIdx.x < E) g_cnt[threadIdx.x] = 0; }

__global__ void scan_kernel()
{
    if (threadIdx.x == 0) {
        int acc = 0;
        for (int e = 0; e < E; e++) { g_off[e] = acc; acc += g_cnt[e]; }
    }
}

__global__ void scatter_kernel()
{
    int i = blockIdx.x * 256 + threadIdx.x;
    if (i < NASSIGN) {
        int e = g_expidx[i];
        int slot = g_off[e] + g_pos[i];
        g_list[slot] = i >> 1;
        g_slotscore[slot] = g_gscore[i];
    }
}

// ---------------- host launcher ----------------
extern "C" void kernel_launch(void* const* d_in, const int* in_sizes, int n_in,
                              void* d_out, int out_size)
{
    const float* x     = (const float*)d_in[0];
    const float* ln1g  = (const float*)d_in[1];
    const float* ln1b  = (const float*)d_in[2];
    const float* Wq    = (const float*)d_in[3];
    const float* Wk    = (const float*)d_in[4];
    const float* Wv    = (const float*)d_in[5];
    const float* Wo    = (const float*)d_in[6];
    const float* bo    = (const float*)d_in[7];
    const float* ln2g  = (const float*)d_in[8];
    const float* ln2b  = (const float*)d_in[9];
    const float* gateW = (const float*)d_in[10];
    const float* gateb = (const float*)d_in[11];
    const float* fcW   = (const float*)d_in[12];
    const float* fcb   = (const float*)d_in[13];
    const float* pjW   = (const float*)d_in[14];
    const float* pjb   = (const float*)d_in[15];
    float* outp = (float*)d_out;

    float *p_hhi, *p_hlo, *p_x1, *p_h2, *p_h2r, *p_fcw, *p_pjw;
    float *p_wqh, *p_wql, *p_wkh, *p_wkl, *p_wvh, *p_wvl, *p_woh, *p_wol;
    cudaGetSymbolAddress((void**)&p_hhi, g_hhi);
    cudaGetSymbolAddress((void**)&p_hlo, g_hlo);
    cudaGetSymbolAddress((void**)&p_x1,  g_x1);
    cudaGetSymbolAddress((void**)&p_h2,  g_h2);
    cudaGetSymbolAddress((void**)&p_h2r, g_h2r);
    cudaGetSymbolAddress((void**)&p_fcw, g_fcw);
    cudaGetSymbolAddress((void**)&p_pjw, g_pjw);
    cudaGetSymbolAddress((void**)&p_wqh, g_wqh); cudaGetSymbolAddress((void**)&p_wql, g_wql);
    cudaGetSymbolAddress((void**)&p_wkh, g_wkh); cudaGetSymbolAddress((void**)&p_wkl, g_wkl);
    cudaGetSymbolAddress((void**)&p_wvh, g_wvh); cudaGetSymbolAddress((void**)&p_wvl, g_wvl);
    cudaGetSymbolAddress((void**)&p_woh, g_woh); cudaGetSymbolAddress((void**)&p_wol, g_wol);

    cudaFuncSetAttribute(gemm_fc_tc,   cudaFuncAttributeMaxDynamicSharedMemorySize, DYNSMEM);
    cudaFuncSetAttribute(gemm_pj_tc,   cudaFuncAttributeMaxDynamicSharedMemorySize, DYNSMEM);
    cudaFuncSetAttribute(gemm3_qkv,    cudaFuncAttributeMaxDynamicSharedMemorySize, DYNSMEM3);
    cudaFuncSetAttribute(gemm3_wo,     cudaFuncAttributeMaxDynamicSharedMemorySize, DYNSMEM3);
    cudaFuncSetAttribute(gemm3_scores, cudaFuncAttributeMaxDynamicSharedMemorySize, DYNSMEM3);
    cudaFuncSetAttribute(gemm3_av,     cudaFuncAttributeMaxDynamicSharedMemorySize, DYNSMEM3);

    zero_cnt_kernel<<<1, 32>>>();

    // MoE weights: unbiased tf32 rounding (pre-pass; in-loop cvt regressed in R9)
    conv_tf32<<<8192, 256>>>(fcW, p_fcw, E*FF*C/4);
    conv_tf32<<<8192, 256>>>(pjW, p_pjw, E*C*FF/4);

    // Attention weights: hi/lo split
    conv_split<<<2048, 256>>>(Wq, p_wqh, p_wql, C*C/4);
    conv_split<<<2048, 256>>>(Wk, p_wkh, p_wkl, C*C/4);
    conv_split<<<2048, 256>>>(Wv, p_wvh, p_wvl, C*C/4);
    conv_split<<<2048, 256>>>(Wo, p_woh, p_wol, C*C/4);

    // LN1 -> split h
    ln_kernel<<<BT, 256>>>(x, ln1g, ln1b, nullptr, nullptr, p_hhi, p_hlo);

    // QKV (3xTF32 MMA): q,k split; v plain
    gemm3_qkv<<<dim3(C/128, BT/128, 3), 256, DYNSMEM3>>>();

    // v transpose + split (padded to 128 rows)
    transp_split<<<dim3(T/32, 4, BH), dim3(32, 8)>>>();

    // attention (3xTF32 MMA, causal-pruned)
    gemm3_scores<<<dim3(T/128, T/128, BH), 256, DYNSMEM3>>>();
    softmax_kernel<<<BH*T, 256>>>();
    gemm3_av<<<dim3(1, T/128, BH), 256, DYNSMEM3>>>();

    // Wo + bias + residual (3xTF32 MMA), dual write
    gemm3_wo<<<dim3(C/128, BT/128), 256, DYNSMEM3>>>(bo, x, p_x1, outp);

    // LN2: exact h2 (gate) + tf32-rounded h2r (fc)
    ln_kernel<<<BT, 256>>>(p_x1, ln2g, ln2b, p_h2, p_h2r, nullptr, nullptr);

    // gating + routing (exact h2)
    gate_kernel<<<BT/4, 128>>>(gateW, gateb);
    scan_kernel<<<1, 32>>>();
    scatter_kernel<<<NASSIGN/256, 256>>>();

    // expert FFN (tf32 MMA, routed top-2; rowTile fastest for L2 weight reuse)
    gemm_fc_tc<<<dim3(BT/128, FF/128, E), 256, DYNSMEM>>>(fcb);
    gemm_pj_tc<<<dim3(BT/128, C/128, E), 256, DYNSMEM>>>(pjb, outp);
}

// round 11
// speedup vs baseline: 1.3022x; 1.2179x over previous
#include <cuda_runtime.h>
#include <cuda_bf16.h>
#include <math.h>
#include <stdint.h>

#define Bb 4
#define T 1024
#define C 1024
#define NH 16
#define HD 64
#define E 8
#define TOPK 2
#define FF 4096
#define BT (Bb*T)
#define BH (Bb*NH)
#define NASSIGN (BT*TOPK)

// smem tile: 128 rows x 144B (fp32: 32 floats+pad / bf16: 64 vals+pad)
#define TILEB (128*144)        // 18432 bytes
#define DYNSMEM  (4*TILEB)     // MoE bf16: A0,A1,B0,B1
#define DYNSMEM3 (8*TILEB)     // split fp32: 147456

// ---------------- scratch ----------------
__device__ float g_hhi[BT*C];
__device__ float g_hlo[BT*C];
__device__ float g_qhi[BT*C];
__device__ float g_qlo[BT*C];
__device__ float g_khi[BT*C];
__device__ float g_klo[BT*C];
__device__ float g_v  [BT*C];
__device__ float g_S  [(size_t)BH*T*T];    // logits, then probs-hi
__device__ float g_Slo[(size_t)BH*T*T];    // probs-lo
__device__ float g_vthi[(size_t)BH*128*T]; // v^T, zero-padded rows 64..127
__device__ float g_vtlo[(size_t)BH*128*T];
__device__ float g_yhi[BT*C];
__device__ float g_ylo[BT*C];
__device__ float g_x1 [BT*C];
__device__ float g_h2 [BT*C];               // exact (gate)
__device__ __nv_bfloat16 g_h2b[BT*C];       // bf16 (fc A)
__device__ __nv_bfloat16 g_h1b[(size_t)NASSIGN*FF];
__device__ float g_wqh[C*C]; __device__ float g_wql[C*C];
__device__ float g_wkh[C*C]; __device__ float g_wkl[C*C];
__device__ float g_wvh[C*C]; __device__ float g_wvl[C*C];
__device__ float g_woh[C*C]; __device__ float g_wol[C*C];
__device__ __nv_bfloat16 g_fcwb[(size_t)E*FF*C];
__device__ __nv_bfloat16 g_pjwb[(size_t)E*C*FF];
__device__ int   g_cnt[E];
__device__ int   g_off[E];
__device__ int   g_expidx[NASSIGN];
__device__ int   g_pos  [NASSIGN];
__device__ float g_gscore[NASSIGN];
__device__ int   g_list [NASSIGN];
__device__ float g_slotscore[NASSIGN];

__device__ __forceinline__ float tf32r(float x){
    float o; asm("cvt.rna.tf32.f32 %0, %1;" : "=f"(o) : "f"(x)); return o;
}

// ---------------- PTX helpers ----------------
__device__ __forceinline__ uint32_t smem_u32(const void* p){
    uint32_t a; asm("{ .reg .u64 t; cvta.to.shared.u64 t, %1; cvt.u32.u64 %0, t; }" : "=r"(a) : "l"(p)); return a;
}
__device__ __forceinline__ void cpa16(uint32_t saddr, const void* g, uint32_t srcsize){
    asm volatile("cp.async.cg.shared.global [%0], [%1], 16, %2;" :: "r"(saddr), "l"(g), "r"(srcsize) : "memory");
}
#define CPA_COMMIT() asm volatile("cp.async.commit_group;" ::: "memory")
#define CPA_WAIT1()  asm volatile("cp.async.wait_group 1;" ::: "memory")
#define CPA_WAIT0()  asm volatile("cp.async.wait_group 0;" ::: "memory")

__device__ __forceinline__ void ldsm_x4(uint32_t &r0, uint32_t &r1, uint32_t &r2, uint32_t &r3, uint32_t addr){
    asm volatile("ldmatrix.sync.aligned.m8n8.x4.shared.b16 {%0,%1,%2,%3},[%4];"
                 : "=r"(r0),"=r"(r1),"=r"(r2),"=r"(r3) : "r"(addr));
}
__device__ __forceinline__ void mma_tf32(float* c, const uint32_t* a, const uint32_t* b){
    asm volatile("mma.sync.aligned.m16n8k8.row.col.f32.tf32.tf32.f32 "
                 "{%0,%1,%2,%3},{%4,%5,%6,%7},{%8,%9},{%0,%1,%2,%3};"
                 : "+f"(c[0]),"+f"(c[1]),"+f"(c[2]),"+f"(c[3])
                 : "r"(a[0]),"r"(a[1]),"r"(a[2]),"r"(a[3]), "r"(b[0]),"r"(b[1]));
}
__device__ __forceinline__ void mma_bf16(float* c, const uint32_t* a, const uint32_t* b){
    asm volatile("mma.sync.aligned.m16n8k16.row.col.f32.bf16.bf16.f32 "
                 "{%0,%1,%2,%3},{%4,%5,%6,%7},{%8,%9},{%0,%1,%2,%3};"
                 : "+f"(c[0]),"+f"(c[1]),"+f"(c[2]),"+f"(c[3])
                 : "r"(a[0]),"r"(a[1]),"r"(a[2]),"r"(a[3]), "r"(b[0]),"r"(b[1]));
}

// =============== fp32 fragment offsets (validated R5+) ===============
__device__ __forceinline__ void frag_offsets(int tid, uint32_t a_off[4], uint32_t b_off[2]){
    int lane = tid & 31, wid = tid >> 5;
    int warpM = wid >> 2, warpN = wid & 3;
#pragma unroll
    for (int mi = 0; mi < 4; mi++) {
        int row = warpM*64 + mi*16 + (lane & 7) + ((lane >> 3) & 1)*8;
        int col4 = (lane >> 4) * 4;
        a_off[mi] = (uint32_t)row*144 + (uint32_t)col4*4;
    }
#pragma unroll
    for (int p = 0; p < 2; p++) {
        int n = warpN*32 + p*16 + (lane & 7) + ((lane >> 4) * 8);
        int col4 = ((lane >> 3) & 1) * 4;
        b_off[p] = (uint32_t)n*144 + (uint32_t)col4*4;
    }
}

// =============== bf16 fragment offsets (validated R4) ===============
__device__ __forceinline__ void frag_offsets_b(int tid, uint32_t a_off[4], uint32_t b_off[2]){
    int lane = tid & 31, wid = tid >> 5;
    int warpM = wid >> 2, warpN = wid & 3;
#pragma unroll
    for (int mi = 0; mi < 4; mi++) {
        int row = warpM*64 + mi*16 + (lane & 15);
        int col = (lane >> 4) * 8;
        a_off[mi] = (uint32_t)row*144 + (uint32_t)col*2;
    }
    int gg = lane >> 3, r = lane & 7;
#pragma unroll
    for (int p = 0; p < 2; p++) {
        int n = warpN*32 + p*16 + ((gg >> 1) << 3) + r;
        b_off[p] = (uint32_t)n*144 + (uint32_t)(gg & 1)*16;
    }
}

// ---------------- bf16 MMA mainloop (MoE): K-chunk = 64 bf16 (128B rows) ----------------
__device__ __forceinline__ void gemmb_mainloop(
    const __nv_bfloat16* const* rowA, const __nv_bfloat16* const* rowB,
    const __nv_bfloat16* dummy, int nchunk, char* sm,
    float acc[4][4][4], int tid)
{
    uint32_t base = smem_u32(sm);
    uint32_t a_off[4], b_off[2];
    frag_offsets_b(tid, a_off, b_off);

#define ISSUEB(kc) do { \
        int b_ = (kc) & 1; \
        uint32_t sa_ = base + b_*TILEB; \
        uint32_t sb_ = base + 2*TILEB + b_*TILEB; \
        _Pragma("unroll") \
        for (int q = 0; q < 4; q++) { \
            int idx = tid + 256*q; \
            int row = idx >> 3, c16 = idx & 7; \
            uint32_t off = (uint32_t)row*144 + c16*16; \
            const __nv_bfloat16* pa = rowA[row]; \
            const void* ga = pa ? (const void*)(pa + (kc)*64 + c16*8) : (const void*)dummy; \
            cpa16(sa_ + off, ga, pa ? 16u : 0u); \
            cpa16(sb_ + off, rowB[row] + (kc)*64 + c16*8, 16u); \
        } \
        CPA_COMMIT(); \
    } while (0)

    ISSUEB(0);
    for (int kc = 0; kc < nchunk; kc++) {
        if (kc + 1 < nchunk) { ISSUEB(kc+1); CPA_WAIT1(); } else { CPA_WAIT0(); }
        __syncthreads();
        int b = kc & 1;
        uint32_t sa = base + b*TILEB;
        uint32_t sb = base + 2*TILEB + b*TILEB;
#pragma unroll
        for (int ks = 0; ks < 4; ks++) {
            uint32_t afr[4][4];
#pragma unroll
            for (int mi = 0; mi < 4; mi++)
                ldsm_x4(afr[mi][0], afr[mi][1], afr[mi][2], afr[mi][3], sa + a_off[mi] + ks*32);
            uint32_t bfr[4][2];
#pragma unroll
            for (int p = 0; p < 2; p++)
                ldsm_x4(bfr[2*p][0], bfr[2*p][1], bfr[2*p+1][0], bfr[2*p+1][1], sb + b_off[p] + ks*32);
#pragma unroll
            for (int mi = 0; mi < 4; mi++)
#pragma unroll
                for (int ni = 0; ni < 4; ni++)
                    mma_bf16(acc[mi][ni], afr[mi], bfr[ni]);
        }
        __syncthreads();
    }
#undef ISSUEB
}

// ---------------- 3xTF32 split mainloop (attention; unchanged, validated) ----------------
__device__ __forceinline__ void gemm3_mainloop(
    const float* Ah, const float* Al, const float* Bh, const float* Bl,
    int lda, int ldb, int nchunk, char* sm, float acc[4][4][4], int tid)
{
    uint32_t base = smem_u32(sm);
    uint32_t a_off[4], b_off[2];
    frag_offsets(tid, a_off, b_off);

#define ISSUE3(kc) do { \
        int b_ = (kc) & 1; \
        uint32_t sah_ = base + b_*TILEB; \
        uint32_t sal_ = base + 2*TILEB + b_*TILEB; \
        uint32_t sbh_ = base + 4*TILEB + b_*TILEB; \
        uint32_t sbl_ = base + 6*TILEB + b_*TILEB; \
        _Pragma("unroll") \
        for (int q = 0; q < 4; q++) { \
            int idx = tid + 256*q; \
            int row = idx >> 3, c16 = idx & 7; \
            uint32_t off = (uint32_t)row*144 + c16*16; \
            size_t goa = (size_t)row*lda + (kc)*32 + c16*4; \
            size_t gob = (size_t)row*ldb + (kc)*32 + c16*4; \
            cpa16(sah_ + off, Ah + goa, 16u); \
            cpa16(sal_ + off, Al + goa, 16u); \
            cpa16(sbh_ + off, Bh + gob, 16u); \
            cpa16(sbl_ + off, Bl + gob, 16u); \
        } \
        CPA_COMMIT(); \
    } while (0)

    ISSUE3(0);
    for (int kc = 0; kc < nchunk; kc++) {
        if (kc + 1 < nchunk) { ISSUE3(kc+1); CPA_WAIT1(); } else { CPA_WAIT0(); }
        __syncthreads();
        int b = kc & 1;
        uint32_t sah = base + b*TILEB;
        uint32_t sal = base + 2*TILEB + b*TILEB;
        uint32_t sbh = base + 4*TILEB + b*TILEB;
        uint32_t sbl = base + 6*TILEB + b*TILEB;
#pragma unroll
        for (int ks = 0; ks < 4; ks++) {
            uint32_t bh[4][2], bl[4][2];
#pragma unroll
            for (int p = 0; p < 2; p++) {
                ldsm_x4(bh[2*p][0], bh[2*p][1], bh[2*p+1][0], bh[2*p+1][1], sbh + b_off[p] + ks*32);
                ldsm_x4(bl[2*p][0], bl[2*p][1], bl[2*p+1][0], bl[2*p+1][1], sbl + b_off[p] + ks*32);
            }
#pragma unroll
            for (int mi = 0; mi < 4; mi++) {
                uint32_t ah[4], al[4];
                ldsm_x4(ah[0], ah[1], ah[2], ah[3], sah + a_off[mi] + ks*32);
                ldsm_x4(al[0], al[1], al[2], al[3], sal + a_off[mi] + ks*32);
#pragma unroll
                for (int ni = 0; ni < 4; ni++) {
                    mma_tf32(acc[mi][ni], ah, bh[ni]);
                    mma_tf32(acc[mi][ni], ah, bl[ni]);
                    mma_tf32(acc[mi][ni], al, bh[ni]);
                }
            }
        }
        __syncthreads();
    }
#undef ISSUE3
}

// ---------------- QKV via 3xTF32; q,k written split, v plain ----------------
__global__ __launch_bounds__(256) void gemm3_qkv()
{
    extern __shared__ char sm[];
    int tid = threadIdx.x;
    int z = blockIdx.z;
    const float* Bh = (z == 0) ? g_wqh : (z == 1) ? g_wkh : g_wvh;
    const float* Bl = (z == 0) ? g_wql : (z == 1) ? g_wkl : g_wvl;
    int rowBase = blockIdx.y * 128, colBase = blockIdx.x * 128;
    float acc[4][4][4] = {};
    gemm3_mainloop(g_hhi + (size_t)rowBase*C, g_hlo + (size_t)rowBase*C,
                   Bh + (size_t)colBase*C,   Bl + (size_t)colBase*C,
                   C, C, C/32, sm, acc, tid);
    int lane = tid & 31, wid = tid >> 5, warpM = wid >> 2, warpN = wid & 3;
    int g = lane >> 2, tg = lane & 3;
    float* Hi = (z == 0) ? g_qhi : g_khi;
    float* Lo = (z == 0) ? g_qlo : g_klo;
#pragma unroll
    for (int mi = 0; mi < 4; mi++)
#pragma unroll
        for (int ni = 0; ni < 4; ni++) {
            int r0 = rowBase + warpM*64 + mi*16 + g;
            int cc = colBase + warpN*32 + ni*8 + tg*2;
#pragma unroll
            for (int h = 0; h < 2; h++) {
                int r = r0 + h*8;
                float v0 = acc[mi][ni][2*h+0];
                float v1 = acc[mi][ni][2*h+1];
                size_t p = (size_t)r*C + cc;
                if (z < 2) {
                    float h0 = tf32r(v0), h1 = tf32r(v1);
                    *(float2*)(Hi + p) = make_float2(h0, h1);
                    *(float2*)(Lo + p) = make_float2(tf32r(v0 - h0), tf32r(v1 - h1));
                } else {
                    *(float2*)(g_v + p) = make_float2(v0, v1);
                }
            }
        }
}

// ---------------- scores via 3xTF32 (K=64, causal tile skip) ----------------
__global__ __launch_bounds__(256) void gemm3_scores()
{
    int z = blockIdx.z; int bb = z >> 4; int hh = z & 15;
    int rowBase = blockIdx.y * 128;
    int colBase = blockIdx.x * 128;
    if (colBase >= rowBase + 128) return;
    extern __shared__ char sm[];
    int tid = threadIdx.x;
    size_t aoff = ((size_t)bb*T + rowBase)*C + hh*HD;
    size_t boff = ((size_t)bb*T + colBase)*C + hh*HD;
    float acc[4][4][4] = {};
    gemm3_mainloop(g_qhi + aoff, g_qlo + aoff, g_khi + boff, g_klo + boff,
                   C, C, HD/32, sm, acc, tid);
    float* Cc = g_S + (size_t)z*T*T;
    int lane = tid & 31, wid = tid >> 5, warpM = wid >> 2, warpN = wid & 3;
    int g = lane >> 2, tg = lane & 3;
#pragma unroll
    for (int mi = 0; mi < 4; mi++)
#pragma unroll
        for (int ni = 0; ni < 4; ni++) {
            int r0 = rowBase + warpM*64 + mi*16 + g;
            int cc = colBase + warpN*32 + ni*8 + tg*2;
#pragma unroll
            for (int h = 0; h < 2; h++) {
                int r = r0 + h*8;
                float* crow = Cc + (size_t)r*T;
                crow[cc]   = (cc   <= r) ? acc[mi][ni][2*h+0]*0.125f : -1e30f;
                crow[cc+1] = (cc+1 <= r) ? acc[mi][ni][2*h+1]*0.125f : -1e30f;
            }
        }
}

// ---------------- row softmax (valid 128-blocks only), split output ----------------
__global__ void softmax_kernel()
{
    size_t row = blockIdx.x;
    int r = (int)(row & (T-1));
    int nv = ((r >> 7) + 1) << 7;
    float* rp  = g_S   + row * T;
    float* rlo = g_Slo + row * T;
    int t = threadIdx.x;
    float v[4]; float m = -1e30f;
#pragma unroll
    for (int i = 0; i < 4; i++) {
        int idx = t + 256*i;
        v[i] = (idx < nv) ? rp[idx] : -1e30f;
        m = fmaxf(m, v[i]);
    }
#pragma unroll
    for (int o = 16; o; o >>= 1) m = fmaxf(m, __shfl_xor_sync(0xffffffffu, m, o));
    __shared__ float sh[8];
    int w = t >> 5, lane = t & 31;
    if (!lane) sh[w] = m;
    __syncthreads();
    __shared__ float m_s, inv_s;
    if (t == 0) {
        float mm = sh[0];
#pragma unroll
        for (int i = 1; i < 8; i++) mm = fmaxf(mm, sh[i]);
        m_s = mm;
    }
    __syncthreads();
    m = m_s;
    float s = 0.f;
#pragma unroll
    for (int i = 0; i < 4; i++) { v[i] = expf(v[i] - m); s += v[i]; }
#pragma unroll
    for (int o = 16; o; o >>= 1) s += __shfl_xor_sync(0xffffffffu, s, o);
    if (!lane) sh[w] = s;
    __syncthreads();
    if (t == 0) {
        float ss = 0.f;
#pragma unroll
        for (int i = 0; i < 8; i++) ss += sh[i];
        inv_s = 1.f / ss;
    }
    __syncthreads();
    float inv = inv_s;
#pragma unroll
    for (int i = 0; i < 4; i++) {
        int idx = t + 256*i;
        if (idx < nv) {
            float p = v[i] * inv;
            float hi = tf32r(p);
            rp[idx]  = hi;
            rlo[idx] = tf32r(p - hi);
        }
    }
}

// ---------------- v transpose + split: vT[bh][c(0..127, pad>=64)][k] ----------------
__global__ void transp_split()
{
    __shared__ float tile[32][33];
    int z  = blockIdx.z;
    int bb = z >> 4, hh = z & 15;
    int c0 = blockIdx.y * 32;
    int k0 = blockIdx.x * 32;
    int tx = threadIdx.x, ty = threadIdx.y;
#pragma unroll
    for (int i = 0; i < 4; i++) {
        int kk = k0 + ty + i*8;
        int cc = c0 + tx;
        float val = (cc < HD) ? g_v[((size_t)bb*T + kk)*C + hh*HD + cc] : 0.f;
        tile[ty + i*8][tx] = val;
    }
    __syncthreads();
#pragma unroll
    for (int i = 0; i < 4; i++) {
        int cc = c0 + ty + i*8;
        int kk = k0 + tx;
        float val = tile[tx][ty + i*8];
        float hi = tf32r(val);
        size_t p = ((size_t)z*128 + cc)*T + kk;
        g_vthi[p] = hi;
        g_vtlo[p] = tf32r(val - hi);
    }
}

// ---------------- AV via 3xTF32 (causal k-bound; N padded to 128, write c<64) ----------------
__global__ __launch_bounds__(256) void gemm3_av()
{
    int z = blockIdx.z; int bb = z >> 4; int hh = z & 15;
    int rowBase = blockIdx.y * 128;
    int nchunk = (rowBase + 128) / 32;
    extern __shared__ char sm[];
    int tid = threadIdx.x;
    size_t aoff = (size_t)z*T*T + (size_t)rowBase*T;
    size_t boff = (size_t)z*128*T;
    float acc[4][4][4] = {};
    gemm3_mainloop(g_S + aoff, g_Slo + aoff, g_vthi + boff, g_vtlo + boff,
                   T, T, nchunk, sm, acc, tid);
    size_t ybase = (size_t)bb*T*C + hh*HD;
    int lane = tid & 31, wid = tid >> 5, warpM = wid >> 2, warpN = wid & 3;
    int g = lane >> 2, tg = lane & 3;
    if (warpN >= 2) return;
#pragma unroll
    for (int mi = 0; mi < 4; mi++)
#pragma unroll
        for (int ni = 0; ni < 4; ni++) {
            int r0 = rowBase + warpM*64 + mi*16 + g;
            int cc = warpN*32 + ni*8 + tg*2;
#pragma unroll
            for (int h = 0; h < 2; h++) {
                int r = r0 + h*8;
                float v0 = acc[mi][ni][2*h+0];
                float v1 = acc[mi][ni][2*h+1];
                float h0 = tf32r(v0), h1 = tf32r(v1);
                size_t p = ybase + (size_t)r*C + cc;
                *(float2*)(g_yhi + p) = make_float2(h0, h1);
                *(float2*)(g_ylo + p) = make_float2(tf32r(v0 - h0), tf32r(v1 - h1));
            }
        }
}

// ---------------- Wo via 3xTF32: out = res + y*Wo^T + bias, dual write ----------------
__global__ __launch_bounds__(256) void gemm3_wo(
    const float* __restrict__ bias, const float* __restrict__ res,
    float* __restrict__ out1, float* __restrict__ out2)
{
    extern __shared__ char sm[];
    int tid = threadIdx.x;
    int rowBase = blockIdx.y * 128, colBase = blockIdx.x * 128;
    float acc[4][4][4] = {};
    gemm3_mainloop(g_yhi + (size_t)rowBase*C, g_ylo + (size_t)rowBase*C,
                   g_woh + (size_t)colBase*C, g_wol + (size_t)colBase*C,
                   C, C, C/32, sm, acc, tid);
    int lane = tid & 31, wid = tid >> 5, warpM = wid >> 2, warpN = wid & 3;
    int g = lane >> 2, tg = lane & 3;
#pragma unroll
    for (int mi = 0; mi < 4; mi++)
#pragma unroll
        for (int ni = 0; ni < 4; ni++) {
            int r0 = rowBase + warpM*64 + mi*16 + g;
            int cc = colBase + warpN*32 + ni*8 + tg*2;
#pragma unroll
            for (int h = 0; h < 2; h++) {
                int r = r0 + h*8;
                float v0 = acc[mi][ni][2*h+0] + bias[cc]   + res[(size_t)r*C + cc];
                float v1 = acc[mi][ni][2*h+1] + bias[cc+1] + res[(size_t)r*C + cc + 1];
                *(float2*)(out1 + (size_t)r*C + cc) = make_float2(v0, v1);
                *(float2*)(out2 + (size_t)r*C + cc) = make_float2(v0, v1);
            }
        }
}

// ---------------- fc (bf16 MMA): gathered A, +bias, GELU, bf16 out ----------------
__global__ __launch_bounds__(256) void gemm_fc_tc(const float* __restrict__ fcb)
{
    int e = blockIdx.z;
    int cnt = g_cnt[e], off = g_off[e];
    int rowBase = blockIdx.x * 128;
    if (rowBase >= cnt) return;
    int colBase = blockIdx.y * 128;
    extern __shared__ char sm[];
    __shared__ const __nv_bfloat16* rowA[128];
    __shared__ const __nv_bfloat16* rowB[128];
    int tid = threadIdx.x;
    const __nv_bfloat16* wbase = g_fcwb + (size_t)e * FF * C;
    if (tid < 128) {
        int r = rowBase + tid;
        rowA[tid] = (r < cnt) ? g_h2b + (size_t)g_list[off + r] * C : nullptr;
        rowB[tid] = wbase + (size_t)(colBase + tid) * C;
    }
    __syncthreads();
    float acc[4][4][4] = {};
    gemmb_mainloop(rowA, rowB, wbase, C/64, sm, acc, tid);
    int lane = tid & 31, wid = tid >> 5, warpM = wid >> 2, warpN = wid & 3;
    int g = lane >> 2, tg = lane & 3;
    const float* fb = fcb + (size_t)e * FF;
#pragma unroll
    for (int mi = 0; mi < 4; mi++)
#pragma unroll
        for (int ni = 0; ni < 4; ni++) {
            int r0 = rowBase + warpM*64 + mi*16 + g;
            int cc = colBase + warpN*32 + ni*8 + tg*2;
#pragma unroll
            for (int h = 0; h < 2; h++) {
                int r = r0 + h*8;
                if (r >= cnt) continue;
                float v0 = acc[mi][ni][2*h+0] + fb[cc];
                float v1 = acc[mi][ni][2*h+1] + fb[cc+1];
                v0 = v0 * 0.5f * (1.f + erff(v0 * 0.70710678118654752f));
                v1 = v1 * 0.5f * (1.f + erff(v1 * 0.70710678118654752f));
                *(__nv_bfloat162*)(g_h1b + (size_t)(off + r)*FF + cc) = __floats2bfloat162_rn(v0, v1);
            }
        }
}

// ---------------- pj (bf16 MMA): +bias, gate-scale, atomicAdd ----------------
__global__ __launch_bounds__(256) void gemm_pj_tc(const float* __restrict__ pjb,
                                                  float* __restrict__ outp)
{
    int e = blockIdx.z;
    int cnt = g_cnt[e], off = g_off[e];
    int rowBase = blockIdx.x * 128;
    if (rowBase >= cnt) return;
    int colBase = blockIdx.y * 128;
    extern __shared__ char sm[];
    __shared__ const __nv_bfloat16* rowA[128];
    __shared__ const __nv_bfloat16* rowB[128];
    int tid = threadIdx.x;
    const __nv_bfloat16* wbase = g_pjwb + (size_t)e * C * FF;
    if (tid < 128) {
        int r = rowBase + tid;
        rowA[tid] = (r < cnt) ? g_h1b + (size_t)(off + r) * FF : nullptr;
        rowB[tid] = wbase + (size_t)(colBase + tid) * FF;
    }
    __syncthreads();
    float acc[4][4][4] = {};
    gemmb_mainloop(rowA, rowB, wbase, FF/64, sm, acc, tid);
    int lane = tid & 31, wid = tid >> 5, warpM = wid >> 2, warpN = wid & 3;
    int g = lane >> 2, tg = lane & 3;
    const float* pb = pjb + (size_t)e * C;
#pragma unroll
    for (int mi = 0; mi < 4; mi++)
#pragma unroll
        for (int ni = 0; ni < 4; ni++) {
            int r0 = rowBase + warpM*64 + mi*16 + g;
            int cc = colBase + warpN*32 + ni*8 + tg*2;
#pragma unroll
            for (int h = 0; h < 2; h++) {
                int r = r0 + h*8;
                if (r >= cnt) continue;
                int tok = g_list[off + r];
                float sc = g_slotscore[off + r];
                float* orow = outp + (size_t)tok * C;
                atomicAdd(&orow[cc],   sc * (acc[mi][ni][2*h+0] + pb[cc]));
                atomicAdd(&orow[cc+1], sc * (acc[mi][ni][2*h+1] + pb[cc+1]));
            }
        }
}

// ---------------- fp32 -> bf16 ----------------
__global__ void conv_f2b(const float* __restrict__ in, __nv_bfloat16* __restrict__ out, int n4)
{
    int stride = gridDim.x * blockDim.x;
    for (int idx = blockIdx.x * blockDim.x + threadIdx.x; idx < n4; idx += stride) {
        float4 v = ((const float4*)in)[idx];
        ((__nv_bfloat162*)out)[idx*2]   = __floats2bfloat162_rn(v.x, v.y);
        ((__nv_bfloat162*)out)[idx*2+1] = __floats2bfloat162_rn(v.z, v.w);
    }
}

// ---------------- fp32 -> (hi, lo) split ----------------
__global__ void conv_split(const float* __restrict__ in, float* __restrict__ hi,
                           float* __restrict__ lo, int n4)
{
    int stride = gridDim.x * blockDim.x;
    for (int idx = blockIdx.x * blockDim.x + threadIdx.x; idx < n4; idx += stride) {
        float4 v = ((const float4*)in)[idx];
        float4 h, l;
        h.x = tf32r(v.x); l.x = tf32r(v.x - h.x);
        h.y = tf32r(v.y); l.y = tf32r(v.y - h.y);
        h.z = tf32r(v.z); l.z = tf32r(v.z - h.z);
        h.w = tf32r(v.w); l.w = tf32r(v.w - h.w);
        ((float4*)hi)[idx] = h;
        ((float4*)lo)[idx] = l;
    }
}

// ---------------- layernorm: exact / bf16 / split outputs ----------------
__global__ void ln_kernel(const float* __restrict__ x, const float* __restrict__ g,
                          const float* __restrict__ b, float* __restrict__ outf,
                          __nv_bfloat16* __restrict__ outb,
                          float* __restrict__ outhi, float* __restrict__ outlo)
{
    int row = blockIdx.x;
    const float* xr = x + (size_t)row * C;
    int t = threadIdx.x;
    float v[4]; float s = 0.f, s2 = 0.f;
#pragma unroll
    for (int i = 0; i < 4; i++) { float val = xr[t + 256*i]; v[i] = val; s += val; s2 += val*val; }
#pragma unroll
    for (int o = 16; o; o >>= 1) { s += __shfl_xor_sync(0xffffffffu, s, o); s2 += __shfl_xor_sync(0xffffffffu, s2, o); }
    __shared__ float sh[8], sh2[8];
    int w = t >> 5, lane = t & 31;
    if (!lane) { sh[w] = s; sh2[w] = s2; }
    __syncthreads();
    __shared__ float mean_s, rstd_s;
    if (t == 0) {
        float S = 0.f, S2 = 0.f;
#pragma unroll
        for (int i = 0; i < 8; i++) { S += sh[i]; S2 += sh2[i]; }
        float mean = S * (1.f/C);
        float var  = S2 * (1.f/C) - mean*mean;
        mean_s = mean; rstd_s = rsqrtf(var + 1e-5f);
    }
    __syncthreads();
    float mean = mean_s, rstd = rstd_s;
#pragma unroll
    for (int i = 0; i < 4; i++) {
        int c = t + 256*i;
        float o = (v[i] - mean) * rstd * g[c] + b[c];
        size_t p = (size_t)row*C + c;
        if (outf) outf[p] = o;
        if (outb) outb[p] = __float2bfloat16(o);
        if (outhi) { float hh = tf32r(o); outhi[p] = hh; outlo[p] = tf32r(o - hh); }
    }
}

// ---------------- gate / routing (reads EXACT h2 once; 8 dots per pass) ----------------
__global__ void gate_kernel(const float* __restrict__ gW, const float* __restrict__ gb)
{
    int token = blockIdx.x * 4 + (threadIdx.x >> 5);
    int lane = threadIdx.x & 31;
    const float* hr = g_h2 + (size_t)token * C;
    float acc[E] = {};
    for (int j = lane; j < C; j += 32) {
        float hv = hr[j];
#pragma unroll
        for (int e = 0; e < E; e++) acc[e] += hv * gW[(size_t)e*C + j];
    }
#pragma unroll
    for (int e = 0; e < E; e++)
#pragma unroll
        for (int o = 16; o; o >>= 1) acc[e] += __shfl_xor_sync(0xffffffffu, acc[e], o);
    if (lane == 0) {
        float logits[E];
#pragma unroll
        for (int e = 0; e < E; e++) logits[e] = acc[e] + gb[e];
        int i0 = 0; float m0 = logits[0];
#pragma unroll
        for (int e = 1; e < E; e++) if (logits[e] > m0) { m0 = logits[e]; i0 = e; }
        int i1 = -1; float m1 = -1e30f;
#pragma unroll
        for (int e = 0; e < E; e++) if (e != i0 && logits[e] > m1) { m1 = logits[e]; i1 = e; }
        float den = 0.f;
#pragma unroll
        for (int e = 0; e < E; e++) den += expf(logits[e] - m0);
        float s0 = 1.f / den;
        float s1 = expf(m1 - m0) / den;
        g_expidx[token*2+0] = i0; g_gscore[token*2+0] = s0;
        g_expidx[token*2+1] = i1; g_gscore[token*2+1] = s1;
        g_pos[token*2+0] = atomicAdd(&g_cnt[i0], 1);
        g_pos[token*2+1] = atomicAdd(&g_cnt[i1], 1);
    }
}

__global__ void zero_cnt_kernel() { if (threadIdx.x < E) g_cnt[threadIdx.x] = 0; }

__global__ void scan_kernel()
{
    if (threadIdx.x == 0) {
        int acc = 0;
        for (int e = 0; e < E; e++) { g_off[e] = acc; acc += g_cnt[e]; }
    }
}

__global__ void scatter_kernel()
{
    int i = blockIdx.x * 256 + threadIdx.x;
    if (i < NASSIGN) {
        int e = g_expidx[i];
        int slot = g_off[e] + g_pos[i];
        g_list[slot] = i >> 1;
        g_slotscore[slot] = g_gscore[i];
    }
}

// ---------------- host launcher ----------------
extern "C" void kernel_launch(void* const* d_in, const int* in_sizes, int n_in,
                              void* d_out, int out_size)
{
    const float* x     = (const float*)d_in[0];
    const float* ln1g  = (const float*)d_in[1];
    const float* ln1b  = (const float*)d_in[2];
    const float* Wq    = (const float*)d_in[3];
    const float* Wk    = (const float*)d_in[4];
    const float* Wv    = (const float*)d_in[5];
    const float* Wo    = (const float*)d_in[6];
    const float* bo    = (const float*)d_in[7];
    const float* ln2g  = (const float*)d_in[8];
    const float* ln2b  = (const float*)d_in[9];
    const float* gateW = (const float*)d_in[10];
    const float* gateb = (const float*)d_in[11];
    const float* fcW   = (const float*)d_in[12];
    const float* fcb   = (const float*)d_in[13];
    const float* pjW   = (const float*)d_in[14];
    const float* pjb   = (const float*)d_in[15];
    float* outp = (float*)d_out;

    float *p_hhi, *p_hlo, *p_x1, *p_h2;
    __nv_bfloat16 *p_h2b, *p_fcwb, *p_pjwb;
    float *p_wqh, *p_wql, *p_wkh, *p_wkl, *p_wvh, *p_wvl, *p_woh, *p_wol;
    cudaGetSymbolAddress((void**)&p_hhi, g_hhi);
    cudaGetSymbolAddress((void**)&p_hlo, g_hlo);
    cudaGetSymbolAddress((void**)&p_x1,  g_x1);
    cudaGetSymbolAddress((void**)&p_h2,  g_h2);
    cudaGetSymbolAddress((void**)&p_h2b, g_h2b);
    cudaGetSymbolAddress((void**)&p_fcwb, g_fcwb);
    cudaGetSymbolAddress((void**)&p_pjwb, g_pjwb);
    cudaGetSymbolAddress((void**)&p_wqh, g_wqh); cudaGetSymbolAddress((void**)&p_wql, g_wql);
    cudaGetSymbolAddress((void**)&p_wkh, g_wkh); cudaGetSymbolAddress((void**)&p_wkl, g_wkl);
    cudaGetSymbolAddress((void**)&p_wvh, g_wvh); cudaGetSymbolAddress((void**)&p_wvl, g_wvl);
    cudaGetSymbolAddress((void**)&p_woh, g_woh); cudaGetSymbolAddress((void**)&p_wol, g_wol);

    cudaFuncSetAttribute(gemm_fc_tc,   cudaFuncAttributeMaxDynamicSharedMemorySize, DYNSMEM);
    cudaFuncSetAttribute(gemm_pj_tc,   cudaFuncAttributeMaxDynamicSharedMemorySize, DYNSMEM);
    cudaFuncSetAttribute(gemm3_qkv,    cudaFuncAttributeMaxDynamicSharedMemorySize, DYNSMEM3);
    cudaFuncSetAttribute(gemm3_wo,     cudaFuncAttributeMaxDynamicSharedMemorySize, DYNSMEM3);
    cudaFuncSetAttribute(gemm3_scores, cudaFuncAttributeMaxDynamicSharedMemorySize, DYNSMEM3);
    cudaFuncSetAttribute(gemm3_av,     cudaFuncAttributeMaxDynamicSharedMemorySize, DYNSMEM3);

    zero_cnt_kernel<<<1, 32>>>();

    // MoE weights -> bf16 (rn)
    conv_f2b<<<8192, 256>>>(fcW, p_fcwb, E*FF*C/4);
    conv_f2b<<<8192, 256>>>(pjW, p_pjwb, E*C*FF/4);

    // Attention weights: hi/lo split
    conv_split<<<2048, 256>>>(Wq, p_wqh, p_wql, C*C/4);
    conv_split<<<2048, 256>>>(Wk, p_wkh, p_wkl, C*C/4);
    conv_split<<<2048, 256>>>(Wv, p_wvh, p_wvl, C*C/4);
    conv_split<<<2048, 256>>>(Wo, p_woh, p_wol, C*C/4);

    // LN1 -> split h
    ln_kernel<<<BT, 256>>>(x, ln1g, ln1b, nullptr, nullptr, p_hhi, p_hlo);

    // QKV (3xTF32 MMA): q,k split; v plain
    gemm3_qkv<<<dim3(C/128, BT/128, 3), 256, DYNSMEM3>>>();

    // v transpose + split (padded to 128 rows)
    transp_split<<<dim3(T/32, 4, BH), dim3(32, 8)>>>();

    // attention (3xTF32 MMA, causal-pruned)
    gemm3_scores<<<dim3(T/128, T/128, BH), 256, DYNSMEM3>>>();
    softmax_kernel<<<BH*T, 256>>>();
    gemm3_av<<<dim3(1, T/128, BH), 256, DYNSMEM3>>>();

    // Wo + bias + residual (3xTF32 MMA), dual write
    gemm3_wo<<<dim3(C/128, BT/128), 256, DYNSMEM3>>>(bo, x, p_x1, outp);

    // LN2: exact h2 (gate) + bf16 h2b (fc A)
    ln_kernel<<<BT, 256>>>(p_x1, ln2g, ln2b, p_h2, p_h2b, nullptr, nullptr);

    // gating + routing (exact h2)
    gate_kernel<<<BT/4, 128>>>(gateW, gateb);
    scan_kernel<<<1, 32>>>();
    scatter_kernel<<<NASSIGN/256, 256>>>();

    // expert FFN (bf16 MMA, routed top-2; rowTile fastest)
    gemm_fc_tc<<<dim3(BT/128, FF/128, E), 256, DYNSMEM>>>(fcb);
    gemm_pj_tc<<<dim3(BT/128, C/128, E), 256, DYNSMEM>>>(pjb, outp);
}

// round 12
// speedup vs baseline: 1.7494x; 1.3435x over previous
#include <cuda_runtime.h>
#include <cuda_bf16.h>
#include <math.h>
#include <stdint.h>

#define Bb 4
#define T 1024
#define C 1024
#define NH 16
#define HD 64
#define E 8
#define TOPK 2
#define FF 4096
#define BT (Bb*T)
#define BH (Bb*NH)
#define NASSIGN (BT*TOPK)

// smem tile: 128 rows x 144B (bf16: 64 vals + 8 pad)
#define TILEB (128*144)        // 18432 bytes
#define DYNSMEM  (4*TILEB)     // MoE bf16: A0,A1,B0,B1
#define DYNSMEM3 (8*TILEB)     // split bf16: Ah0,Ah1,Al0,Al1,Bh0,Bh1,Bl0,Bl1

typedef __nv_bfloat16 bf16;

// ---------------- scratch ----------------
__device__ bf16  g_hbh[BT*C];
__device__ bf16  g_hbl[BT*C];
__device__ bf16  g_qbh[BT*C];
__device__ bf16  g_qbl[BT*C];
__device__ bf16  g_kbh[BT*C];
__device__ bf16  g_kbl[BT*C];
__device__ float g_v  [BT*C];
__device__ float g_S  [(size_t)BH*T*T];    // fp32 logits
__device__ bf16  g_Sbh[(size_t)BH*T*T];    // probs hi
__device__ bf16  g_Sbl[(size_t)BH*T*T];    // probs lo
__device__ bf16  g_vtbh[(size_t)BH*128*T]; // v^T, zero-padded rows 64..127
__device__ bf16  g_vtbl[(size_t)BH*128*T];
__device__ bf16  g_ybh[BT*C];
__device__ bf16  g_ybl[BT*C];
__device__ float g_x1 [BT*C];
__device__ float g_h2 [BT*C];              // exact (gate)
__device__ bf16  g_h2b[BT*C];              // bf16 (fc A)
__device__ bf16  g_h1b[(size_t)NASSIGN*FF];
__device__ bf16  g_wqbh[C*C]; __device__ bf16 g_wqbl[C*C];
__device__ bf16  g_wkbh[C*C]; __device__ bf16 g_wkbl[C*C];
__device__ bf16  g_wvbh[C*C]; __device__ bf16 g_wvbl[C*C];
__device__ bf16  g_wobh[C*C]; __device__ bf16 g_wobl[C*C];
__device__ bf16  g_fcwb[(size_t)E*FF*C];
__device__ bf16  g_pjwb[(size_t)E*C*FF];
__device__ int   g_cnt[E];
__device__ int   g_off[E];
__device__ int   g_expidx[NASSIGN];
__device__ int   g_pos  [NASSIGN];
__device__ float g_gscore[NASSIGN];
__device__ int   g_list [NASSIGN];
__device__ float g_slotscore[NASSIGN];

// ---------------- PTX helpers ----------------
__device__ __forceinline__ uint32_t smem_u32(const void* p){
    uint32_t a; asm("{ .reg .u64 t; cvta.to.shared.u64 t, %1; cvt.u32.u64 %0, t; }" : "=r"(a) : "l"(p)); return a;
}
__device__ __forceinline__ void cpa16(uint32_t saddr, const void* g, uint32_t srcsize){
    asm volatile("cp.async.cg.shared.global [%0], [%1], 16, %2;" :: "r"(saddr), "l"(g), "r"(srcsize) : "memory");
}
#define CPA_COMMIT() asm volatile("cp.async.commit_group;" ::: "memory")
#define CPA_WAIT1()  asm volatile("cp.async.wait_group 1;" ::: "memory")
#define CPA_WAIT0()  asm volatile("cp.async.wait_group 0;" ::: "memory")

__device__ __forceinline__ void ldsm_x4(uint32_t &r0, uint32_t &r1, uint32_t &r2, uint32_t &r3, uint32_t addr){
    asm volatile("ldmatrix.sync.aligned.m8n8.x4.shared.b16 {%0,%1,%2,%3},[%4];"
                 : "=r"(r0),"=r"(r1),"=r"(r2),"=r"(r3) : "r"(addr));
}
__device__ __forceinline__ void mma_bf16(float* c, const uint32_t* a, const uint32_t* b){
    asm volatile("mma.sync.aligned.m16n8k16.row.col.f32.bf16.bf16.f32 "
                 "{%0,%1,%2,%3},{%4,%5,%6,%7},{%8,%9},{%0,%1,%2,%3};"
                 : "+f"(c[0]),"+f"(c[1]),"+f"(c[2]),"+f"(c[3])
                 : "r"(a[0]),"r"(a[1]),"r"(a[2]),"r"(a[3]), "r"(b[0]),"r"(b[1]));
}
__device__ __forceinline__ void bsplit(float v, bf16 &hi, bf16 &lo){
    hi = __float2bfloat16(v);
    lo = __float2bfloat16(v - __bfloat162float(hi));
}

// =============== bf16 fragment offsets (validated R4/R11) ===============
__device__ __forceinline__ void frag_offsets_b(int tid, uint32_t a_off[4], uint32_t b_off[2]){
    int lane = tid & 31, wid = tid >> 5;
    int warpM = wid >> 2, warpN = wid & 3;
#pragma unroll
    for (int mi = 0; mi < 4; mi++) {
        int row = warpM*64 + mi*16 + (lane & 15);
        int col = (lane >> 4) * 8;
        a_off[mi] = (uint32_t)row*144 + (uint32_t)col*2;
    }
    int gg = lane >> 3, r = lane & 7;
#pragma unroll
    for (int p = 0; p < 2; p++) {
        int n = warpN*32 + p*16 + ((gg >> 1) << 3) + r;
        b_off[p] = (uint32_t)n*144 + (uint32_t)(gg & 1)*16;
    }
}

// ---------------- bf16 1x MMA mainloop (MoE): K-chunk = 64 ----------------
__device__ __forceinline__ void gemmb_mainloop(
    const bf16* const* rowA, const bf16* const* rowB,
    const bf16* dummy, int nchunk, char* sm,
    float acc[4][4][4], int tid)
{
    uint32_t base = smem_u32(sm);
    uint32_t a_off[4], b_off[2];
    frag_offsets_b(tid, a_off, b_off);

#define ISSUEB(kc) do { \
        int b_ = (kc) & 1; \
        uint32_t sa_ = base + b_*TILEB; \
        uint32_t sb_ = base + 2*TILEB + b_*TILEB; \
        _Pragma("unroll") \
        for (int q = 0; q < 4; q++) { \
            int idx = tid + 256*q; \
            int row = idx >> 3, c16 = idx & 7; \
            uint32_t off = (uint32_t)row*144 + c16*16; \
            const bf16* pa = rowA[row]; \
            const void* ga = pa ? (const void*)(pa + (kc)*64 + c16*8) : (const void*)dummy; \
            cpa16(sa_ + off, ga, pa ? 16u : 0u); \
            cpa16(sb_ + off, rowB[row] + (kc)*64 + c16*8, 16u); \
        } \
        CPA_COMMIT(); \
    } while (0)

    ISSUEB(0);
    for (int kc = 0; kc < nchunk; kc++) {
        if (kc + 1 < nchunk) { ISSUEB(kc+1); CPA_WAIT1(); } else { CPA_WAIT0(); }
        __syncthreads();
        int b = kc & 1;
        uint32_t sa = base + b*TILEB;
        uint32_t sb = base + 2*TILEB + b*TILEB;
#pragma unroll
        for (int ks = 0; ks < 4; ks++) {
            uint32_t afr[4][4];
#pragma unroll
            for (int mi = 0; mi < 4; mi++)
                ldsm_x4(afr[mi][0], afr[mi][1], afr[mi][2], afr[mi][3], sa + a_off[mi] + ks*32);
            uint32_t bfr[4][2];
#pragma unroll
            for (int p = 0; p < 2; p++)
                ldsm_x4(bfr[2*p][0], bfr[2*p][1], bfr[2*p+1][0], bfr[2*p+1][1], sb + b_off[p] + ks*32);
#pragma unroll
            for (int mi = 0; mi < 4; mi++)
#pragma unroll
                for (int ni = 0; ni < 4; ni++)
                    mma_bf16(acc[mi][ni], afr[mi], bfr[ni]);
        }
        __syncthreads();
    }
#undef ISSUEB
}

// ---------------- split-bf16 3-term mainloop: C += AhBh + AhBl + AlBh ----------------
__device__ __forceinline__ void gemm3b_mainloop(
    const bf16* Ah, const bf16* Al, const bf16* Bh, const bf16* Bl,
    int lda, int ldb, int nchunk, char* sm, float acc[4][4][4], int tid)
{
    uint32_t base = smem_u32(sm);
    uint32_t a_off[4], b_off[2];
    frag_offsets_b(tid, a_off, b_off);

#define ISSUE3B(kc) do { \
        int b_ = (kc) & 1; \
        uint32_t sah_ = base + b_*TILEB; \
        uint32_t sal_ = base + 2*TILEB + b_*TILEB; \
        uint32_t sbh_ = base + 4*TILEB + b_*TILEB; \
        uint32_t sbl_ = base + 6*TILEB + b_*TILEB; \
        _Pragma("unroll") \
        for (int q = 0; q < 4; q++) { \
            int idx = tid + 256*q; \
            int row = idx >> 3, c16 = idx & 7; \
            uint32_t off = (uint32_t)row*144 + c16*16; \
            size_t goa = (size_t)row*lda + (kc)*64 + c16*8; \
            size_t gob = (size_t)row*ldb + (kc)*64 + c16*8; \
            cpa16(sah_ + off, Ah + goa, 16u); \
            cpa16(sal_ + off, Al + goa, 16u); \
            cpa16(sbh_ + off, Bh + gob, 16u); \
            cpa16(sbl_ + off, Bl + gob, 16u); \
        } \
        CPA_COMMIT(); \
    } while (0)

    ISSUE3B(0);
    for (int kc = 0; kc < nchunk; kc++) {
        if (kc + 1 < nchunk) { ISSUE3B(kc+1); CPA_WAIT1(); } else { CPA_WAIT0(); }
        __syncthreads();
        int b = kc & 1;
        uint32_t sah = base + b*TILEB;
        uint32_t sal = base + 2*TILEB + b*TILEB;
        uint32_t sbh = base + 4*TILEB + b*TILEB;
        uint32_t sbl = base + 6*TILEB + b*TILEB;
#pragma unroll
        for (int ks = 0; ks < 4; ks++) {
            uint32_t bh[4][2], bl[4][2];
#pragma unroll
            for (int p = 0; p < 2; p++) {
                ldsm_x4(bh[2*p][0], bh[2*p][1], bh[2*p+1][0], bh[2*p+1][1], sbh + b_off[p] + ks*32);
                ldsm_x4(bl[2*p][0], bl[2*p][1], bl[2*p+1][0], bl[2*p+1][1], sbl + b_off[p] + ks*32);
            }
#pragma unroll
            for (int mi = 0; mi < 4; mi++) {
                uint32_t ah[4], al[4];
                ldsm_x4(ah[0], ah[1], ah[2], ah[3], sah + a_off[mi] + ks*32);
                ldsm_x4(al[0], al[1], al[2], al[3], sal + a_off[mi] + ks*32);
#pragma unroll
                for (int ni = 0; ni < 4; ni++) {
                    mma_bf16(acc[mi][ni], ah, bh[ni]);
                    mma_bf16(acc[mi][ni], ah, bl[ni]);
                    mma_bf16(acc[mi][ni], al, bh[ni]);
                }
            }
        }
        __syncthreads();
    }
#undef ISSUE3B
}

// ---------------- QKV via split-bf16; q,k written split, v plain fp32 ----------------
__global__ __launch_bounds__(256) void gemm3b_qkv()
{
    extern __shared__ char sm[];
    int tid = threadIdx.x;
    int z = blockIdx.z;
    const bf16* Bh = (z == 0) ? g_wqbh : (z == 1) ? g_wkbh : g_wvbh;
    const bf16* Bl = (z == 0) ? g_wqbl : (z == 1) ? g_wkbl : g_wvbl;
    int rowBase = blockIdx.y * 128, colBase = blockIdx.x * 128;
    float acc[4][4][4] = {};
    gemm3b_mainloop(g_hbh + (size_t)rowBase*C, g_hbl + (size_t)rowBase*C,
                    Bh + (size_t)colBase*C,    Bl + (size_t)colBase*C,
                    C, C, C/64, sm, acc, tid);
    int lane = tid & 31, wid = tid >> 5, warpM = wid >> 2, warpN = wid & 3;
    int g = lane >> 2, tg = lane & 3;
    bf16* Hi = (z == 0) ? g_qbh : g_kbh;
    bf16* Lo = (z == 0) ? g_qbl : g_kbl;
#pragma unroll
    for (int mi = 0; mi < 4; mi++)
#pragma unroll
        for (int ni = 0; ni < 4; ni++) {
            int r0 = rowBase + warpM*64 + mi*16 + g;
            int cc = colBase + warpN*32 + ni*8 + tg*2;
#pragma unroll
            for (int h = 0; h < 2; h++) {
                int r = r0 + h*8;
                float v0 = acc[mi][ni][2*h+0];
                float v1 = acc[mi][ni][2*h+1];
                size_t p = (size_t)r*C + cc;
                if (z < 2) {
                    bf16 h0, l0, h1, l1;
                    bsplit(v0, h0, l0); bsplit(v1, h1, l1);
                    Hi[p] = h0; Hi[p+1] = h1;
                    Lo[p] = l0; Lo[p+1] = l1;
                } else {
                    *(float2*)(g_v + p) = make_float2(v0, v1);
                }
            }
        }
}

// ---------------- scores via split-bf16 (K=64 -> 1 chunk, causal tile skip) ----------------
__global__ __launch_bounds__(256) void gemm3b_scores()
{
    int z = blockIdx.z; int bb = z >> 4; int hh = z & 15;
    int rowBase = blockIdx.y * 128;
    int colBase = blockIdx.x * 128;
    if (colBase >= rowBase + 128) return;
    extern __shared__ char sm[];
    int tid = threadIdx.x;
    size_t aoff = ((size_t)bb*T + rowBase)*C + hh*HD;
    size_t boff = ((size_t)bb*T + colBase)*C + hh*HD;
    float acc[4][4][4] = {};
    gemm3b_mainloop(g_qbh + aoff, g_qbl + aoff, g_kbh + boff, g_kbl + boff,
                    C, C, 1, sm, acc, tid);
    float* Cc = g_S + (size_t)z*T*T;
    int lane = tid & 31, wid = tid >> 5, warpM = wid >> 2, warpN = wid & 3;
    int g = lane >> 2, tg = lane & 3;
#pragma unroll
    for (int mi = 0; mi < 4; mi++)
#pragma unroll
        for (int ni = 0; ni < 4; ni++) {
            int r0 = rowBase + warpM*64 + mi*16 + g;
            int cc = colBase + warpN*32 + ni*8 + tg*2;
#pragma unroll
            for (int h = 0; h < 2; h++) {
                int r = r0 + h*8;
                float* crow = Cc + (size_t)r*T;
                crow[cc]   = (cc   <= r) ? acc[mi][ni][2*h+0]*0.125f : -1e30f;
                crow[cc+1] = (cc+1 <= r) ? acc[mi][ni][2*h+1]*0.125f : -1e30f;
            }
        }
}

// ---------------- row softmax (valid 128-blocks only), bf16 split output ----------------
__global__ void softmax_kernel()
{
    size_t row = blockIdx.x;
    int r = (int)(row & (T-1));
    int nv = ((r >> 7) + 1) << 7;
    float* rp  = g_S   + row * T;
    bf16*  rbh = g_Sbh + row * T;
    bf16*  rbl = g_Sbl + row * T;
    int t = threadIdx.x;
    float v[4]; float m = -1e30f;
#pragma unroll
    for (int i = 0; i < 4; i++) {
        int idx = t + 256*i;
        v[i] = (idx < nv) ? rp[idx] : -1e30f;
        m = fmaxf(m, v[i]);
    }
#pragma unroll
    for (int o = 16; o; o >>= 1) m = fmaxf(m, __shfl_xor_sync(0xffffffffu, m, o));
    __shared__ float sh[8];
    int w = t >> 5, lane = t & 31;
    if (!lane) sh[w] = m;
    __syncthreads();
    __shared__ float m_s, inv_s;
    if (t == 0) {
        float mm = sh[0];
#pragma unroll
        for (int i = 1; i < 8; i++) mm = fmaxf(mm, sh[i]);
        m_s = mm;
    }
    __syncthreads();
    m = m_s;
    float s = 0.f;
#pragma unroll
    for (int i = 0; i < 4; i++) { v[i] = expf(v[i] - m); s += v[i]; }
#pragma unroll
    for (int o = 16; o; o >>= 1) s += __shfl_xor_sync(0xffffffffu, s, o);
    if (!lane) sh[w] = s;
    __syncthreads();
    if (t == 0) {
        float ss = 0.f;
#pragma unroll
        for (int i = 0; i < 8; i++) ss += sh[i];
        inv_s = 1.f / ss;
    }
    __syncthreads();
    float inv = inv_s;
#pragma unroll
    for (int i = 0; i < 4; i++) {
        int idx = t + 256*i;
        if (idx < nv) {
            float p = v[i] * inv;
            bf16 hi, lo; bsplit(p, hi, lo);
            rbh[idx] = hi;
            rbl[idx] = lo;
        }
    }
}

// ---------------- v transpose + bf16 split: vT[bh][c(0..127, pad>=64)][k] ----------------
__global__ void transp_split()
{
    __shared__ float tile[32][33];
    int z  = blockIdx.z;
    int bb = z >> 4, hh = z & 15;
    int c0 = blockIdx.y * 32;
    int k0 = blockIdx.x * 32;
    int tx = threadIdx.x, ty = threadIdx.y;
#pragma unroll
    for (int i = 0; i < 4; i++) {
        int kk = k0 + ty + i*8;
        int cc = c0 + tx;
        float val = (cc < HD) ? g_v[((size_t)bb*T + kk)*C + hh*HD + cc] : 0.f;
        tile[ty + i*8][tx] = val;
    }
    __syncthreads();
#pragma unroll
    for (int i = 0; i < 4; i++) {
        int cc = c0 + ty + i*8;
        int kk = k0 + tx;
        float val = tile[tx][ty + i*8];
        bf16 hi, lo; bsplit(val, hi, lo);
        size_t p = ((size_t)z*128 + cc)*T + kk;
        g_vtbh[p] = hi;
        g_vtbl[p] = lo;
    }
}

// ---------------- AV via split-bf16 (causal k-bound; N padded, write c<64) ----------------
__global__ __launch_bounds__(256) void gemm3b_av()
{
    int z = blockIdx.z; int bb = z >> 4; int hh = z & 15;
    int rowBase = blockIdx.y * 128;
    int nchunk = (rowBase + 128) / 64;
    extern __shared__ char sm[];
    int tid = threadIdx.x;
    size_t aoff = (size_t)z*T*T + (size_t)rowBase*T;
    size_t boff = (size_t)z*128*T;
    float acc[4][4][4] = {};
    gemm3b_mainloop(g_Sbh + aoff, g_Sbl + aoff, g_vtbh + boff, g_vtbl + boff,
                    T, T, nchunk, sm, acc, tid);
    size_t ybase = (size_t)bb*T*C + hh*HD;
    int lane = tid & 31, wid = tid >> 5, warpM = wid >> 2, warpN = wid & 3;
    int g = lane >> 2, tg = lane & 3;
    if (warpN >= 2) return;
#pragma unroll
    for (int mi = 0; mi < 4; mi++)
#pragma unroll
        for (int ni = 0; ni < 4; ni++) {
            int r0 = rowBase + warpM*64 + mi*16 + g;
            int cc = warpN*32 + ni*8 + tg*2;
#pragma unroll
            for (int h = 0; h < 2; h++) {
                int r = r0 + h*8;
                float v0 = acc[mi][ni][2*h+0];
                float v1 = acc[mi][ni][2*h+1];
                size_t p = ybase + (size_t)r*C + cc;
                bf16 h0, l0, h1, l1;
                bsplit(v0, h0, l0); bsplit(v1, h1, l1);
                g_ybh[p] = h0; g_ybh[p+1] = h1;
                g_ybl[p] = l0; g_ybl[p+1] = l1;
            }
        }
}

// ---------------- Wo via split-bf16: out = res + y*Wo^T + bias, dual write ----------------
__global__ __launch_bounds__(256) void gemm3b_wo(
    const float* __restrict__ bias, const float* __restrict__ res,
    float* __restrict__ out1, float* __restrict__ out2)
{
    extern __shared__ char sm[];
    int tid = threadIdx.x;
    int rowBase = blockIdx.y * 128, colBase = blockIdx.x * 128;
    float acc[4][4][4] = {};
    gemm3b_mainloop(g_ybh + (size_t)rowBase*C, g_ybl + (size_t)rowBase*C,
                    g_wobh + (size_t)colBase*C, g_wobl + (size_t)colBase*C,
                    C, C, C/64, sm, acc, tid);
    int lane = tid & 31, wid = tid >> 5, warpM = wid >> 2, warpN = wid & 3;
    int g = lane >> 2, tg = lane & 3;
#pragma unroll
    for (int mi = 0; mi < 4; mi++)
#pragma unroll
        for (int ni = 0; ni < 4; ni++) {
            int r0 = rowBase + warpM*64 + mi*16 + g;
            int cc = colBase + warpN*32 + ni*8 + tg*2;
#pragma unroll
            for (int h = 0; h < 2; h++) {
                int r = r0 + h*8;
                float v0 = acc[mi][ni][2*h+0] + bias[cc]   + res[(size_t)r*C + cc];
                float v1 = acc[mi][ni][2*h+1] + bias[cc+1] + res[(size_t)r*C + cc + 1];
                *(float2*)(out1 + (size_t)r*C + cc) = make_float2(v0, v1);
                *(float2*)(out2 + (size_t)r*C + cc) = make_float2(v0, v1);
            }
        }
}

// ---------------- fc (bf16 MMA): gathered A, +bias, GELU, bf16 out ----------------
__global__ __launch_bounds__(256) void gemm_fc_tc(const float* __restrict__ fcb)
{
    int e = blockIdx.z;
    int cnt = g_cnt[e], off = g_off[e];
    int rowBase = blockIdx.x * 128;
    if (rowBase >= cnt) return;
    int colBase = blockIdx.y * 128;
    extern __shared__ char sm[];
    __shared__ const bf16* rowA[128];
    __shared__ const bf16* rowB[128];
    int tid = threadIdx.x;
    const bf16* wbase = g_fcwb + (size_t)e * FF * C;
    if (tid < 128) {
        int r = rowBase + tid;
        rowA[tid] = (r < cnt) ? g_h2b + (size_t)g_list[off + r] * C : nullptr;
        rowB[tid] = wbase + (size_t)(colBase + tid) * C;
    }
    __syncthreads();
    float acc[4][4][4] = {};
    gemmb_mainloop(rowA, rowB, wbase, C/64, sm, acc, tid);
    int lane = tid & 31, wid = tid >> 5, warpM = wid >> 2, warpN = wid & 3;
    int g = lane >> 2, tg = lane & 3;
    const float* fb = fcb + (size_t)e * FF;
#pragma unroll
    for (int mi = 0; mi < 4; mi++)
#pragma unroll
        for (int ni = 0; ni < 4; ni++) {
            int r0 = rowBase + warpM*64 + mi*16 + g;
            int cc = colBase + warpN*32 + ni*8 + tg*2;
#pragma unroll
            for (int h = 0; h < 2; h++) {
                int r = r0 + h*8;
                if (r >= cnt) continue;
                float v0 = acc[mi][ni][2*h+0] + fb[cc];
                float v1 = acc[mi][ni][2*h+1] + fb[cc+1];
                v0 = v0 * 0.5f * (1.f + erff(v0 * 0.70710678118654752f));
                v1 = v1 * 0.5f * (1.f + erff(v1 * 0.70710678118654752f));
                *(__nv_bfloat162*)(g_h1b + (size_t)(off + r)*FF + cc) = __floats2bfloat162_rn(v0, v1);
            }
        }
}

// ---------------- pj (bf16 MMA): +bias, gate-scale, atomicAdd ----------------
__global__ __launch_bounds__(256) void gemm_pj_tc(const float* __restrict__ pjb,
                                                  float* __restrict__ outp)
{
    int e = blockIdx.z;
    int cnt = g_cnt[e], off = g_off[e];
    int rowBase = blockIdx.x * 128;
    if (rowBase >= cnt) return;
    int colBase = blockIdx.y * 128;
    extern __shared__ char sm[];
    __shared__ const bf16* rowA[128];
    __shared__ const bf16* rowB[128];
    int tid = threadIdx.x;
    const bf16* wbase = g_pjwb + (size_t)e * C * FF;
    if (tid < 128) {
        int r = rowBase + tid;
        rowA[tid] = (r < cnt) ? g_h1b + (size_t)(off + r) * FF : nullptr;
        rowB[tid] = wbase + (size_t)(colBase + tid) * FF;
    }
    __syncthreads();
    float acc[4][4][4] = {};
    gemmb_mainloop(rowA, rowB, wbase, FF/64, sm, acc, tid);
    int lane = tid & 31, wid = tid >> 5, warpM = wid >> 2, warpN = wid & 3;
    int g = lane >> 2, tg = lane & 3;
    const float* pb = pjb + (size_t)e * C;
#pragma unroll
    for (int mi = 0; mi < 4; mi++)
#pragma unroll
        for (int ni = 0; ni < 4; ni++) {
            int r0 = rowBase + warpM*64 + mi*16 + g;
            int cc = colBase + warpN*32 + ni*8 + tg*2;
#pragma unroll
            for (int h = 0; h < 2; h++) {
                int r = r0 + h*8;
                if (r >= cnt) continue;
                int tok = g_list[off + r];
                float sc = g_slotscore[off + r];
                float* orow = outp + (size_t)tok * C;
                atomicAdd(&orow[cc],   sc * (acc[mi][ni][2*h+0] + pb[cc]));
                atomicAdd(&orow[cc+1], sc * (acc[mi][ni][2*h+1] + pb[cc+1]));
            }
        }
}

// ---------------- fp32 -> bf16 ----------------
__global__ void conv_f2b(const float* __restrict__ in, bf16* __restrict__ out, int n4)
{
    int stride = gridDim.x * blockDim.x;
    for (int idx = blockIdx.x * blockDim.x + threadIdx.x; idx < n4; idx += stride) {
        float4 v = ((const float4*)in)[idx];
        ((__nv_bfloat162*)out)[idx*2]   = __floats2bfloat162_rn(v.x, v.y);
        ((__nv_bfloat162*)out)[idx*2+1] = __floats2bfloat162_rn(v.z, v.w);
    }
}

// ---------------- fp32 -> bf16 (hi, lo) split ----------------
__global__ void conv_splitb(const float* __restrict__ in, bf16* __restrict__ hi,
                            bf16* __restrict__ lo, int n4)
{
    int stride = gridDim.x * blockDim.x;
    for (int idx = blockIdx.x * blockDim.x + threadIdx.x; idx < n4; idx += stride) {
        float4 v = ((const float4*)in)[idx];
        bf16 h0,l0,h1,l1,h2,l2,h3,l3;
        bsplit(v.x, h0, l0); bsplit(v.y, h1, l1);
        bsplit(v.z, h2, l2); bsplit(v.w, h3, l3);
        ((__nv_bfloat162*)hi)[idx*2]   = __nv_bfloat162(h0, h1);
        ((__nv_bfloat162*)hi)[idx*2+1] = __nv_bfloat162(h2, h3);
        ((__nv_bfloat162*)lo)[idx*2]   = __nv_bfloat162(l0, l1);
        ((__nv_bfloat162*)lo)[idx*2+1] = __nv_bfloat162(l2, l3);
    }
}

// ---------------- layernorm: exact / bf16 / bf16-split outputs ----------------
__global__ void ln_kernel(const float* __restrict__ x, const float* __restrict__ g,
                          const float* __restrict__ b, float* __restrict__ outf,
                          bf16* __restrict__ outb,
                          bf16* __restrict__ outhi, bf16* __restrict__ outlo)
{
    int row = blockIdx.x;
    const float* xr = x + (size_t)row * C;
    int t = threadIdx.x;
    float v[4]; float s = 0.f, s2 = 0.f;
#pragma unroll
    for (int i = 0; i < 4; i++) { float val = xr[t + 256*i]; v[i] = val; s += val; s2 += val*val; }
#pragma unroll
    for (int o = 16; o; o >>= 1) { s += __shfl_xor_sync(0xffffffffu, s, o); s2 += __shfl_xor_sync(0xffffffffu, s2, o); }
    __shared__ float sh[8], sh2[8];
    int w = t >> 5, lane = t & 31;
    if (!lane) { sh[w] = s; sh2[w] = s2; }
    __syncthreads();
    __shared__ float mean_s, rstd_s;
    if (t == 0) {
        float S = 0.f, S2 = 0.f;
#pragma unroll
        for (int i = 0; i < 8; i++) { S += sh[i]; S2 += sh2[i]; }
        float mean = S * (1.f/C);
        float var  = S2 * (1.f/C) - mean*mean;
        mean_s = mean; rstd_s = rsqrtf(var + 1e-5f);
    }
    __syncthreads();
    float mean = mean_s, rstd = rstd_s;
#pragma unroll
    for (int i = 0; i < 4; i++) {
        int c = t + 256*i;
        float o = (v[i] - mean) * rstd * g[c] + b[c];
        size_t p = (size_t)row*C + c;
        if (outf) outf[p] = o;
        if (outb) outb[p] = __float2bfloat16(o);
        if (outhi) { bf16 hh, ll; bsplit(o, hh, ll); outhi[p] = hh; outlo[p] = ll; }
    }
}

// ---------------- gate / routing (reads EXACT h2 once; 8 dots per pass) ----------------
__global__ void gate_kernel(const float* __restrict__ gW, const float* __restrict__ gb)
{
    int token = blockIdx.x * 4 + (threadIdx.x >> 5);
    int lane = threadIdx.x & 31;
    const float* hr = g_h2 + (size_t)token * C;
    float acc[E] = {};
    for (int j = lane; j < C; j += 32) {
        float hv = hr[j];
#pragma unroll
        for (int e = 0; e < E; e++) acc[e] += hv * gW[(size_t)e*C + j];
    }
#pragma unroll
    for (int e = 0; e < E; e++)
#pragma unroll
        for (int o = 16; o; o >>= 1) acc[e] += __shfl_xor_sync(0xffffffffu, acc[e], o);
    if (lane == 0) {
        float logits[E];
#pragma unroll
        for (int e = 0; e < E; e++) logits[e] = acc[e] + gb[e];
        int i0 = 0; float m0 = logits[0];
#pragma unroll
        for (int e = 1; e < E; e++) if (logits[e] > m0) { m0 = logits[e]; i0 = e; }
        int i1 = -1; float m1 = -1e30f;
#pragma unroll
        for (int e = 0; e < E; e++) if (e != i0 && logits[e] > m1) { m1 = logits[e]; i1 = e; }
        float den = 0.f;
#pragma unroll
        for (int e = 0; e < E; e++) den += expf(logits[e] - m0);
        float s0 = 1.f / den;
        float s1 = expf(m1 - m0) / den;
        g_expidx[token*2+0] = i0; g_gscore[token*2+0] = s0;
        g_expidx[token*2+1] = i1; g_gscore[token*2+1] = s1;
        g_pos[token*2+0] = atomicAdd(&g_cnt[i0], 1);
        g_pos[token*2+1] = atomicAdd(&g_cnt[i1], 1);
    }
}

__global__ void zero_cnt_kernel() { if (threadIdx.x < E) g_cnt[threadIdx.x] = 0; }

__global__ void scan_kernel()
{
    if (threadIdx.x == 0) {
        int acc = 0;
        for (int e = 0; e < E; e++) { g_off[e] = acc; acc += g_cnt[e]; }
    }
}

__global__ void scatter_kernel()
{
    int i = blockIdx.x * 256 + threadIdx.x;
    if (i < NASSIGN) {
        int e = g_expidx[i];
        int slot = g_off[e] + g_pos[i];
        g_list[slot] = i >> 1;
        g_slotscore[slot] = g_gscore[i];
    }
}

// ---------------- host launcher ----------------
extern "C" void kernel_launch(void* const* d_in, const int* in_sizes, int n_in,
                              void* d_out, int out_size)
{
    const float* x     = (const float*)d_in[0];
    const float* ln1g  = (const float*)d_in[1];
    const float* ln1b  = (const float*)d_in[2];
    const float* Wq    = (const float*)d_in[3];
    const float* Wk    = (const float*)d_in[4];
    const float* Wv    = (const float*)d_in[5];
    const float* Wo    = (const float*)d_in[6];
    const float* bo    = (const float*)d_in[7];
    const float* ln2g  = (const float*)d_in[8];
    const float* ln2b  = (const float*)d_in[9];
    const float* gateW = (const float*)d_in[10];
    const float* gateb = (const float*)d_in[11];
    const float* fcW   = (const float*)d_in[12];
    const float* fcb   = (const float*)d_in[13];
    const float* pjW   = (const float*)d_in[14];
    const float* pjb   = (const float*)d_in[15];
    float* outp = (float*)d_out;

    float *p_x1, *p_h2;
    bf16 *p_hbh, *p_hbl, *p_h2b, *p_fcwb, *p_pjwb;
    bf16 *p_wqbh, *p_wqbl, *p_wkbh, *p_wkbl, *p_wvbh, *p_wvbl, *p_wobh, *p_wobl;
    cudaGetSymbolAddress((void**)&p_x1,  g_x1);
    cudaGetSymbolAddress((void**)&p_h2,  g_h2);
    cudaGetSymbolAddress((void**)&p_hbh, g_hbh);
    cudaGetSymbolAddress((void**)&p_hbl, g_hbl);
    cudaGetSymbolAddress((void**)&p_h2b, g_h2b);
    cudaGetSymbolAddress((void**)&p_fcwb, g_fcwb);
    cudaGetSymbolAddress((void**)&p_pjwb, g_pjwb);
    cudaGetSymbolAddress((void**)&p_wqbh, g_wqbh); cudaGetSymbolAddress((void**)&p_wqbl, g_wqbl);
    cudaGetSymbolAddress((void**)&p_wkbh, g_wkbh); cudaGetSymbolAddress((void**)&p_wkbl, g_wkbl);
    cudaGetSymbolAddress((void**)&p_wvbh, g_wvbh); cudaGetSymbolAddress((void**)&p_wvbl, g_wvbl);
    cudaGetSymbolAddress((void**)&p_wobh, g_wobh); cudaGetSymbolAddress((void**)&p_wobl, g_wobl);

    cudaFuncSetAttribute(gemm_fc_tc,    cudaFuncAttributeMaxDynamicSharedMemorySize, DYNSMEM);
    cudaFuncSetAttribute(gemm_pj_tc,    cudaFuncAttributeMaxDynamicSharedMemorySize, DYNSMEM);
    cudaFuncSetAttribute(gemm3b_qkv,    cudaFuncAttributeMaxDynamicSharedMemorySize, DYNSMEM3);
    cudaFuncSetAttribute(gemm3b_wo,     cudaFuncAttributeMaxDynamicSharedMemorySize, DYNSMEM3);
    cudaFuncSetAttribute(gemm3b_scores, cudaFuncAttributeMaxDynamicSharedMemorySize, DYNSMEM3);
    cudaFuncSetAttribute(gemm3b_av,     cudaFuncAttributeMaxDynamicSharedMemorySize, DYNSMEM3);

    zero_cnt_kernel<<<1, 32>>>();

    // MoE weights -> bf16
    conv_f2b<<<8192, 256>>>(fcW, p_fcwb, E*FF*C/4);
    conv_f2b<<<8192, 256>>>(pjW, p_pjwb, E*C*FF/4);

    // Attention weights: bf16 hi/lo split
    conv_splitb<<<2048, 256>>>(Wq, p_wqbh, p_wqbl, C*C/4);
    conv_splitb<<<2048, 256>>>(Wk, p_wkbh, p_wkbl, C*C/4);
    conv_splitb<<<2048, 256>>>(Wv, p_wvbh, p_wvbl, C*C/4);
    conv_splitb<<<2048, 256>>>(Wo, p_wobh, p_wobl, C*C/4);

    // LN1 -> bf16 split h
    ln_kernel<<<BT, 256>>>(x, ln1g, ln1b, nullptr, nullptr, p_hbh, p_hbl);

    // QKV (split-bf16 MMA): q,k split; v plain
    gemm3b_qkv<<<dim3(C/128, BT/128, 3), 256, DYNSMEM3>>>();

    // v transpose + bf16 split (padded to 128 rows)
    transp_split<<<dim3(T/32, 4, BH), dim3(32, 8)>>>();

    // attention (split-bf16 MMA, causal-pruned)
    gemm3b_scores<<<dim3(T/128, T/128, BH), 256, DYNSMEM3>>>();
    softmax_kernel<<<BH*T, 256>>>();
    gemm3b_av<<<dim3(1, T/128, BH), 256, DYNSMEM3>>>();

    // Wo + bias + residual (split-bf16 MMA), dual write
    gemm3b_wo<<<dim3(C/128, BT/128), 256, DYNSMEM3>>>(bo, x, p_x1, outp);

    // LN2: exact h2 (gate) + bf16 h2b (fc A)
    ln_kernel<<<BT, 256>>>(p_x1, ln2g, ln2b, p_h2, p_h2b, nullptr, nullptr);

    // gating + routing (exact h2)
    gate_kernel<<<BT/4, 128>>>(gateW, gateb);
    scan_kernel<<<1, 32>>>();
    scatter_kernel<<<NASSIGN/256, 256>>>();

    // expert FFN (bf16 MMA, routed top-2)
    gemm_fc_tc<<<dim3(BT/128, FF/128, E), 256, DYNSMEM>>>(fcb);
    gemm_pj_tc<<<dim3(BT/128, C/128, E), 256, DYNSMEM>>>(pjb, outp);
}

// round 13
// speedup vs baseline: 1.7934x; 1.0251x over previous
#include <cuda_runtime.h>
#include <cuda_bf16.h>
#include <math.h>
#include <stdint.h>

#define Bb 4
#define T 1024
#define C 1024
#define NH 16
#define HD 64
#define E 8
#define TOPK 2
#define FF 4096
#define BT (Bb*T)
#define BH (Bb*NH)
#define NASSIGN (BT*TOPK)

// smem tile: 128 rows x 144B (bf16: 64 vals + 8 pad)
#define TILEB (128*144)        // 18432 bytes
#define DYNSMEM  (4*TILEB)     // MoE bf16: A0,A1,B0,B1
#define DYNSMEM3 (8*TILEB)     // split bf16: Ah0,Ah1,Al0,Al1,Bh0,Bh1,Bl0,Bl1
// AV: A tiles 256 rows, B tiles 64 rows
#define TILEB_A (256*144)      // 36864
#define TILEB_B (64*144)       // 9216
#define DYNSMEM_AV (4*TILEB_A + 4*TILEB_B)  // 184320

typedef __nv_bfloat16 bf16;

// ---------------- scratch ----------------
__device__ bf16  g_hbh[BT*C];
__device__ bf16  g_hbl[BT*C];
__device__ bf16  g_qbh[BT*C];
__device__ bf16  g_qbl[BT*C];
__device__ bf16  g_kbh[BT*C];
__device__ bf16  g_kbl[BT*C];
__device__ float g_v  [BT*C];
__device__ float g_S  [(size_t)BH*T*T];    // fp32 logits
__device__ bf16  g_Sbh[(size_t)BH*T*T];    // probs hi
__device__ bf16  g_Sbl[(size_t)BH*T*T];    // probs lo
__device__ bf16  g_vtbh[(size_t)BH*128*T]; // v^T (rows 0..63 used)
__device__ bf16  g_vtbl[(size_t)BH*128*T];
__device__ bf16  g_ybh[BT*C];
__device__ bf16  g_ybl[BT*C];
__device__ float g_x1 [BT*C];
__device__ float g_h2 [BT*C];              // exact (gate)
__device__ bf16  g_h2b[BT*C];              // bf16 (fc A)
__device__ bf16  g_h1b[(size_t)NASSIGN*FF];
__device__ bf16  g_wqbh[C*C]; __device__ bf16 g_wqbl[C*C];
__device__ bf16  g_wkbh[C*C]; __device__ bf16 g_wkbl[C*C];
__device__ bf16  g_wvbh[C*C]; __device__ bf16 g_wvbl[C*C];
__device__ bf16  g_wobh[C*C]; __device__ bf16 g_wobl[C*C];
__device__ bf16  g_fcwb[(size_t)E*FF*C];
__device__ bf16  g_pjwb[(size_t)E*C*FF];
__device__ int   g_cnt[E];
__device__ int   g_off[E];
__device__ int   g_expidx[NASSIGN];
__device__ int   g_pos  [NASSIGN];
__device__ float g_gscore[NASSIGN];
__device__ int   g_list [NASSIGN];
__device__ float g_slotscore[NASSIGN];

// ---------------- PTX helpers ----------------
__device__ __forceinline__ uint32_t smem_u32(const void* p){
    uint32_t a; asm("{ .reg .u64 t; cvta.to.shared.u64 t, %1; cvt.u32.u64 %0, t; }" : "=r"(a) : "l"(p)); return a;
}
__device__ __forceinline__ void cpa16(uint32_t saddr, const void* g, uint32_t srcsize){
    asm volatile("cp.async.cg.shared.global [%0], [%1], 16, %2;" :: "r"(saddr), "l"(g), "r"(srcsize) : "memory");
}
#define CPA_COMMIT() asm volatile("cp.async.commit_group;" ::: "memory")
#define CPA_WAIT1()  asm volatile("cp.async.wait_group 1;" ::: "memory")
#define CPA_WAIT0()  asm volatile("cp.async.wait_group 0;" ::: "memory")

__device__ __forceinline__ void ldsm_x4(uint32_t &r0, uint32_t &r1, uint32_t &r2, uint32_t &r3, uint32_t addr){
    asm volatile("ldmatrix.sync.aligned.m8n8.x4.shared.b16 {%0,%1,%2,%3},[%4];"
                 : "=r"(r0),"=r"(r1),"=r"(r2),"=r"(r3) : "r"(addr));
}
__device__ __forceinline__ void mma_bf16(float* c, const uint32_t* a, const uint32_t* b){
    asm volatile("mma.sync.aligned.m16n8k16.row.col.f32.bf16.bf16.f32 "
                 "{%0,%1,%2,%3},{%4,%5,%6,%7},{%8,%9},{%0,%1,%2,%3};"
                 : "+f"(c[0]),"+f"(c[1]),"+f"(c[2]),"+f"(c[3])
                 : "r"(a[0]),"r"(a[1]),"r"(a[2]),"r"(a[3]), "r"(b[0]),"r"(b[1]));
}
__device__ __forceinline__ void bsplit(float v, bf16 &hi, bf16 &lo){
    hi = __float2bfloat16(v);
    lo = __float2bfloat16(v - __bfloat162float(hi));
}

// =============== bf16 fragment offsets, 128x128 tiles (validated R4/R11) ===============
__device__ __forceinline__ void frag_offsets_b(int tid, uint32_t a_off[4], uint32_t b_off[2]){
    int lane = tid & 31, wid = tid >> 5;
    int warpM = wid >> 2, warpN = wid & 3;
#pragma unroll
    for (int mi = 0; mi < 4; mi++) {
        int row = warpM*64 + mi*16 + (lane & 15);
        int col = (lane >> 4) * 8;
        a_off[mi] = (uint32_t)row*144 + (uint32_t)col*2;
    }
    int gg = lane >> 3, r = lane & 7;
#pragma unroll
    for (int p = 0; p < 2; p++) {
        int n = warpN*32 + p*16 + ((gg >> 1) << 3) + r;
        b_off[p] = (uint32_t)n*144 + (uint32_t)(gg & 1)*16;
    }
}

// ---------------- bf16 1x MMA mainloop (MoE): K-chunk = 64 ----------------
__device__ __forceinline__ void gemmb_mainloop(
    const bf16* const* rowA, const bf16* const* rowB,
    const bf16* dummy, int nchunk, char* sm,
    float acc[4][4][4], int tid)
{
    uint32_t base = smem_u32(sm);
    uint32_t a_off[4], b_off[2];
    frag_offsets_b(tid, a_off, b_off);

#define ISSUEB(kc) do { \
        int b_ = (kc) & 1; \
        uint32_t sa_ = base + b_*TILEB; \
        uint32_t sb_ = base + 2*TILEB + b_*TILEB; \
        _Pragma("unroll") \
        for (int q = 0; q < 4; q++) { \
            int idx = tid + 256*q; \
            int row = idx >> 3, c16 = idx & 7; \
            uint32_t off = (uint32_t)row*144 + c16*16; \
            const bf16* pa = rowA[row]; \
            const void* ga = pa ? (const void*)(pa + (kc)*64 + c16*8) : (const void*)dummy; \
            cpa16(sa_ + off, ga, pa ? 16u : 0u); \
            cpa16(sb_ + off, rowB[row] + (kc)*64 + c16*8, 16u); \
        } \
        CPA_COMMIT(); \
    } while (0)

    ISSUEB(0);
    for (int kc = 0; kc < nchunk; kc++) {
        if (kc + 1 < nchunk) { ISSUEB(kc+1); CPA_WAIT1(); } else { CPA_WAIT0(); }
        __syncthreads();
        int b = kc & 1;
        uint32_t sa = base + b*TILEB;
        uint32_t sb = base + 2*TILEB + b*TILEB;
#pragma unroll
        for (int ks = 0; ks < 4; ks++) {
            uint32_t afr[4][4];
#pragma unroll
            for (int mi = 0; mi < 4; mi++)
                ldsm_x4(afr[mi][0], afr[mi][1], afr[mi][2], afr[mi][3], sa + a_off[mi] + ks*32);
            uint32_t bfr[4][2];
#pragma unroll
            for (int p = 0; p < 2; p++)
                ldsm_x4(bfr[2*p][0], bfr[2*p][1], bfr[2*p+1][0], bfr[2*p+1][1], sb + b_off[p] + ks*32);
#pragma unroll
            for (int mi = 0; mi < 4; mi++)
#pragma unroll
                for (int ni = 0; ni < 4; ni++)
                    mma_bf16(acc[mi][ni], afr[mi], bfr[ni]);
        }
        __syncthreads();
    }
#undef ISSUEB
}

// ---------------- split-bf16 3-term mainloop (128x128): C += AhBh + AhBl + AlBh ----------------
__device__ __forceinline__ void gemm3b_mainloop(
    const bf16* Ah, const bf16* Al, const bf16* Bh, const bf16* Bl,
    int lda, int ldb, int nchunk, char* sm, float acc[4][4][4], int tid)
{
    uint32_t base = smem_u32(sm);
    uint32_t a_off[4], b_off[2];
    frag_offsets_b(tid, a_off, b_off);

#define ISSUE3B(kc) do { \
        int b_ = (kc) & 1; \
        uint32_t sah_ = base + b_*TILEB; \
        uint32_t sal_ = base + 2*TILEB + b_*TILEB; \
        uint32_t sbh_ = base + 4*TILEB + b_*TILEB; \
        uint32_t sbl_ = base + 6*TILEB + b_*TILEB; \
        _Pragma("unroll") \
        for (int q = 0; q < 4; q++) { \
            int idx = tid + 256*q; \
            int row = idx >> 3, c16 = idx & 7; \
            uint32_t off = (uint32_t)row*144 + c16*16; \
            size_t goa = (size_t)row*lda + (kc)*64 + c16*8; \
            size_t gob = (size_t)row*ldb + (kc)*64 + c16*8; \
            cpa16(sah_ + off, Ah + goa, 16u); \
            cpa16(sal_ + off, Al + goa, 16u); \
            cpa16(sbh_ + off, Bh + gob, 16u); \
            cpa16(sbl_ + off, Bl + gob, 16u); \
        } \
        CPA_COMMIT(); \
    } while (0)

    ISSUE3B(0);
    for (int kc = 0; kc < nchunk; kc++) {
        if (kc + 1 < nchunk) { ISSUE3B(kc+1); CPA_WAIT1(); } else { CPA_WAIT0(); }
        __syncthreads();
        int b = kc & 1;
        uint32_t sah = base + b*TILEB;
        uint32_t sal = base + 2*TILEB + b*TILEB;
        uint32_t sbh = base + 4*TILEB + b*TILEB;
        uint32_t sbl = base + 6*TILEB + b*TILEB;
#pragma unroll
        for (int ks = 0; ks < 4; ks++) {
            uint32_t bh[4][2], bl[4][2];
#pragma unroll
            for (int p = 0; p < 2; p++) {
                ldsm_x4(bh[2*p][0], bh[2*p][1], bh[2*p+1][0], bh[2*p+1][1], sbh + b_off[p] + ks*32);
                ldsm_x4(bl[2*p][0], bl[2*p][1], bl[2*p+1][0], bl[2*p+1][1], sbl + b_off[p] + ks*32);
            }
#pragma unroll
            for (int mi = 0; mi < 4; mi++) {
                uint32_t ah[4], al[4];
                ldsm_x4(ah[0], ah[1], ah[2], ah[3], sah + a_off[mi] + ks*32);
                ldsm_x4(al[0], al[1], al[2], al[3], sal + a_off[mi] + ks*32);
#pragma unroll
                for (int ni = 0; ni < 4; ni++) {
                    mma_bf16(acc[mi][ni], ah, bh[ni]);
                    mma_bf16(acc[mi][ni], ah, bl[ni]);
                    mma_bf16(acc[mi][ni], al, bh[ni]);
                }
            }
        }
        __syncthreads();
    }
#undef ISSUE3B
}

// ---------------- QKV via split-bf16; q,k written split, v plain fp32 ----------------
__global__ __launch_bounds__(256) void gemm3b_qkv()
{
    extern __shared__ char sm[];
    int tid = threadIdx.x;
    int z = blockIdx.z;
    const bf16* Bh = (z == 0) ? g_wqbh : (z == 1) ? g_wkbh : g_wvbh;
    const bf16* Bl = (z == 0) ? g_wqbl : (z == 1) ? g_wkbl : g_wvbl;
    int rowBase = blockIdx.y * 128, colBase = blockIdx.x * 128;
    float acc[4][4][4] = {};
    gemm3b_mainloop(g_hbh + (size_t)rowBase*C, g_hbl + (size_t)rowBase*C,
                    Bh + (size_t)colBase*C,    Bl + (size_t)colBase*C,
                    C, C, C/64, sm, acc, tid);
    int lane = tid & 31, wid = tid >> 5, warpM = wid >> 2, warpN = wid & 3;
    int g = lane >> 2, tg = lane & 3;
    bf16* Hi = (z == 0) ? g_qbh : g_kbh;
    bf16* Lo = (z == 0) ? g_qbl : g_kbl;
#pragma unroll
    for (int mi = 0; mi < 4; mi++)
#pragma unroll
        for (int ni = 0; ni < 4; ni++) {
            int r0 = rowBase + warpM*64 + mi*16 + g;
            int cc = colBase + warpN*32 + ni*8 + tg*2;
#pragma unroll
            for (int h = 0; h < 2; h++) {
                int r = r0 + h*8;
                float v0 = acc[mi][ni][2*h+0];
                float v1 = acc[mi][ni][2*h+1];
                size_t p = (size_t)r*C + cc;
                if (z < 2) {
                    bf16 h0, l0, h1, l1;
                    bsplit(v0, h0, l0); bsplit(v1, h1, l1);
                    Hi[p] = h0; Hi[p+1] = h1;
                    Lo[p] = l0; Lo[p+1] = l1;
                } else {
                    *(float2*)(g_v + p) = make_float2(v0, v1);
                }
            }
        }
}

// ---------------- scores via split-bf16 (K=64 -> 1 chunk, causal tile skip) ----------------
__global__ __launch_bounds__(256) void gemm3b_scores()
{
    int z = blockIdx.z; int bb = z >> 4; int hh = z & 15;
    int rowBase = blockIdx.y * 128;
    int colBase = blockIdx.x * 128;
    if (colBase >= rowBase + 128) return;
    extern __shared__ char sm[];
    int tid = threadIdx.x;
    size_t aoff = ((size_t)bb*T + rowBase)*C + hh*HD;
    size_t boff = ((size_t)bb*T + colBase)*C + hh*HD;
    float acc[4][4][4] = {};
    gemm3b_mainloop(g_qbh + aoff, g_qbl + aoff, g_kbh + boff, g_kbl + boff,
                    C, C, 1, sm, acc, tid);
    float* Cc = g_S + (size_t)z*T*T;
    int lane = tid & 31, wid = tid >> 5, warpM = wid >> 2, warpN = wid & 3;
    int g = lane >> 2, tg = lane & 3;
#pragma unroll
    for (int mi = 0; mi < 4; mi++)
#pragma unroll
        for (int ni = 0; ni < 4; ni++) {
            int r0 = rowBase + warpM*64 + mi*16 + g;
            int cc = colBase + warpN*32 + ni*8 + tg*2;
#pragma unroll
            for (int h = 0; h < 2; h++) {
                int r = r0 + h*8;
                float* crow = Cc + (size_t)r*T;
                crow[cc]   = (cc   <= r) ? acc[mi][ni][2*h+0]*0.125f : -1e30f;
                crow[cc+1] = (cc+1 <= r) ? acc[mi][ni][2*h+1]*0.125f : -1e30f;
            }
        }
}

// ---------------- row softmax: read logits [0,nv128), write probs zero-padded to nv256 ----------------
__global__ void softmax_kernel()
{
    size_t row = blockIdx.x;
    int r = (int)(row & (T-1));
    int nv  = ((r >> 7) + 1) << 7;   // valid (read) bound, 128-aligned
    int nv2 = ((r >> 8) + 1) << 8;   // write bound, 256-aligned (AV-256 reads this far)
    float* rp  = g_S   + row * T;
    bf16*  rbh = g_Sbh + row * T;
    bf16*  rbl = g_Sbl + row * T;
    int t = threadIdx.x;
    float v[4]; float m = -1e30f;
#pragma unroll
    for (int i = 0; i < 4; i++) {
        int idx = t + 256*i;
        v[i] = (idx < nv) ? rp[idx] : -1e30f;
        m = fmaxf(m, v[i]);
    }
#pragma unroll
    for (int o = 16; o; o >>= 1) m = fmaxf(m, __shfl_xor_sync(0xffffffffu, m, o));
    __shared__ float sh[8];
    int w = t >> 5, lane = t & 31;
    if (!lane) sh[w] = m;
    __syncthreads();
    __shared__ float m_s, inv_s;
    if (t == 0) {
        float mm = sh[0];
#pragma unroll
        for (int i = 1; i < 8; i++) mm = fmaxf(mm, sh[i]);
        m_s = mm;
    }
    __syncthreads();
    m = m_s;
    float s = 0.f;
#pragma unroll
    for (int i = 0; i < 4; i++) { v[i] = expf(v[i] - m); s += v[i]; }
#pragma unroll
    for (int o = 16; o; o >>= 1) s += __shfl_xor_sync(0xffffffffu, s, o);
    if (!lane) sh[w] = s;
    __syncthreads();
    if (t == 0) {
        float ss = 0.f;
#pragma unroll
        for (int i = 0; i < 8; i++) ss += sh[i];
        inv_s = 1.f / ss;
    }
    __syncthreads();
    float inv = inv_s;
#pragma unroll
    for (int i = 0; i < 4; i++) {
        int idx = t + 256*i;
        if (idx < nv) {
            float p = v[i] * inv;
            bf16 hi, lo; bsplit(p, hi, lo);
            rbh[idx] = hi;
            rbl[idx] = lo;
        } else if (idx < nv2) {
            rbh[idx] = __float2bfloat16(0.f);
            rbl[idx] = __float2bfloat16(0.f);
        }
    }
}

// ---------------- v transpose + bf16 split: vT[bh][c(0..63)][k] ----------------
__global__ void transp_split()
{
    __shared__ float tile[32][33];
    int z  = blockIdx.z;
    int bb = z >> 4, hh = z & 15;
    int c0 = blockIdx.y * 32;            // 0, 32
    int k0 = blockIdx.x * 32;
    int tx = threadIdx.x, ty = threadIdx.y;
#pragma unroll
    for (int i = 0; i < 4; i++) {
        int kk = k0 + ty + i*8;
        int cc = c0 + tx;
        tile[ty + i*8][tx] = g_v[((size_t)bb*T + kk)*C + hh*HD + cc];
    }
    __syncthreads();
#pragma unroll
    for (int i = 0; i < 4; i++) {
        int cc = c0 + ty + i*8;
        int kk = k0 + tx;
        float val = tile[tx][ty + i*8];
        bf16 hi, lo; bsplit(val, hi, lo);
        size_t p = ((size_t)z*128 + cc)*T + kk;
        g_vtbh[p] = hi;
        g_vtbl[p] = lo;
    }
}

// ---------------- AV via split-bf16, M=256 x N=64 (no padding waste) ----------------
__global__ __launch_bounds__(256) void gemm3b_av()
{
    int z = blockIdx.z; int bb = z >> 4; int hh = z & 15;
    int rowBase = blockIdx.y * 256;
    int nchunk = (rowBase + 256) / 64;   // causal k-bound (probs zero-padded to nv256)
    extern __shared__ char sm[];
    int tid = threadIdx.x;
    uint32_t base = smem_u32(sm);
    const bf16* Ah = g_Sbh + (size_t)z*T*T + (size_t)rowBase*T;
    const bf16* Al = g_Sbl + (size_t)z*T*T + (size_t)rowBase*T;
    const bf16* Bh = g_vtbh + (size_t)z*128*T;
    const bf16* Bl = g_vtbl + (size_t)z*128*T;

    // fragment offsets for 4x2 warp grid (M=256, N=64)
    int lane = tid & 31, wid = tid >> 5;
    int warpM = wid >> 1, warpN = wid & 1;
    uint32_t a_off[4], b_off[2];
#pragma unroll
    for (int mi = 0; mi < 4; mi++) {
        int row = warpM*64 + mi*16 + (lane & 15);
        int col = (lane >> 4) * 8;
        a_off[mi] = (uint32_t)row*144 + (uint32_t)col*2;
    }
    {
        int gg = lane >> 3, rr = lane & 7;
#pragma unroll
        for (int p = 0; p < 2; p++) {
            int n = warpN*32 + p*16 + ((gg >> 1) << 3) + rr;
            b_off[p] = (uint32_t)n*144 + (uint32_t)(gg & 1)*16;
        }
    }
    float acc[4][4][4] = {};

    // smem layout: Ah0 Ah1 Al0 Al1 (TILEB_A each), Bh0 Bh1 Bl0 Bl1 (TILEB_B each)
#define AV_ISSUE(kc) do { \
        int b_ = (kc) & 1; \
        uint32_t sah_ = base + b_*TILEB_A; \
        uint32_t sal_ = base + 2*TILEB_A + b_*TILEB_A; \
        uint32_t sbh_ = base + 4*TILEB_A + b_*TILEB_B; \
        uint32_t sbl_ = base + 4*TILEB_A + 2*TILEB_B + b_*TILEB_B; \
        _Pragma("unroll") \
        for (int q = 0; q < 8; q++) { \
            int idx = tid + 256*q; \
            int row = idx >> 3, c16 = idx & 7; \
            uint32_t off = (uint32_t)row*144 + c16*16; \
            size_t go = (size_t)row*T + (kc)*64 + c16*8; \
            cpa16(sah_ + off, Ah + go, 16u); \
            cpa16(sal_ + off, Al + go, 16u); \
        } \
        _Pragma("unroll") \
        for (int q = 0; q < 2; q++) { \
            int idx = tid + 256*q; \
            int row = idx >> 3, c16 = idx & 7; \
            uint32_t off = (uint32_t)row*144 + c16*16; \
            size_t go = (size_t)row*T + (kc)*64 + c16*8; \
            cpa16(sbh_ + off, Bh + go, 16u); \
            cpa16(sbl_ + off, Bl + go, 16u); \
        } \
        CPA_COMMIT(); \
    } while (0)

    AV_ISSUE(0);
    for (int kc = 0; kc < nchunk; kc++) {
        if (kc + 1 < nchunk) { AV_ISSUE(kc+1); CPA_WAIT1(); } else { CPA_WAIT0(); }
        __syncthreads();
        int b = kc & 1;
        uint32_t sah = base + b*TILEB_A;
        uint32_t sal = base + 2*TILEB_A + b*TILEB_A;
        uint32_t sbh = base + 4*TILEB_A + b*TILEB_B;
        uint32_t sbl = base + 4*TILEB_A + 2*TILEB_B + b*TILEB_B;
#pragma unroll
        for (int ks = 0; ks < 4; ks++) {
            uint32_t bh[4][2], bl[4][2];
#pragma unroll
            for (int p = 0; p < 2; p++) {
                ldsm_x4(bh[2*p][0], bh[2*p][1], bh[2*p+1][0], bh[2*p+1][1], sbh + b_off[p] + ks*32);
                ldsm_x4(bl[2*p][0], bl[2*p][1], bl[2*p+1][0], bl[2*p+1][1], sbl + b_off[p] + ks*32);
            }
#pragma unroll
            for (int mi = 0; mi < 4; mi++) {
                uint32_t ah[4], al[4];
                ldsm_x4(ah[0], ah[1], ah[2], ah[3], sah + a_off[mi] + ks*32);
                ldsm_x4(al[0], al[1], al[2], al[3], sal + a_off[mi] + ks*32);
#pragma unroll
                for (int ni = 0; ni < 4; ni++) {
                    mma_bf16(acc[mi][ni], ah, bh[ni]);
                    mma_bf16(acc[mi][ni], ah, bl[ni]);
                    mma_bf16(acc[mi][ni], al, bh[ni]);
                }
            }
        }
        __syncthreads();
    }
#undef AV_ISSUE

    size_t ybase = (size_t)bb*T*C + hh*HD;
    int g = lane >> 2, tg = lane & 3;
#pragma unroll
    for (int mi = 0; mi < 4; mi++)
#pragma unroll
        for (int ni = 0; ni < 4; ni++) {
            int r0 = rowBase + warpM*64 + mi*16 + g;
            int cc = warpN*32 + ni*8 + tg*2;
#pragma unroll
            for (int h = 0; h < 2; h++) {
                int r = r0 + h*8;
                float v0 = acc[mi][ni][2*h+0];
                float v1 = acc[mi][ni][2*h+1];
                size_t p = ybase + (size_t)r*C + cc;
                bf16 h0, l0, h1, l1;
                bsplit(v0, h0, l0); bsplit(v1, h1, l1);
                g_ybh[p] = h0; g_ybh[p+1] = h1;
                g_ybl[p] = l0; g_ybl[p+1] = l1;
            }
        }
}

// ---------------- Wo via split-bf16: out = res + y*Wo^T + bias, dual write ----------------
__global__ __launch_bounds__(256) void gemm3b_wo(
    const float* __restrict__ bias, const float* __restrict__ res,
    float* __restrict__ out1, float* __restrict__ out2)
{
    extern __shared__ char sm[];
    int tid = threadIdx.x;
    int rowBase = blockIdx.y * 128, colBase = blockIdx.x * 128;
    float acc[4][4][4] = {};
    gemm3b_mainloop(g_ybh + (size_t)rowBase*C, g_ybl + (size_t)rowBase*C,
                    g_wobh + (size_t)colBase*C, g_wobl + (size_t)colBase*C,
                    C, C, C/64, sm, acc, tid);
    int lane = tid & 31, wid = tid >> 5, warpM = wid >> 2, warpN = wid & 3;
    int g = lane >> 2, tg = lane & 3;
#pragma unroll
    for (int mi = 0; mi < 4; mi++)
#pragma unroll
        for (int ni = 0; ni < 4; ni++) {
            int r0 = rowBase + warpM*64 + mi*16 + g;
            int cc = colBase + warpN*32 + ni*8 + tg*2;
#pragma unroll
            for (int h = 0; h < 2; h++) {
                int r = r0 + h*8;
                float v0 = acc[mi][ni][2*h+0] + bias[cc]   + res[(size_t)r*C + cc];
                float v1 = acc[mi][ni][2*h+1] + bias[cc+1] + res[(size_t)r*C + cc + 1];
                *(float2*)(out1 + (size_t)r*C + cc) = make_float2(v0, v1);
                *(float2*)(out2 + (size_t)r*C + cc) = make_float2(v0, v1);
            }
        }
}

// ---------------- fc (bf16 MMA): gathered A, +bias, GELU, bf16 out ----------------
__global__ __launch_bounds__(256) void gemm_fc_tc(const float* __restrict__ fcb)
{
    int e = blockIdx.z;
    int cnt = g_cnt[e], off = g_off[e];
    int rowBase = blockIdx.x * 128;
    if (rowBase >= cnt) return;
    int colBase = blockIdx.y * 128;
    extern __shared__ char sm[];
    __shared__ const bf16* rowA[128];
    __shared__ const bf16* rowB[128];
    int tid = threadIdx.x;
    const bf16* wbase = g_fcwb + (size_t)e * FF * C;
    if (tid < 128) {
        int r = rowBase + tid;
        rowA[tid] = (r < cnt) ? g_h2b + (size_t)g_list[off + r] * C : nullptr;
        rowB[tid] = wbase + (size_t)(colBase + tid) * C;
    }
    __syncthreads();
    float acc[4][4][4] = {};
    gemmb_mainloop(rowA, rowB, wbase, C/64, sm, acc, tid);
    int lane = tid & 31, wid = tid >> 5, warpM = wid >> 2, warpN = wid & 3;
    int g = lane >> 2, tg = lane & 3;
    const float* fb = fcb + (size_t)e * FF;
#pragma unroll
    for (int mi = 0; mi < 4; mi++)
#pragma unroll
        for (int ni = 0; ni < 4; ni++) {
            int r0 = rowBase + warpM*64 + mi*16 + g;
            int cc = colBase + warpN*32 + ni*8 + tg*2;
#pragma unroll
            for (int h = 0; h < 2; h++) {
                int r = r0 + h*8;
                if (r >= cnt) continue;
                float v0 = acc[mi][ni][2*h+0] + fb[cc];
                float v1 = acc[mi][ni][2*h+1] + fb[cc+1];
                v0 = v0 * 0.5f * (1.f + erff(v0 * 0.70710678118654752f));
                v1 = v1 * 0.5f * (1.f + erff(v1 * 0.70710678118654752f));
                *(__nv_bfloat162*)(g_h1b + (size_t)(off + r)*FF + cc) = __floats2bfloat162_rn(v0, v1);
            }
        }
}

// ---------------- pj (bf16 MMA): +bias, gate-scale, atomicAdd ----------------
__global__ __launch_bounds__(256) void gemm_pj_tc(const float* __restrict__ pjb,
                                                  float* __restrict__ outp)
{
    int e = blockIdx.z;
    int cnt = g_cnt[e], off = g_off[e];
    int rowBase = blockIdx.x * 128;
    if (rowBase >= cnt) return;
    int colBase = blockIdx.y * 128;
    extern __shared__ char sm[];
    __shared__ const bf16* rowA[128];
    __shared__ const bf16* rowB[128];
    int tid = threadIdx.x;
    const bf16* wbase = g_pjwb + (size_t)e * C * FF;
    if (tid < 128) {
        int r = rowBase + tid;
        rowA[tid] = (r < cnt) ? g_h1b + (size_t)(off + r) * FF : nullptr;
        rowB[tid] = wbase + (size_t)(colBase + tid) * FF;
    }
    __syncthreads();
    float acc[4][4][4] = {};
    gemmb_mainloop(rowA, rowB, wbase, FF/64, sm, acc, tid);
    int lane = tid & 31, wid = tid >> 5, warpM = wid >> 2, warpN = wid & 3;
    int g = lane >> 2, tg = lane & 3;
    const float* pb = pjb + (size_t)e * C;
#pragma unroll
    for (int mi = 0; mi < 4; mi++)
#pragma unroll
        for (int ni = 0; ni < 4; ni++) {
            int r0 = rowBase + warpM*64 + mi*16 + g;
            int cc = colBase + warpN*32 + ni*8 + tg*2;
#pragma unroll
            for (int h = 0; h < 2; h++) {
                int r = r0 + h*8;
                if (r >= cnt) continue;
                int tok = g_list[off + r];
                float sc = g_slotscore[off + r];
                float* orow = outp + (size_t)tok * C;
                atomicAdd(&orow[cc],   sc * (acc[mi][ni][2*h+0] + pb[cc]));
                atomicAdd(&orow[cc+1], sc * (acc[mi][ni][2*h+1] + pb[cc+1]));
            }
        }
}

// ---------------- fp32 -> bf16 ----------------
__global__ void conv_f2b(const float* __restrict__ in, bf16* __restrict__ out, int n4)
{
    int stride = gridDim.x * blockDim.x;
    for (int idx = blockIdx.x * blockDim.x + threadIdx.x; idx < n4; idx += stride) {
        float4 v = ((const float4*)in)[idx];
        ((__nv_bfloat162*)out)[idx*2]   = __floats2bfloat162_rn(v.x, v.y);
        ((__nv_bfloat162*)out)[idx*2+1] = __floats2bfloat162_rn(v.z, v.w);
    }
}

// ---------------- fp32 -> bf16 (hi, lo) split ----------------
__global__ void conv_splitb(const float* __restrict__ in, bf16* __restrict__ hi,
                            bf16* __restrict__ lo, int n4)
{
    int stride = gridDim.x * blockDim.x;
    for (int idx = blockIdx.x * blockDim.x + threadIdx.x; idx < n4; idx += stride) {
        float4 v = ((const float4*)in)[idx];
        bf16 h0,l0,h1,l1,h2,l2,h3,l3;
        bsplit(v.x, h0, l0); bsplit(v.y, h1, l1);
        bsplit(v.z, h2, l2); bsplit(v.w, h3, l3);
        ((__nv_bfloat162*)hi)[idx*2]   = __nv_bfloat162(h0, h1);
        ((__nv_bfloat162*)hi)[idx*2+1] = __nv_bfloat162(h2, h3);
        ((__nv_bfloat162*)lo)[idx*2]   = __nv_bfloat162(l0, l1);
        ((__nv_bfloat162*)lo)[idx*2+1] = __nv_bfloat162(l2, l3);
    }
}

// ---------------- layernorm: exact / bf16 / bf16-split outputs ----------------
__global__ void ln_kernel(const float* __restrict__ x, const float* __restrict__ g,
                          const float* __restrict__ b, float* __restrict__ outf,
                          bf16* __restrict__ outb,
                          bf16* __restrict__ outhi, bf16* __restrict__ outlo)
{
    int row = blockIdx.x;
    const float* xr = x + (size_t)row * C;
    int t = threadIdx.x;
    float v[4]; float s = 0.f, s2 = 0.f;
#pragma unroll
    for (int i = 0; i < 4; i++) { float val = xr[t + 256*i]; v[i] = val; s += val; s2 += val*val; }
#pragma unroll
    for (int o = 16; o; o >>= 1) { s += __shfl_xor_sync(0xffffffffu, s, o); s2 += __shfl_xor_sync(0xffffffffu, s2, o); }
    __shared__ float sh[8], sh2[8];
    int w = t >> 5, lane = t & 31;
    if (!lane) { sh[w] = s; sh2[w] = s2; }
    __syncthreads();
    __shared__ float mean_s, rstd_s;
    if (t == 0) {
        float S = 0.f, S2 = 0.f;
#pragma unroll
        for (int i = 0; i < 8; i++) { S += sh[i]; S2 += sh2[i]; }
        float mean = S * (1.f/C);
        float var  = S2 * (1.f/C) - mean*mean;
        mean_s = mean; rstd_s = rsqrtf(var + 1e-5f);
    }
    __syncthreads();
    float mean = mean_s, rstd = rstd_s;
#pragma unroll
    for (int i = 0; i < 4; i++) {
        int c = t + 256*i;
        float o = (v[i] - mean) * rstd * g[c] + b[c];
        size_t p = (size_t)row*C + c;
        if (outf) outf[p] = o;
        if (outb) outb[p] = __float2bfloat16(o);
        if (outhi) { bf16 hh, ll; bsplit(o, hh, ll); outhi[p] = hh; outlo[p] = ll; }
    }
}

// ---------------- gate / routing (reads EXACT h2 once; 8 dots per pass) ----------------
__global__ void gate_kernel(const float* __restrict__ gW, const float* __restrict__ gb)
{
    int token = blockIdx.x * 4 + (threadIdx.x >> 5);
    int lane = threadIdx.x & 31;
    const float* hr = g_h2 + (size_t)token * C;
    float acc[E] = {};
    for (int j = lane; j < C; j += 32) {
        float hv = hr[j];
#pragma unroll
        for (int e = 0; e < E; e++) acc[e] += hv * gW[(size_t)e*C + j];
    }
#pragma unroll
    for (int e = 0; e < E; e++)
#pragma unroll
        for (int o = 16; o; o >>= 1) acc[e] += __shfl_xor_sync(0xffffffffu, acc[e], o);
    if (lane == 0) {
        float logits[E];
#pragma unroll
        for (int e = 0; e < E; e++) logits[e] = acc[e] + gb[e];
        int i0 = 0; float m0 = logits[0];
#pragma unroll
        for (int e = 1; e < E; e++) if (logits[e] > m0) { m0 = logits[e]; i0 = e; }
        int i1 = -1; float m1 = -1e30f;
#pragma unroll
        for (int e = 0; e < E; e++) if (e != i0 && logits[e] > m1) { m1 = logits[e]; i1 = e; }
        float den = 0.f;
#pragma unroll
        for (int e = 0; e < E; e++) den += expf(logits[e] - m0);
        float s0 = 1.f / den;
        float s1 = expf(m1 - m0) / den;
        g_expidx[token*2+0] = i0; g_gscore[token*2+0] = s0;
        g_expidx[token*2+1] = i1; g_gscore[token*2+1] = s1;
        g_pos[token*2+0] = atomicAdd(&g_cnt[i0], 1);
        g_pos[token*2+1] = atomicAdd(&g_cnt[i1], 1);
    }
}

__global__ void zero_cnt_kernel() { if (threadIdx.x < E) g_cnt[threadIdx.x] = 0; }

__global__ void scan_kernel()
{
    if (threadIdx.x == 0) {
        int acc = 0;
        for (int e = 0; e < E; e++) { g_off[e] = acc; acc += g_cnt[e]; }
    }
}

__global__ void scatter_kernel()
{
    int i = blockIdx.x * 256 + threadIdx.x;
    if (i < NASSIGN) {
        int e = g_expidx[i];
        int slot = g_off[e] + g_pos[i];
        g_list[slot] = i >> 1;
        g_slotscore[slot] = g_gscore[i];
    }
}

// ---------------- host launcher ----------------
extern "C" void kernel_launch(void* const* d_in, const int* in_sizes, int n_in,
                              void* d_out, int out_size)
{
    const float* x     = (const float*)d_in[0];
    const float* ln1g  = (const float*)d_in[1];
    const float* ln1b  = (const float*)d_in[2];
    const float* Wq    = (const float*)d_in[3];
    const float* Wk    = (const float*)d_in[4];
    const float* Wv    = (const float*)d_in[5];
    const float* Wo    = (const float*)d_in[6];
    const float* bo    = (const float*)d_in[7];
    const float* ln2g  = (const float*)d_in[8];
    const float* ln2b  = (const float*)d_in[9];
    const float* gateW = (const float*)d_in[10];
    const float* gateb = (const float*)d_in[11];
    const float* fcW   = (const float*)d_in[12];
    const float* fcb   = (const float*)d_in[13];
    const float* pjW   = (const float*)d_in[14];
    const float* pjb   = (const float*)d_in[15];
    float* outp = (float*)d_out;

    float *p_x1, *p_h2;
    bf16 *p_hbh, *p_hbl, *p_h2b, *p_fcwb, *p_pjwb;
    bf16 *p_wqbh, *p_wqbl, *p_wkbh, *p_wkbl, *p_wvbh, *p_wvbl, *p_wobh, *p_wobl;
    cudaGetSymbolAddress((void**)&p_x1,  g_x1);
    cudaGetSymbolAddress((void**)&p_h2,  g_h2);
    cudaGetSymbolAddress((void**)&p_hbh, g_hbh);
    cudaGetSymbolAddress((void**)&p_hbl, g_hbl);
    cudaGetSymbolAddress((void**)&p_h2b, g_h2b);
    cudaGetSymbolAddress((void**)&p_fcwb, g_fcwb);
    cudaGetSymbolAddress((void**)&p_pjwb, g_pjwb);
    cudaGetSymbolAddress((void**)&p_wqbh, g_wqbh); cudaGetSymbolAddress((void**)&p_wqbl, g_wqbl);
    cudaGetSymbolAddress((void**)&p_wkbh, g_wkbh); cudaGetSymbolAddress((void**)&p_wkbl, g_wkbl);
    cudaGetSymbolAddress((void**)&p_wvbh, g_wvbh); cudaGetSymbolAddress((void**)&p_wvbl, g_wvbl);
    cudaGetSymbolAddress((void**)&p_wobh, g_wobh); cudaGetSymbolAddress((void**)&p_wobl, g_wobl);

    cudaFuncSetAttribute(gemm_fc_tc,    cudaFuncAttributeMaxDynamicSharedMemorySize, DYNSMEM);
    cudaFuncSetAttribute(gemm_pj_tc,    cudaFuncAttributeMaxDynamicSharedMemorySize, DYNSMEM);
    cudaFuncSetAttribute(gemm3b_qkv,    cudaFuncAttributeMaxDynamicSharedMemorySize, DYNSMEM3);
    cudaFuncSetAttribute(gemm3b_wo,     cudaFuncAttributeMaxDynamicSharedMemorySize, DYNSMEM3);
    cudaFuncSetAttribute(gemm3b_scores, cudaFuncAttributeMaxDynamicSharedMemorySize, DYNSMEM3);
    cudaFuncSetAttribute(gemm3b_av,     cudaFuncAttributeMaxDynamicSharedMemorySize, DYNSMEM_AV);

    zero_cnt_kernel<<<1, 32>>>();

    // MoE weights -> bf16
    conv_f2b<<<8192, 256>>>(fcW, p_fcwb, E*FF*C/4);
    conv_f2b<<<8192, 256>>>(pjW, p_pjwb, E*C*FF/4);

    // Attention weights: bf16 hi/lo split
    conv_splitb<<<2048, 256>>>(Wq, p_wqbh, p_wqbl, C*C/4);
    conv_splitb<<<2048, 256>>>(Wk, p_wkbh, p_wkbl, C*C/4);
    conv_splitb<<<2048, 256>>>(Wv, p_wvbh, p_wvbl, C*C/4);
    conv_splitb<<<2048, 256>>>(Wo, p_wobh, p_wobl, C*C/4);

    // LN1 -> bf16 split h
    ln_kernel<<<BT, 256>>>(x, ln1g, ln1b, nullptr, nullptr, p_hbh, p_hbl);

    // QKV (split-bf16 MMA): q,k split; v plain
    gemm3b_qkv<<<dim3(C/128, BT/128, 3), 256, DYNSMEM3>>>();

    // v transpose + bf16 split (64 rows used)
    transp_split<<<dim3(T/32, 2, BH), dim3(32, 8)>>>();

    // attention (split-bf16 MMA, causal-pruned)
    gemm3b_scores<<<dim3(T/128, T/128, BH), 256, DYNSMEM3>>>();
    softmax_kernel<<<BH*T, 256>>>();
    gemm3b_av<<<dim3(1, T/256, BH), 256, DYNSMEM_AV>>>();

    // Wo + bias + residual (split-bf16 MMA), dual write
    gemm3b_wo<<<dim3(C/128, BT/128), 256, DYNSMEM3>>>(bo, x, p_x1, outp);

    // LN2: exact h2 (gate) + bf16 h2b (fc A)
    ln_kernel<<<BT, 256>>>(p_x1, ln2g, ln2b, p_h2, p_h2b, nullptr, nullptr);

    // gating + routing (exact h2)
    gate_kernel<<<BT/4, 128>>>(gateW, gateb);
    scan_kernel<<<1, 32>>>();
    scatter_kernel<<<NASSIGN/256, 256>>>();

    // expert FFN (bf16 MMA, routed top-2)
    gemm_fc_tc<<<dim3(BT/128, FF/128, E), 256, DYNSMEM>>>(fcb);
    gemm_pj_tc<<<dim3(BT/128, C/128, E), 256, DYNSMEM>>>(pjb, outp);
}

// round 14
// speedup vs baseline: 1.8058x; 1.0069x over previous
#include <cuda_runtime.h>
#include <cuda_bf16.h>
#include <math.h>
#include <stdint.h>

#define Bb 4
#define T 1024
#define C 1024
#define NH 16
#define HD 64
#define E 8
#define TOPK 2
#define FF 4096
#define BT (Bb*T)
#define BH (Bb*NH)
#define NASSIGN (BT*TOPK)

// smem tile: 128 rows x 144B (bf16: 64 vals + 8 pad)
#define TILEB (128*144)        // 18432 bytes
#define DYNSMEM   (4*TILEB)    // MoE bf16 double-buffered (A0,B0|A1,B1)
#define DYNSMEM3  (8*TILEB)    // split bf16 double-buffered
#define DYNSMEM3S (4*TILEB)    // split bf16 single-buffered (scores, nchunk=1)
// AV: A tiles 256 rows, B tiles 64 rows
#define TILEB_A (256*144)
#define TILEB_B (64*144)
#define DYNSMEM_AV (4*TILEB_A + 4*TILEB_B)

typedef __nv_bfloat16 bf16;

// ---------------- scratch ----------------
__device__ bf16  g_hbh[BT*C];
__device__ bf16  g_hbl[BT*C];
__device__ bf16  g_qbh[BT*C];
__device__ bf16  g_qbl[BT*C];
__device__ bf16  g_kbh[BT*C];
__device__ bf16  g_kbl[BT*C];
__device__ float g_v  [BT*C];
__device__ float g_S  [(size_t)BH*T*T];    // fp32 logits
__device__ bf16  g_Sbh[(size_t)BH*T*T];    // probs hi
__device__ bf16  g_Sbl[(size_t)BH*T*T];    // probs lo
__device__ bf16  g_vtbh[(size_t)BH*128*T]; // v^T (rows 0..63 used)
__device__ bf16  g_vtbl[(size_t)BH*128*T];
__device__ bf16  g_ybh[BT*C];
__device__ bf16  g_ybl[BT*C];
__device__ float g_x1 [BT*C];
__device__ float g_h2 [BT*C];              // exact (gate)
__device__ bf16  g_h2b[BT*C];              // bf16 (fc A)
__device__ bf16  g_h1b[(size_t)NASSIGN*FF];
__device__ bf16  g_wqbh[C*C]; __device__ bf16 g_wqbl[C*C];
__device__ bf16  g_wkbh[C*C]; __device__ bf16 g_wkbl[C*C];
__device__ bf16  g_wvbh[C*C]; __device__ bf16 g_wvbl[C*C];
__device__ bf16  g_wobh[C*C]; __device__ bf16 g_wobl[C*C];
__device__ bf16  g_fcwb[(size_t)E*FF*C];
__device__ bf16  g_pjwb[(size_t)E*C*FF];
__device__ int   g_cnt[E];
__device__ int   g_off[E];
__device__ int   g_expidx[NASSIGN];
__device__ int   g_pos  [NASSIGN];
__device__ float g_gscore[NASSIGN];
__device__ int   g_list [NASSIGN];
__device__ float g_slotscore[NASSIGN];

// ---------------- PTX helpers ----------------
__device__ __forceinline__ uint32_t smem_u32(const void* p){
    uint32_t a; asm("{ .reg .u64 t; cvta.to.shared.u64 t, %1; cvt.u32.u64 %0, t; }" : "=r"(a) : "l"(p)); return a;
}
__device__ __forceinline__ void cpa16(uint32_t saddr, const void* g, uint32_t srcsize){
    asm volatile("cp.async.cg.shared.global [%0], [%1], 16, %2;" :: "r"(saddr), "l"(g), "r"(srcsize) : "memory");
}
#define CPA_COMMIT() asm volatile("cp.async.commit_group;" ::: "memory")
#define CPA_WAIT1()  asm volatile("cp.async.wait_group 1;" ::: "memory")
#define CPA_WAIT0()  asm volatile("cp.async.wait_group 0;" ::: "memory")

__device__ __forceinline__ void ldsm_x4(uint32_t &r0, uint32_t &r1, uint32_t &r2, uint32_t &r3, uint32_t addr){
    asm volatile("ldmatrix.sync.aligned.m8n8.x4.shared.b16 {%0,%1,%2,%3},[%4];"
                 : "=r"(r0),"=r"(r1),"=r"(r2),"=r"(r3) : "r"(addr));
}
__device__ __forceinline__ void mma_bf16(float* c, const uint32_t* a, const uint32_t* b){
    asm volatile("mma.sync.aligned.m16n8k16.row.col.f32.bf16.bf16.f32 "
                 "{%0,%1,%2,%3},{%4,%5,%6,%7},{%8,%9},{%0,%1,%2,%3};"
                 : "+f"(c[0]),"+f"(c[1]),"+f"(c[2]),"+f"(c[3])
                 : "r"(a[0]),"r"(a[1]),"r"(a[2]),"r"(a[3]), "r"(b[0]),"r"(b[1]));
}
__device__ __forceinline__ void bsplit(float v, bf16 &hi, bf16 &lo){
    hi = __float2bfloat16(v);
    lo = __float2bfloat16(v - __bfloat162float(hi));
}

// =============== bf16 fragment offsets, 128x128 tiles (validated) ===============
__device__ __forceinline__ void frag_offsets_b(int tid, uint32_t a_off[4], uint32_t b_off[2]){
    int lane = tid & 31, wid = tid >> 5;
    int warpM = wid >> 2, warpN = wid & 3;
#pragma unroll
    for (int mi = 0; mi < 4; mi++) {
        int row = warpM*64 + mi*16 + (lane & 15);
        int col = (lane >> 4) * 8;
        a_off[mi] = (uint32_t)row*144 + (uint32_t)col*2;
    }
    int gg = lane >> 3, r = lane & 7;
#pragma unroll
    for (int p = 0; p < 2; p++) {
        int n = warpN*32 + p*16 + ((gg >> 1) << 3) + r;
        b_off[p] = (uint32_t)n*144 + (uint32_t)(gg & 1)*16;
    }
}

// ---------------- bf16 1x MMA mainloop (MoE): K-chunk = 64 ----------------
__device__ __forceinline__ void gemmb_mainloop(
    const bf16* const* rowA, const bf16* const* rowB,
    const bf16* dummy, int nchunk, char* sm,
    float acc[4][4][4], int tid)
{
    uint32_t base = smem_u32(sm);
    uint32_t a_off[4], b_off[2];
    frag_offsets_b(tid, a_off, b_off);

#define ISSUEB(kc) do { \
        int b_ = (kc) & 1; \
        uint32_t sa_ = base + b_*(2*TILEB); \
        uint32_t sb_ = base + b_*(2*TILEB) + TILEB; \
        _Pragma("unroll") \
        for (int q = 0; q < 4; q++) { \
            int idx = tid + 256*q; \
            int row = idx >> 3, c16 = idx & 7; \
            uint32_t off = (uint32_t)row*144 + c16*16; \
            const bf16* pa = rowA[row]; \
            const void* ga = pa ? (const void*)(pa + (kc)*64 + c16*8) : (const void*)dummy; \
            cpa16(sa_ + off, ga, pa ? 16u : 0u); \
            cpa16(sb_ + off, rowB[row] + (kc)*64 + c16*8, 16u); \
        } \
        CPA_COMMIT(); \
    } while (0)

    ISSUEB(0);
    for (int kc = 0; kc < nchunk; kc++) {
        if (kc + 1 < nchunk) { ISSUEB(kc+1); CPA_WAIT1(); } else { CPA_WAIT0(); }
        __syncthreads();
        int b = kc & 1;
        uint32_t sa = base + b*(2*TILEB);
        uint32_t sb = base + b*(2*TILEB) + TILEB;
#pragma unroll
        for (int ks = 0; ks < 4; ks++) {
            uint32_t afr[4][4];
#pragma unroll
            for (int mi = 0; mi < 4; mi++)
                ldsm_x4(afr[mi][0], afr[mi][1], afr[mi][2], afr[mi][3], sa + a_off[mi] + ks*32);
            uint32_t bfr[4][2];
#pragma unroll
            for (int p = 0; p < 2; p++)
                ldsm_x4(bfr[2*p][0], bfr[2*p][1], bfr[2*p+1][0], bfr[2*p+1][1], sb + b_off[p] + ks*32);
#pragma unroll
            for (int mi = 0; mi < 4; mi++)
#pragma unroll
                for (int ni = 0; ni < 4; ni++)
                    mma_bf16(acc[mi][ni], afr[mi], bfr[ni]);
        }
        __syncthreads();
    }
#undef ISSUEB
}

// ---------------- split-bf16 3-term mainloop (128x128, BUFFER-MAJOR smem) ----------------
// buf b at base + b*4*TILEB: [Ah, Al, Bh, Bl]. Single-buffer callers (nchunk=1)
// may allocate only 4*TILEB.
__device__ __forceinline__ void gemm3b_mainloop(
    const bf16* Ah, const bf16* Al, const bf16* Bh, const bf16* Bl,
    int lda, int ldb, int nchunk, char* sm, float acc[4][4][4], int tid)
{
    uint32_t base = smem_u32(sm);
    uint32_t a_off[4], b_off[2];
    frag_offsets_b(tid, a_off, b_off);

#define ISSUE3B(kc) do { \
        uint32_t bufb = base + ((kc) & 1)*(4*TILEB); \
        _Pragma("unroll") \
        for (int q = 0; q < 4; q++) { \
            int idx = tid + 256*q; \
            int row = idx >> 3, c16 = idx & 7; \
            uint32_t off = (uint32_t)row*144 + c16*16; \
            size_t goa = (size_t)row*lda + (kc)*64 + c16*8; \
            size_t gob = (size_t)row*ldb + (kc)*64 + c16*8; \
            cpa16(bufb + off, Ah + goa, 16u); \
            cpa16(bufb + TILEB + off, Al + goa, 16u); \
            cpa16(bufb + 2*TILEB + off, Bh + gob, 16u); \
            cpa16(bufb + 3*TILEB + off, Bl + gob, 16u); \
        } \
        CPA_COMMIT(); \
    } while (0)

    ISSUE3B(0);
    for (int kc = 0; kc < nchunk; kc++) {
        if (kc + 1 < nchunk) { ISSUE3B(kc+1); CPA_WAIT1(); } else { CPA_WAIT0(); }
        __syncthreads();
        uint32_t bufb = base + (kc & 1)*(4*TILEB);
        uint32_t sah = bufb;
        uint32_t sal = bufb + TILEB;
        uint32_t sbh = bufb + 2*TILEB;
        uint32_t sbl = bufb + 3*TILEB;
#pragma unroll
        for (int ks = 0; ks < 4; ks++) {
            uint32_t bh[4][2], bl[4][2];
#pragma unroll
            for (int p = 0; p < 2; p++) {
                ldsm_x4(bh[2*p][0], bh[2*p][1], bh[2*p+1][0], bh[2*p+1][1], sbh + b_off[p] + ks*32);
                ldsm_x4(bl[2*p][0], bl[2*p][1], bl[2*p+1][0], bl[2*p+1][1], sbl + b_off[p] + ks*32);
            }
#pragma unroll
            for (int mi = 0; mi < 4; mi++) {
                uint32_t ah[4], al[4];
                ldsm_x4(ah[0], ah[1], ah[2], ah[3], sah + a_off[mi] + ks*32);
                ldsm_x4(al[0], al[1], al[2], al[3], sal + a_off[mi] + ks*32);
#pragma unroll
                for (int ni = 0; ni < 4; ni++) {
                    mma_bf16(acc[mi][ni], ah, bh[ni]);
                    mma_bf16(acc[mi][ni], ah, bl[ni]);
                    mma_bf16(acc[mi][ni], al, bh[ni]);
                }
            }
        }
        __syncthreads();
    }
#undef ISSUE3B
}

// ---------------- QKV via split-bf16; q,k written split, v plain fp32 ----------------
__global__ __launch_bounds__(256) void gemm3b_qkv()
{
    extern __shared__ char sm[];
    int tid = threadIdx.x;
    int z = blockIdx.z;
    const bf16* Bh = (z == 0) ? g_wqbh : (z == 1) ? g_wkbh : g_wvbh;
    const bf16* Bl = (z == 0) ? g_wqbl : (z == 1) ? g_wkbl : g_wvbl;
    int rowBase = blockIdx.y * 128, colBase = blockIdx.x * 128;
    float acc[4][4][4] = {};
    gemm3b_mainloop(g_hbh + (size_t)rowBase*C, g_hbl + (size_t)rowBase*C,
                    Bh + (size_t)colBase*C,    Bl + (size_t)colBase*C,
                    C, C, C/64, sm, acc, tid);
    int lane = tid & 31, wid = tid >> 5, warpM = wid >> 2, warpN = wid & 3;
    int g = lane >> 2, tg = lane & 3;
    bf16* Hi = (z == 0) ? g_qbh : g_kbh;
    bf16* Lo = (z == 0) ? g_qbl : g_kbl;
#pragma unroll
    for (int mi = 0; mi < 4; mi++)
#pragma unroll
        for (int ni = 0; ni < 4; ni++) {
            int r0 = rowBase + warpM*64 + mi*16 + g;
            int cc = colBase + warpN*32 + ni*8 + tg*2;
#pragma unroll
            for (int h = 0; h < 2; h++) {
                int r = r0 + h*8;
                float v0 = acc[mi][ni][2*h+0];
                float v1 = acc[mi][ni][2*h+1];
                size_t p = (size_t)r*C + cc;
                if (z < 2) {
                    bf16 h0, l0, h1, l1;
                    bsplit(v0, h0, l0); bsplit(v1, h1, l1);
                    Hi[p] = h0; Hi[p+1] = h1;
                    Lo[p] = l0; Lo[p+1] = l1;
                } else {
                    *(float2*)(g_v + p) = make_float2(v0, v1);
                }
            }
        }
}

// ---------------- scores via split-bf16 (K=64 -> 1 chunk; single buffer; 2 CTAs/SM) ----------------
__global__ __launch_bounds__(256, 2) void gemm3b_scores()
{
    int z = blockIdx.z; int bb = z >> 4; int hh = z & 15;
    int rowBase = blockIdx.y * 128;
    int colBase = blockIdx.x * 128;
    if (colBase >= rowBase + 128) return;
    extern __shared__ char sm[];
    int tid = threadIdx.x;
    size_t aoff = ((size_t)bb*T + rowBase)*C + hh*HD;
    size_t boff = ((size_t)bb*T + colBase)*C + hh*HD;
    float acc[4][4][4] = {};
    gemm3b_mainloop(g_qbh + aoff, g_qbl + aoff, g_kbh + boff, g_kbl + boff,
                    C, C, 1, sm, acc, tid);
    float* Cc = g_S + (size_t)z*T*T;
    int lane = tid & 31, wid = tid >> 5, warpM = wid >> 2, warpN = wid & 3;
    int g = lane >> 2, tg = lane & 3;
#pragma unroll
    for (int mi = 0; mi < 4; mi++)
#pragma unroll
        for (int ni = 0; ni < 4; ni++) {
            int r0 = rowBase + warpM*64 + mi*16 + g;
            int cc = colBase + warpN*32 + ni*8 + tg*2;
#pragma unroll
            for (int h = 0; h < 2; h++) {
                int r = r0 + h*8;
                float* crow = Cc + (size_t)r*T;
                crow[cc]   = (cc   <= r) ? acc[mi][ni][2*h+0]*0.125f : -1e30f;
                crow[cc+1] = (cc+1 <= r) ? acc[mi][ni][2*h+1]*0.125f : -1e30f;
            }
        }
}

// ---------------- row softmax: read logits [0,nv128), write probs zero-padded to nv256 ----------------
__global__ void softmax_kernel()
{
    size_t row = blockIdx.x;
    int r = (int)(row & (T-1));
    int nv  = ((r >> 7) + 1) << 7;
    int nv2 = ((r >> 8) + 1) << 8;
    float* rp  = g_S   + row * T;
    bf16*  rbh = g_Sbh + row * T;
    bf16*  rbl = g_Sbl + row * T;
    int t = threadIdx.x;
    float v[4]; float m = -1e30f;
#pragma unroll
    for (int i = 0; i < 4; i++) {
        int idx = t + 256*i;
        v[i] = (idx < nv) ? rp[idx] : -1e30f;
        m = fmaxf(m, v[i]);
    }
#pragma unroll
    for (int o = 16; o; o >>= 1) m = fmaxf(m, __shfl_xor_sync(0xffffffffu, m, o));
    __shared__ float sh[8];
    int w = t >> 5, lane = t & 31;
    if (!lane) sh[w] = m;
    __syncthreads();
    __shared__ float m_s, inv_s;
    if (t == 0) {
        float mm = sh[0];
#pragma unroll
        for (int i = 1; i < 8; i++) mm = fmaxf(mm, sh[i]);
        m_s = mm;
    }
    __syncthreads();
    m = m_s;
    float s = 0.f;
#pragma unroll
    for (int i = 0; i < 4; i++) { v[i] = expf(v[i] - m); s += v[i]; }
#pragma unroll
    for (int o = 16; o; o >>= 1) s += __shfl_xor_sync(0xffffffffu, s, o);
    if (!lane) sh[w] = s;
    __syncthreads();
    if (t == 0) {
        float ss = 0.f;
#pragma unroll
        for (int i = 0; i < 8; i++) ss += sh[i];
        inv_s = 1.f / ss;
    }
    __syncthreads();
    float inv = inv_s;
#pragma unroll
    for (int i = 0; i < 4; i++) {
        int idx = t + 256*i;
        if (idx < nv) {
            float p = v[i] * inv;
            bf16 hi, lo; bsplit(p, hi, lo);
            rbh[idx] = hi;
            rbl[idx] = lo;
        } else if (idx < nv2) {
            rbh[idx] = __float2bfloat16(0.f);
            rbl[idx] = __float2bfloat16(0.f);
        }
    }
}

// ---------------- v transpose + bf16 split: vT[bh][c(0..63)][k] ----------------
__global__ void transp_split()
{
    __shared__ float tile[32][33];
    int z  = blockIdx.z;
    int bb = z >> 4, hh = z & 15;
    int c0 = blockIdx.y * 32;
    int k0 = blockIdx.x * 32;
    int tx = threadIdx.x, ty = threadIdx.y;
#pragma unroll
    for (int i = 0; i < 4; i++) {
        int kk = k0 + ty + i*8;
        int cc = c0 + tx;
        tile[ty + i*8][tx] = g_v[((size_t)bb*T + kk)*C + hh*HD + cc];
    }
    __syncthreads();
#pragma unroll
    for (int i = 0; i < 4; i++) {
        int cc = c0 + ty + i*8;
        int kk = k0 + tx;
        float val = tile[tx][ty + i*8];
        bf16 hi, lo; bsplit(val, hi, lo);
        size_t p = ((size_t)z*128 + cc)*T + kk;
        g_vtbh[p] = hi;
        g_vtbl[p] = lo;
    }
}

// ---------------- AV via split-bf16, M=256 x N=64 ----------------
__global__ __launch_bounds__(256) void gemm3b_av()
{
    int z = blockIdx.z; int bb = z >> 4; int hh = z & 15;
    int rowBase = blockIdx.y * 256;
    int nchunk = (rowBase + 256) / 64;
    extern __shared__ char sm[];
    int tid = threadIdx.x;
    uint32_t base = smem_u32(sm);
    const bf16* Ah = g_Sbh + (size_t)z*T*T + (size_t)rowBase*T;
    const bf16* Al = g_Sbl + (size_t)z*T*T + (size_t)rowBase*T;
    const bf16* Bh = g_vtbh + (size_t)z*128*T;
    const bf16* Bl = g_vtbl + (size_t)z*128*T;

    int lane = tid & 31, wid = tid >> 5;
    int warpM = wid >> 1, warpN = wid & 1;
    uint32_t a_off[4], b_off[2];
#pragma unroll
    for (int mi = 0; mi < 4; mi++) {
        int row = warpM*64 + mi*16 + (lane & 15);
        int col = (lane >> 4) * 8;
        a_off[mi] = (uint32_t)row*144 + (uint32_t)col*2;
    }
    {
        int gg = lane >> 3, rr = lane & 7;
#pragma unroll
        for (int p = 0; p < 2; p++) {
            int n = warpN*32 + p*16 + ((gg >> 1) << 3) + rr;
            b_off[p] = (uint32_t)n*144 + (uint32_t)(gg & 1)*16;
        }
    }
    float acc[4][4][4] = {};

#define AV_ISSUE(kc) do { \
        int b_ = (kc) & 1; \
        uint32_t sah_ = base + b_*TILEB_A; \
        uint32_t sal_ = base + 2*TILEB_A + b_*TILEB_A; \
        uint32_t sbh_ = base + 4*TILEB_A + b_*TILEB_B; \
        uint32_t sbl_ = base + 4*TILEB_A + 2*TILEB_B + b_*TILEB_B; \
        _Pragma("unroll") \
        for (int q = 0; q < 8; q++) { \
            int idx = tid + 256*q; \
            int row = idx >> 3, c16 = idx & 7; \
            uint32_t off = (uint32_t)row*144 + c16*16; \
            size_t go = (size_t)row*T + (kc)*64 + c16*8; \
            cpa16(sah_ + off, Ah + go, 16u); \
            cpa16(sal_ + off, Al + go, 16u); \
        } \
        _Pragma("unroll") \
        for (int q = 0; q < 2; q++) { \
            int idx = tid + 256*q; \
            int row = idx >> 3, c16 = idx & 7; \
            uint32_t off = (uint32_t)row*144 + c16*16; \
            size_t go = (size_t)row*T + (kc)*64 + c16*8; \
            cpa16(sbh_ + off, Bh + go, 16u); \
            cpa16(sbl_ + off, Bl + go, 16u); \
        } \
        CPA_COMMIT(); \
    } while (0)

    AV_ISSUE(0);
    for (int kc = 0; kc < nchunk; kc++) {
        if (kc + 1 < nchunk) { AV_ISSUE(kc+1); CPA_WAIT1(); } else { CPA_WAIT0(); }
        __syncthreads();
        int b = kc & 1;
        uint32_t sah = base + b*TILEB_A;
        uint32_t sal = base + 2*TILEB_A + b*TILEB_A;
        uint32_t sbh = base + 4*TILEB_A + b*TILEB_B;
        uint32_t sbl = base + 4*TILEB_A + 2*TILEB_B + b*TILEB_B;
#pragma unroll
        for (int ks = 0; ks < 4; ks++) {
            uint32_t bh[4][2], bl[4][2];
#pragma unroll
            for (int p = 0; p < 2; p++) {
                ldsm_x4(bh[2*p][0], bh[2*p][1], bh[2*p+1][0], bh[2*p+1][1], sbh + b_off[p] + ks*32);
                ldsm_x4(bl[2*p][0], bl[2*p][1], bl[2*p+1][0], bl[2*p+1][1], sbl + b_off[p] + ks*32);
            }
#pragma unroll
            for (int mi = 0; mi < 4; mi++) {
                uint32_t ah[4], al[4];
                ldsm_x4(ah[0], ah[1], ah[2], ah[3], sah + a_off[mi] + ks*32);
                ldsm_x4(al[0], al[1], al[2], al[3], sal + a_off[mi] + ks*32);
#pragma unroll
                for (int ni = 0; ni < 4; ni++) {
                    mma_bf16(acc[mi][ni], ah, bh[ni]);
                    mma_bf16(acc[mi][ni], ah, bl[ni]);
                    mma_bf16(acc[mi][ni], al, bh[ni]);
                }
            }
        }
        __syncthreads();
    }
#undef AV_ISSUE

    size_t ybase = (size_t)bb*T*C + hh*HD;
    int g = lane >> 2, tg = lane & 3;
#pragma unroll
    for (int mi = 0; mi < 4; mi++)
#pragma unroll
        for (int ni = 0; ni < 4; ni++) {
            int r0 = rowBase + warpM*64 + mi*16 + g;
            int cc = warpN*32 + ni*8 + tg*2;
#pragma unroll
            for (int h = 0; h < 2; h++) {
                int r = r0 + h*8;
                float v0 = acc[mi][ni][2*h+0];
                float v1 = acc[mi][ni][2*h+1];
                size_t p = ybase + (size_t)r*C + cc;
                bf16 h0, l0, h1, l1;
                bsplit(v0, h0, l0); bsplit(v1, h1, l1);
                g_ybh[p] = h0; g_ybh[p+1] = h1;
                g_ybl[p] = l0; g_ybl[p+1] = l1;
            }
        }
}

// ---------------- Wo via split-bf16: out = res + y*Wo^T + bias, dual write ----------------
__global__ __launch_bounds__(256) void gemm3b_wo(
    const float* __restrict__ bias, const float* __restrict__ res,
    float* __restrict__ out1, float* __restrict__ out2)
{
    extern __shared__ char sm[];
    int tid = threadIdx.x;
    int rowBase = blockIdx.y * 128, colBase = blockIdx.x * 128;
    float acc[4][4][4] = {};
    gemm3b_mainloop(g_ybh + (size_t)rowBase*C, g_ybl + (size_t)rowBase*C,
                    g_wobh + (size_t)colBase*C, g_wobl + (size_t)colBase*C,
                    C, C, C/64, sm, acc, tid);
    int lane = tid & 31, wid = tid >> 5, warpM = wid >> 2, warpN = wid & 3;
    int g = lane >> 2, tg = lane & 3;
#pragma unroll
    for (int mi = 0; mi < 4; mi++)
#pragma unroll
        for (int ni = 0; ni < 4; ni++) {
            int r0 = rowBase + warpM*64 + mi*16 + g;
            int cc = colBase + warpN*32 + ni*8 + tg*2;
#pragma unroll
            for (int h = 0; h < 2; h++) {
                int r = r0 + h*8;
                float v0 = acc[mi][ni][2*h+0] + bias[cc]   + res[(size_t)r*C + cc];
                float v1 = acc[mi][ni][2*h+1] + bias[cc+1] + res[(size_t)r*C + cc + 1];
                *(float2*)(out1 + (size_t)r*C + cc) = make_float2(v0, v1);
                *(float2*)(out2 + (size_t)r*C + cc) = make_float2(v0, v1);
            }
        }
}

// ---------------- fc (bf16 MMA, 2 CTAs/SM): gathered A, +bias, GELU, bf16 out ----------------
__global__ __launch_bounds__(256, 2) void gemm_fc_tc(const float* __restrict__ fcb)
{
    int e = blockIdx.z;
    int cnt = g_cnt[e], off = g_off[e];
    int rowBase = blockIdx.x * 128;
    if (rowBase >= cnt) return;
    int colBase = blockIdx.y * 128;
    extern __shared__ char sm[];
    __shared__ const bf16* rowA[128];
    __shared__ const bf16* rowB[128];
    int tid = threadIdx.x;
    const bf16* wbase = g_fcwb + (size_t)e * FF * C;
    if (tid < 128) {
        int r = rowBase + tid;
        rowA[tid] = (r < cnt) ? g_h2b + (size_t)g_list[off + r] * C : nullptr;
        rowB[tid] = wbase + (size_t)(colBase + tid) * C;
    }
    __syncthreads();
    float acc[4][4][4] = {};
    gemmb_mainloop(rowA, rowB, wbase, C/64, sm, acc, tid);
    int lane = tid & 31, wid = tid >> 5, warpM = wid >> 2, warpN = wid & 3;
    int g = lane >> 2, tg = lane & 3;
    const float* fb = fcb + (size_t)e * FF;
#pragma unroll
    for (int mi = 0; mi < 4; mi++)
#pragma unroll
        for (int ni = 0; ni < 4; ni++) {
            int r0 = rowBase + warpM*64 + mi*16 + g;
            int cc = colBase + warpN*32 + ni*8 + tg*2;
#pragma unroll
            for (int h = 0; h < 2; h++) {
                int r = r0 + h*8;
                if (r >= cnt) continue;
                float v0 = acc[mi][ni][2*h+0] + fb[cc];
                float v1 = acc[mi][ni][2*h+1] + fb[cc+1];
                v0 = v0 * 0.5f * (1.f + erff(v0 * 0.70710678118654752f));
                v1 = v1 * 0.5f * (1.f + erff(v1 * 0.70710678118654752f));
                *(__nv_bfloat162*)(g_h1b + (size_t)(off + r)*FF + cc) = __floats2bfloat162_rn(v0, v1);
            }
        }
}

// ---------------- pj (bf16 MMA, 2 CTAs/SM): +bias, gate-scale, atomicAdd ----------------
__global__ __launch_bounds__(256, 2) void gemm_pj_tc(const float* __restrict__ pjb,
                                                     float* __restrict__ outp)
{
    int e = blockIdx.z;
    int cnt = g_cnt[e], off = g_off[e];
    int rowBase = blockIdx.x * 128;
    if (rowBase >= cnt) return;
    int colBase = blockIdx.y * 128;
    extern __shared__ char sm[];
    __shared__ const bf16* rowA[128];
    __shared__ const bf16* rowB[128];
    int tid = threadIdx.x;
    const bf16* wbase = g_pjwb + (size_t)e * C * FF;
    if (tid < 128) {
        int r = rowBase + tid;
        rowA[tid] = (r < cnt) ? g_h1b + (size_t)(off + r) * FF : nullptr;
        rowB[tid] = wbase + (size_t)(colBase + tid) * FF;
    }
    __syncthreads();
    float acc[4][4][4] = {};
    gemmb_mainloop(rowA, rowB, wbase, FF/64, sm, acc, tid);
    int lane = tid & 31, wid = tid >> 5, warpM = wid >> 2, warpN = wid & 3;
    int g = lane >> 2, tg = lane & 3;
    const float* pb = pjb + (size_t)e * C;
#pragma unroll
    for (int mi = 0; mi < 4; mi++)
#pragma unroll
        for (int ni = 0; ni < 4; ni++) {
            int r0 = rowBase + warpM*64 + mi*16 + g;
            int cc = colBase + warpN*32 + ni*8 + tg*2;
#pragma unroll
            for (int h = 0; h < 2; h++) {
                int r = r0 + h*8;
                if (r >= cnt) continue;
                int tok = g_list[off + r];
                float sc = g_slotscore[off + r];
                float* orow = outp + (size_t)tok * C;
                atomicAdd(&orow[cc],   sc * (acc[mi][ni][2*h+0] + pb[cc]));
                atomicAdd(&orow[cc+1], sc * (acc[mi][ni][2*h+1] + pb[cc+1]));
            }
        }
}

// ---------------- fp32 -> bf16 ----------------
__global__ void conv_f2b(const float* __restrict__ in, bf16* __restrict__ out, int n4)
{
    int stride = gridDim.x * blockDim.x;
    for (int idx = blockIdx.x * blockDim.x + threadIdx.x; idx < n4; idx += stride) {
        float4 v = ((const float4*)in)[idx];
        ((__nv_bfloat162*)out)[idx*2]   = __floats2bfloat162_rn(v.x, v.y);
        ((__nv_bfloat162*)out)[idx*2+1] = __floats2bfloat162_rn(v.z, v.w);
    }
}

// ---------------- fp32 -> bf16 (hi, lo) split ----------------
__global__ void conv_splitb(const float* __restrict__ in, bf16* __restrict__ hi,
                            bf16* __restrict__ lo, int n4)
{
    int stride = gridDim.x * blockDim.x;
    for (int idx = blockIdx.x * blockDim.x + threadIdx.x; idx < n4; idx += stride) {
        float4 v = ((const float4*)in)[idx];
        bf16 h0,l0,h1,l1,h2,l2,h3,l3;
        bsplit(v.x, h0, l0); bsplit(v.y, h1, l1);
        bsplit(v.z, h2, l2); bsplit(v.w, h3, l3);
        ((__nv_bfloat162*)hi)[idx*2]   = __nv_bfloat162(h0, h1);
        ((__nv_bfloat162*)hi)[idx*2+1] = __nv_bfloat162(h2, h3);
        ((__nv_bfloat162*)lo)[idx*2]   = __nv_bfloat162(l0, l1);
        ((__nv_bfloat162*)lo)[idx*2+1] = __nv_bfloat162(l2, l3);
    }
}

// ---------------- layernorm: exact / bf16 / bf16-split outputs ----------------
__global__ void ln_kernel(const float* __restrict__ x, const float* __restrict__ g,
                          const float* __restrict__ b, float* __restrict__ outf,
                          bf16* __restrict__ outb,
                          bf16* __restrict__ outhi, bf16* __restrict__ outlo)
{
    int row = blockIdx.x;
    const float* xr = x + (size_t)row * C;
    int t = threadIdx.x;
    float v[4]; float s = 0.f, s2 = 0.f;
#pragma unroll
    for (int i = 0; i < 4; i++) { float val = xr[t + 256*i]; v[i] = val; s += val; s2 += val*val; }
#pragma unroll
    for (int o = 16; o; o >>= 1) { s += __shfl_xor_sync(0xffffffffu, s, o); s2 += __shfl_xor_sync(0xffffffffu, s2, o); }
    __shared__ float sh[8], sh2[8];
    int w = t >> 5, lane = t & 31;
    if (!lane) { sh[w] = s; sh2[w] = s2; }
    __syncthreads();
    __shared__ float mean_s, rstd_s;
    if (t == 0) {
        float S = 0.f, S2 = 0.f;
#pragma unroll
        for (int i = 0; i < 8; i++) { S += sh[i]; S2 += sh2[i]; }
        float mean = S * (1.f/C);
        float var  = S2 * (1.f/C) - mean*mean;
        mean_s = mean; rstd_s = rsqrtf(var + 1e-5f);
    }
    __syncthreads();
    float mean = mean_s, rstd = rstd_s;
#pragma unroll
    for (int i = 0; i < 4; i++) {
        int c = t + 256*i;
        float o = (v[i] - mean) * rstd * g[c] + b[c];
        size_t p = (size_t)row*C + c;
        if (outf) outf[p] = o;
        if (outb) outb[p] = __float2bfloat16(o);
        if (outhi) { bf16 hh, ll; bsplit(o, hh, ll); outhi[p] = hh; outlo[p] = ll; }
    }
}

// ---------------- gate / routing (reads EXACT h2 once; 8 dots per pass) ----------------
__global__ void gate_kernel(const float* __restrict__ gW, const float* __restrict__ gb)
{
    int token = blockIdx.x * 4 + (threadIdx.x >> 5);
    int lane = threadIdx.x & 31;
    const float* hr = g_h2 + (size_t)token * C;
    float acc[E] = {};
    for (int j = lane; j < C; j += 32) {
        float hv = hr[j];
#pragma unroll
        for (int e = 0; e < E; e++) acc[e] += hv * gW[(size_t)e*C + j];
    }
#pragma unroll
    for (int e = 0; e < E; e++)
#pragma unroll
        for (int o = 16; o; o >>= 1) acc[e] += __shfl_xor_sync(0xffffffffu, acc[e], o);
    if (lane == 0) {
        float logits[E];
#pragma unroll
        for (int e = 0; e < E; e++) logits[e] = acc[e] + gb[e];
        int i0 = 0; float m0 = logits[0];
#pragma unroll
        for (int e = 1; e < E; e++) if (logits[e] > m0) { m0 = logits[e]; i0 = e; }
        int i1 = -1; float m1 = -1e30f;
#pragma unroll
        for (int e = 0; e < E; e++) if (e != i0 && logits[e] > m1) { m1 = logits[e]; i1 = e; }
        float den = 0.f;
#pragma unroll
        for (int e = 0; e < E; e++) den += expf(logits[e] - m0);
        float s0 = 1.f / den;
        float s1 = expf(m1 - m0) / den;
        g_expidx[token*2+0] = i0; g_gscore[token*2+0] = s0;
        g_expidx[token*2+1] = i1; g_gscore[token*2+1] = s1;
        g_pos[token*2+0] = atomicAdd(&g_cnt[i0], 1);
        g_pos[token*2+1] = atomicAdd(&g_cnt[i1], 1);
    }
}

__global__ void zero_cnt_kernel() { if (threadIdx.x < E) g_cnt[threadIdx.x] = 0; }

__global__ void scan_kernel()
{
    if (threadIdx.x == 0) {
        int acc = 0;
        for (int e = 0; e < E; e++) { g_off[e] = acc; acc += g_cnt[e]; }
    }
}

__global__ void scatter_kernel()
{
    int i = blockIdx.x * 256 + threadIdx.x;
    if (i < NASSIGN) {
        int e = g_expidx[i];
        int slot = g_off[e] + g_pos[i];
        g_list[slot] = i >> 1;
        g_slotscore[slot] = g_gscore[i];
    }
}

// ---------------- host launcher ----------------
extern "C" void kernel_launch(void* const* d_in, const int* in_sizes, int n_in,
                              void* d_out, int out_size)
{
    const float* x     = (const float*)d_in[0];
    const float* ln1g  = (const float*)d_in[1];
    const float* ln1b  = (const float*)d_in[2];
    const float* Wq    = (const float*)d_in[3];
    const float* Wk    = (const float*)d_in[4];
    const float* Wv    = (const float*)d_in[5];
    const float* Wo    = (const float*)d_in[6];
    const float* bo    = (const float*)d_in[7];
    const float* ln2g  = (const float*)d_in[8];
    const float* ln2b  = (const float*)d_in[9];
    const float* gateW = (const float*)d_in[10];
    const float* gateb = (const float*)d_in[11];
    const float* fcW   = (const float*)d_in[12];
    const float* fcb   = (const float*)d_in[13];
    const float* pjW   = (const float*)d_in[14];
    const float* pjb   = (const float*)d_in[15];
    float* outp = (float*)d_out;

    float *p_x1, *p_h2;
    bf16 *p_hbh, *p_hbl, *p_h2b, *p_fcwb, *p_pjwb;
    bf16 *p_wqbh, *p_wqbl, *p_wkbh, *p_wkbl, *p_wvbh, *p_wvbl, *p_wobh, *p_wobl;
    cudaGetSymbolAddress((void**)&p_x1,  g_x1);
    cudaGetSymbolAddress((void**)&p_h2,  g_h2);
    cudaGetSymbolAddress((void**)&p_hbh, g_hbh);
    cudaGetSymbolAddress((void**)&p_hbl, g_hbl);
    cudaGetSymbolAddress((void**)&p_h2b, g_h2b);
    cudaGetSymbolAddress((void**)&p_fcwb, g_fcwb);
    cudaGetSymbolAddress((void**)&p_pjwb, g_pjwb);
    cudaGetSymbolAddress((void**)&p_wqbh, g_wqbh); cudaGetSymbolAddress((void**)&p_wqbl, g_wqbl);
    cudaGetSymbolAddress((void**)&p_wkbh, g_wkbh); cudaGetSymbolAddress((void**)&p_wkbl, g_wkbl);
    cudaGetSymbolAddress((void**)&p_wvbh, g_wvbh); cudaGetSymbolAddress((void**)&p_wvbl, g_wvbl);
    cudaGetSymbolAddress((void**)&p_wobh, g_wobh); cudaGetSymbolAddress((void**)&p_wobl, g_wobl);

    cudaFuncSetAttribute(gemm_fc_tc,    cudaFuncAttributeMaxDynamicSharedMemorySize, DYNSMEM);
    cudaFuncSetAttribute(gemm_pj_tc,    cudaFuncAttributeMaxDynamicSharedMemorySize, DYNSMEM);
    cudaFuncSetAttribute(gemm3b_qkv,    cudaFuncAttributeMaxDynamicSharedMemorySize, DYNSMEM3);
    cudaFuncSetAttribute(gemm3b_wo,     cudaFuncAttributeMaxDynamicSharedMemorySize, DYNSMEM3);
    cudaFuncSetAttribute(gemm3b_scores, cudaFuncAttributeMaxDynamicSharedMemorySize, DYNSMEM3S);
    cudaFuncSetAttribute(gemm3b_av,     cudaFuncAttributeMaxDynamicSharedMemorySize, DYNSMEM_AV);

    zero_cnt_kernel<<<1, 32>>>();

    // MoE weights -> bf16
    conv_f2b<<<8192, 256>>>(fcW, p_fcwb, E*FF*C/4);
    conv_f2b<<<8192, 256>>>(pjW, p_pjwb, E*C*FF/4);

    // Attention weights: bf16 hi/lo split
    conv_splitb<<<2048, 256>>>(Wq, p_wqbh, p_wqbl, C*C/4);
    conv_splitb<<<2048, 256>>>(Wk, p_wkbh, p_wkbl, C*C/4);
    conv_splitb<<<2048, 256>>>(Wv, p_wvbh, p_wvbl, C*C/4);
    conv_splitb<<<2048, 256>>>(Wo, p_wobh, p_wobl, C*C/4);

    // LN1 -> bf16 split h
    ln_kernel<<<BT, 256>>>(x, ln1g, ln1b, nullptr, nullptr, p_hbh, p_hbl);

    // QKV (split-bf16 MMA): q,k split; v plain
    gemm3b_qkv<<<dim3(C/128, BT/128, 3), 256, DYNSMEM3>>>();

    // v transpose + bf16 split (64 rows used)
    transp_split<<<dim3(T/32, 2, BH), dim3(32, 8)>>>();

    // attention (split-bf16 MMA, causal-pruned)
    gemm3b_scores<<<dim3(T/128, T/128, BH), 256, DYNSMEM3S>>>();
    softmax_kernel<<<BH*T, 256>>>();
    gemm3b_av<<<dim3(1, T/256, BH), 256, DYNSMEM_AV>>>();

    // Wo + bias + residual (split-bf16 MMA), dual write
    gemm3b_wo<<<dim3(C/128, BT/128), 256, DYNSMEM3>>>(bo, x, p_x1, outp);

    // LN2: exact h2 (gate) + bf16 h2b (fc A)
    ln_kernel<<<BT, 256>>>(p_x1, ln2g, ln2b, p_h2, p_h2b, nullptr, nullptr);

    // gating + routing (exact h2)
    gate_kernel<<<BT/4, 128>>>(gateW, gateb);
    scan_kernel<<<1, 32>>>();
    scatter_kernel<<<NASSIGN/256, 256>>>();

    // expert FFN (bf16 MMA, routed top-2, 2 CTAs/SM)
    gemm_fc_tc<<<dim3(BT/128, FF/128, E), 256, DYNSMEM>>>(fcb);
    gemm_pj_tc<<<dim3(BT/128, C/128, E), 256, DYNSMEM>>>(pjb, outp);
}